// round 1
// baseline (speedup 1.0000x reference)
#include <cuda_runtime.h>
#include <math_constants.h>

#define B_  4
#define S_  2048
#define D_  1024
#define H_  16
#define HD_ 64

// Scratch (device globals: allocation-free rule)
__device__ float g_xq[B_ * S_ * D_];   // [b, h, s, dh]
__device__ float g_xk[B_ * S_ * D_];   // [b, h, s, dh]
__device__ float g_xv[B_ * S_ * D_];   // [b, h, s, dh]
__device__ float g_ctx[B_ * S_ * D_];  // [b, s, h*64+dh]

// ---------------------------------------------------------------------------
// SGEMM: C[M=8192, N=1024] = A[8192,1024] * W[1024,1024]
// mode 0/1/2: C = g_xq/g_xk/g_xv with [b,h,s,dh] permuted store
// mode 3:     A = g_ctx, C = Cout (d_out), plain row-major store
// ---------------------------------------------------------------------------
__global__ __launch_bounds__(256) void gemm_k(const float* __restrict__ A,
                                              const float* __restrict__ W,
                                              float* __restrict__ Cout,
                                              int mode)
{
    __shared__ float As[8][128];
    __shared__ float Bs[8][128];

    const float* Ap = (mode == 3) ? g_ctx : A;
    float* Cp = (mode == 0) ? g_xq : (mode == 1) ? g_xk : (mode == 2) ? g_xv : Cout;

    const int tid = threadIdx.x;
    const int tx = tid & 15;
    const int ty = tid >> 4;
    const int m0 = blockIdx.y * 128;
    const int n0 = blockIdx.x * 128;

    const int arow = tid >> 1;
    const int acol = (tid & 1) * 4;
    const int brow = tid >> 5;
    const int bcol = (tid & 31) * 4;

    const float* Aptr = Ap + (m0 + arow) * 1024 + acol;
    const float* Wptr = W + brow * 1024 + n0 + bcol;

    float acc[8][8];
#pragma unroll
    for (int i = 0; i < 8; i++)
#pragma unroll
        for (int j = 0; j < 8; j++) acc[i][j] = 0.f;

    for (int k0 = 0; k0 < 1024; k0 += 8) {
        float4 av = *(const float4*)(Aptr + k0);
        float4 bv = *(const float4*)(Wptr + (long)k0 * 1024);
        __syncthreads();
        As[acol + 0][arow] = av.x;
        As[acol + 1][arow] = av.y;
        As[acol + 2][arow] = av.z;
        As[acol + 3][arow] = av.w;
        *(float4*)&Bs[brow][bcol] = bv;
        __syncthreads();
#pragma unroll
        for (int k = 0; k < 8; k++) {
            float a[8], b[8];
#pragma unroll
            for (int i = 0; i < 8; i++) a[i] = As[k][ty + 16 * i];
#pragma unroll
            for (int j = 0; j < 8; j++) b[j] = Bs[k][tx + 16 * j];
#pragma unroll
            for (int i = 0; i < 8; i++)
#pragma unroll
                for (int j = 0; j < 8; j++) acc[i][j] = fmaf(a[i], b[j], acc[i][j]);
        }
    }

    if (mode < 3) {
        // permuted store: token t -> (b,s), col o -> (h,dh); write [b,h,s,dh]
#pragma unroll
        for (int i = 0; i < 8; i++) {
            int t = m0 + ty + 16 * i;
            int bb = t >> 11;       // / 2048
            int s = t & 2047;
#pragma unroll
            for (int j = 0; j < 8; j++) {
                int o = n0 + tx + 16 * j;
                int h = o >> 6;
                int dh = o & 63;
                Cp[(((long)(bb * H_ + h) * S_) + s) * HD_ + dh] = acc[i][j];
            }
        }
    } else {
#pragma unroll
        for (int i = 0; i < 8; i++) {
            long row = m0 + ty + 16 * i;
#pragma unroll
            for (int j = 0; j < 8; j++)
                Cp[row * 1024 + n0 + tx + 16 * j] = acc[i][j];
        }
    }
}

// ---------------------------------------------------------------------------
// Flash attention, causal. Bq=128, Bk=64, 256 threads, fp32.
// grid (qt=16, h=16, b=4)
// ---------------------------------------------------------------------------
#define QSTRIDE 132
#define KVSTRIDE 68
#define SSTRIDE 68
#define OFF_Q  0
#define OFF_KV (64 * QSTRIDE)              // 8448
#define OFF_S  (OFF_KV + 64 * KVSTRIDE)    // 12800
#define OFF_M  (OFF_S + 128 * SSTRIDE)     // 21504
#define OFF_L  (OFF_M + 128)
#define OFF_C  (OFF_L + 128)
#define SMEM_FLOATS (OFF_C + 128)          // 21888 floats = 87552 B

extern __shared__ float sm[];

__global__ __launch_bounds__(256) void attn_k()
{
    const int tid = threadIdx.x;
    const int tx = tid & 15;
    const int ty = tid >> 4;
    const int qt = blockIdx.x;
    const int h  = blockIdx.y;
    const int b  = blockIdx.z;
    const int q0 = qt * 128;
    const long bh = (long)(b * H_ + h);

    const float* Qg = g_xq + bh * S_ * HD_;
    const float* Kg = g_xk + bh * S_ * HD_;
    const float* Vg = g_xv + bh * S_ * HD_;

    // Load Q tile transposed: Qt[d][i], i=0..127
    {
        int i = tid >> 1;
        int dg = (tid & 1) * 32;
        const float* src = Qg + (long)(q0 + i) * HD_ + dg;
#pragma unroll
        for (int q4 = 0; q4 < 8; q4++) {
            float4 v4 = *(const float4*)(src + q4 * 4);
            int d = dg + q4 * 4;
            sm[OFF_Q + (d + 0) * QSTRIDE + i] = v4.x;
            sm[OFF_Q + (d + 1) * QSTRIDE + i] = v4.y;
            sm[OFF_Q + (d + 2) * QSTRIDE + i] = v4.z;
            sm[OFF_Q + (d + 3) * QSTRIDE + i] = v4.w;
        }
    }
    if (tid < 128) {
        sm[OFF_M + tid] = -CUDART_INF_F;
        sm[OFF_L + tid] = 0.f;
    }

    float acc[8][4];
#pragma unroll
    for (int i = 0; i < 8; i++)
#pragma unroll
        for (int j = 0; j < 4; j++) acc[i][j] = 0.f;

    const int nkv = 2 * qt + 2;
    for (int kv = 0; kv < nkv; kv++) {
        const int k0 = kv * 64;
        __syncthreads();  // prior PV done (and Q/init done on iter 0)

        // Load K tile transposed: Kt[d][j]
        {
            int j = tid >> 2;
            int dg = (tid & 3) * 16;
            const float* src = Kg + (long)(k0 + j) * HD_ + dg;
#pragma unroll
            for (int q4 = 0; q4 < 4; q4++) {
                float4 v4 = *(const float4*)(src + q4 * 4);
                int d = dg + q4 * 4;
                sm[OFF_KV + (d + 0) * KVSTRIDE + j] = v4.x;
                sm[OFF_KV + (d + 1) * KVSTRIDE + j] = v4.y;
                sm[OFF_KV + (d + 2) * KVSTRIDE + j] = v4.z;
                sm[OFF_KV + (d + 3) * KVSTRIDE + j] = v4.w;
            }
        }
        __syncthreads();

        // S = Q K^T  (rows ty+16i, cols tx+16j)
        float s_acc[8][4];
#pragma unroll
        for (int i = 0; i < 8; i++)
#pragma unroll
            for (int j = 0; j < 4; j++) s_acc[i][j] = 0.f;

#pragma unroll 8
        for (int d = 0; d < 64; d++) {
            float a[8], bb[4];
#pragma unroll
            for (int i = 0; i < 8; i++) a[i] = sm[OFF_Q + d * QSTRIDE + ty + 16 * i];
#pragma unroll
            for (int j = 0; j < 4; j++) bb[j] = sm[OFF_KV + d * KVSTRIDE + tx + 16 * j];
#pragma unroll
            for (int i = 0; i < 8; i++)
#pragma unroll
                for (int j = 0; j < 4; j++) s_acc[i][j] = fmaf(a[i], bb[j], s_acc[i][j]);
        }
        // write S with scale + causal mask
#pragma unroll
        for (int i = 0; i < 8; i++) {
            int r = ty + 16 * i;
#pragma unroll
            for (int j = 0; j < 4; j++) {
                int col = tx + 16 * j;
                float v = s_acc[i][j] * 0.125f;
                if (k0 + col > q0 + r) v = -CUDART_INF_F;
                sm[OFF_S + r * SSTRIDE + col] = v;
            }
        }
        __syncthreads();

        // softmax (tid<128) overlapped with V load (tid>=128)
        if (tid < 128) {
            int r = tid;
            float mold = sm[OFF_M + r];
            float mx = mold;
#pragma unroll 8
            for (int j = 0; j < 64; j++) mx = fmaxf(mx, sm[OFF_S + r * SSTRIDE + j]);
            float corr = __expf(mold - mx);
            float ssum = 0.f;
#pragma unroll 8
            for (int j = 0; j < 64; j++) {
                float p = __expf(sm[OFF_S + r * SSTRIDE + j] - mx);
                sm[OFF_S + r * SSTRIDE + j] = p;
                ssum += p;
            }
            sm[OFF_M + r] = mx;
            sm[OFF_L + r] = sm[OFF_L + r] * corr + ssum;
            sm[OFF_C + r] = corr;
        } else {
            int t2 = tid - 128;
            int d = t2 >> 1;
            int jg = (t2 & 1) * 32;
            const float* src = Vg + (long)(k0 + d) * HD_ + jg;
#pragma unroll
            for (int q4 = 0; q4 < 8; q4++) {
                float4 v4 = *(const float4*)(src + q4 * 4);
                *(float4*)&sm[OFF_KV + d * KVSTRIDE + jg + q4 * 4] = v4;
            }
        }
        __syncthreads();

        // rescale accumulators, then O += P V
        float cr[8];
#pragma unroll
        for (int i = 0; i < 8; i++) cr[i] = sm[OFF_C + ty + 16 * i];
#pragma unroll
        for (int i = 0; i < 8; i++)
#pragma unroll
            for (int j = 0; j < 4; j++) acc[i][j] *= cr[i];

#pragma unroll 8
        for (int d = 0; d < 64; d++) {
            float a[8], bb[4];
#pragma unroll
            for (int i = 0; i < 8; i++) a[i] = sm[OFF_S + (ty + 16 * i) * SSTRIDE + d];
#pragma unroll
            for (int j = 0; j < 4; j++) bb[j] = sm[OFF_KV + d * KVSTRIDE + tx + 16 * j];
#pragma unroll
            for (int i = 0; i < 8; i++)
#pragma unroll
                for (int j = 0; j < 4; j++) acc[i][j] = fmaf(a[i], bb[j], acc[i][j]);
        }
    }

    // epilogue: divide by l, write ctx [b, s, h*64+col]
    float invl[8];
#pragma unroll
    for (int i = 0; i < 8; i++) invl[i] = 1.f / sm[OFF_L + ty + 16 * i];
#pragma unroll
    for (int i = 0; i < 8; i++) {
        int s = q0 + ty + 16 * i;
#pragma unroll
        for (int j = 0; j < 4; j++) {
            int col = tx + 16 * j;
            g_ctx[((long)(b * S_ + s)) * D_ + h * HD_ + col] = acc[i][j] * invl[i];
        }
    }
}

// ---------------------------------------------------------------------------
extern "C" void kernel_launch(void* const* d_in, const int* in_sizes, int n_in,
                              void* d_out, int out_size)
{
    const float* q  = (const float*)d_in[0];
    const float* k  = (const float*)d_in[1];
    const float* v  = (const float*)d_in[2];
    const float* wq = (const float*)d_in[3];
    const float* wk = (const float*)d_in[4];
    const float* wv = (const float*)d_in[5];
    const float* wo = (const float*)d_in[6];
    float* out = (float*)d_out;

    dim3 gb(8, 64);
    dim3 tb(256);

    gemm_k<<<gb, tb>>>(q, wq, nullptr, 0);
    gemm_k<<<gb, tb>>>(k, wk, nullptr, 1);
    gemm_k<<<gb, tb>>>(v, wv, nullptr, 2);

    size_t smem = SMEM_FLOATS * sizeof(float);  // 87552 B
    cudaFuncSetAttribute(attn_k, cudaFuncAttributeMaxDynamicSharedMemorySize, (int)smem);
    attn_k<<<dim3(16, 16, 4), 256, smem>>>();

    gemm_k<<<gb, tb>>>(nullptr, wo, out, 3);
}

// round 3
// speedup vs baseline: 1.4624x; 1.4624x over previous
#include <cuda_runtime.h>
#include <cuda_bf16.h>
#include <math_constants.h>
#include <cstdint>

#define B_  4
#define S_  2048
#define D_  1024
#define H_  16
#define HD_ 64

// Scratch (device globals: allocation-free rule)
__device__ float g_xq[B_ * S_ * D_];   // [b, h, s, dh]
__device__ float g_xk[B_ * S_ * D_];
__device__ float g_xv[B_ * S_ * D_];
__device__ float g_ctx[B_ * S_ * D_];  // [b, s, h*64+dh]
__device__ __nv_bfloat16 g_wth[4ull * 1024 * 1024];  // W^T hi  [n][k]
__device__ __nv_bfloat16 g_wtl[4ull * 1024 * 1024];  // W^T lo  [n][k]

extern __shared__ float sm[];

__device__ __forceinline__ uint32_t smem_u32(const void* p) {
    uint32_t a;
    asm("{ .reg .u64 t; cvta.to.shared.u64 t, %1; cvt.u32.u64 %0, t; }" : "=r"(a) : "l"(p));
    return a;
}

#define STS128(addr, v) \
    asm volatile("st.shared.v4.b32 [%0], {%1,%2,%3,%4};" \
                 :: "r"(addr), "r"((v).x), "r"((v).y), "r"((v).z), "r"((v).w) : "memory")
#define LDS32(r, addr) \
    asm volatile("ld.shared.b32 %0, [%1];" : "=r"(r) : "r"(addr))

__device__ __forceinline__ void mma_bf16(float* d, const uint32_t* a, const uint32_t* b) {
    asm volatile(
        "mma.sync.aligned.m16n8k16.row.col.f32.bf16.bf16.f32 "
        "{%0,%1,%2,%3}, {%4,%5,%6,%7}, {%8,%9}, {%0,%1,%2,%3};"
        : "+f"(d[0]), "+f"(d[1]), "+f"(d[2]), "+f"(d[3])
        : "r"(a[0]), "r"(a[1]), "r"(a[2]), "r"(a[3]), "r"(b[0]), "r"(b[1]));
}

__device__ __forceinline__ void split2(float x, float y, uint32_t& hi, uint32_t& lo) {
    __nv_bfloat162 h = __floats2bfloat162_rn(x, y);
    float rx = x - __bfloat162float(h.x);
    float ry = y - __bfloat162float(h.y);
    __nv_bfloat162 l = __floats2bfloat162_rn(rx, ry);
    hi = reinterpret_cast<uint32_t&>(h);
    lo = reinterpret_cast<uint32_t&>(l);
}

// ---------------------------------------------------------------------------
// Weight transpose + bf16 hi/lo split: Wt[n][k] = W[k][n]
// ---------------------------------------------------------------------------
__global__ __launch_bounds__(256) void wsplit_k(const float* __restrict__ W, int widx) {
    __shared__ float t[32][33];
    const int n0 = blockIdx.x * 32, k0 = blockIdx.y * 32;
    const int tx = threadIdx.x, ty = threadIdx.y;
#pragma unroll
    for (int i = 0; i < 32; i += 8)
        t[ty + i][tx] = W[(size_t)(k0 + ty + i) * 1024 + n0 + tx];
    __syncthreads();
    __nv_bfloat16* Th = g_wth + (size_t)widx * 1024 * 1024;
    __nv_bfloat16* Tl = g_wtl + (size_t)widx * 1024 * 1024;
#pragma unroll
    for (int i = 0; i < 32; i += 8) {
        const int n = n0 + ty + i, k = k0 + tx;
        float x = t[tx][ty + i];
        __nv_bfloat16 h = __float2bfloat16(x);
        float lo = x - __bfloat162float(h);
        Th[(size_t)n * 1024 + k] = h;
        Tl[(size_t)n * 1024 + k] = __float2bfloat16(lo);
    }
}

// ---------------------------------------------------------------------------
// Split-bf16 HMMA GEMM: C[8192,1024] = A[8192,1024] @ W[1024,1024]
// BM=128, BN=128, BK=32, 256 threads, 8 warps each 32x64.
// smem rows padded to 80B (20 words) -> conflict-free fragment lds.
// ---------------------------------------------------------------------------
#define GS_AH 0
#define GS_AL 10240
#define GS_BH 20480
#define GS_BL 30720
#define GS_TOTAL 40960

__global__ __launch_bounds__(256, 2)
void gemm_mma(const float* __restrict__ Aext, int widx, float* __restrict__ Cout, int mode)
{
    __shared__ __align__(16) unsigned char smem_raw[GS_TOTAL];
    const uint32_t sb = smem_u32(smem_raw);

    const int tid = threadIdx.x;
    const int wid = tid >> 5;
    const int lid = tid & 31;
    const int g = lid >> 2;       // groupID 0..7
    const int t4 = lid & 3;       // 0..3
    const int wm = wid & 3;       // warp row 0..3 (32 rows each)
    const int wn = wid >> 2;      // warp col 0..1 (64 cols each)

    const float* Ap = (mode == 3) ? g_ctx : Aext;
    const __nv_bfloat16* Wth = g_wth + (size_t)widx * 1024 * 1024;
    const __nv_bfloat16* Wtl = g_wtl + (size_t)widx * 1024 * 1024;

    const int m0 = blockIdx.y * 128;
    const int n0 = blockIdx.x * 128;

    // loader mapping: row r = tid/2, khalf = (tid&1)*16
    const int lr = tid >> 1;
    const int kh = (tid & 1) * 16;
    const float* Asrc = Ap + (size_t)(m0 + lr) * 1024 + kh;
    const __nv_bfloat16* BhSrc = Wth + (size_t)(n0 + lr) * 1024 + kh;
    const __nv_bfloat16* BlSrc = Wtl + (size_t)(n0 + lr) * 1024 + kh;
    const uint32_t sA = sb + (uint32_t)lr * 80 + (uint32_t)kh * 2;
    const uint32_t sB = sA;  // same row/k mapping, different region offsets

    float acc[2][8][4];
#pragma unroll
    for (int mt = 0; mt < 2; mt++)
#pragma unroll
        for (int nt = 0; nt < 8; nt++)
#pragma unroll
            for (int q = 0; q < 4; q++) acc[mt][nt][q] = 0.f;

    // fragment base addresses (byte): row*80 + kk*32 + t4*4
    const uint32_t aRow0 = (uint32_t)(wm * 32 + g);
    const uint32_t bRow0 = (uint32_t)(wn * 64 + g);

    for (int c = 0; c < 32; c++) {
        const int kg = c * 32;
        // ---- load & split into smem ----
        float4 f0 = *(const float4*)(Asrc + kg);
        float4 f1 = *(const float4*)(Asrc + kg + 4);
        float4 f2 = *(const float4*)(Asrc + kg + 8);
        float4 f3 = *(const float4*)(Asrc + kg + 12);
        uint4 bh0 = *(const uint4*)(BhSrc + kg);
        uint4 bh1 = *(const uint4*)(BhSrc + kg + 8);
        uint4 bl0 = *(const uint4*)(BlSrc + kg);
        uint4 bl1 = *(const uint4*)(BlSrc + kg + 8);

        uint4 h0, h1, l0, l1;
        split2(f0.x, f0.y, h0.x, l0.x);
        split2(f0.z, f0.w, h0.y, l0.y);
        split2(f1.x, f1.y, h0.z, l0.z);
        split2(f1.z, f1.w, h0.w, l0.w);
        split2(f2.x, f2.y, h1.x, l1.x);
        split2(f2.z, f2.w, h1.y, l1.y);
        split2(f3.x, f3.y, h1.z, l1.z);
        split2(f3.z, f3.w, h1.w, l1.w);

        __syncthreads();
        STS128(sA + GS_AH, h0);
        STS128(sA + GS_AH + 16, h1);
        STS128(sA + GS_AL, l0);
        STS128(sA + GS_AL + 16, l1);
        STS128(sB + GS_BH, bh0);
        STS128(sB + GS_BH + 16, bh1);
        STS128(sB + GS_BL, bl0);
        STS128(sB + GS_BL + 16, bl1);
        __syncthreads();

        // ---- compute: 2 k16 steps, 3 passes each ----
#pragma unroll
        for (int kk = 0; kk < 2; kk++) {
            const uint32_t kof = (uint32_t)kk * 32 + (uint32_t)t4 * 4;

            uint32_t ah[2][4], al[2][4], bhf[8][2], blf[8][2];
#pragma unroll
            for (int mt = 0; mt < 2; mt++) {
                const uint32_t ab = sb + (aRow0 + mt * 16) * 80 + kof;
                LDS32(ah[mt][0], ab + GS_AH);
                LDS32(ah[mt][1], ab + GS_AH + 640);
                LDS32(ah[mt][2], ab + GS_AH + 16);
                LDS32(ah[mt][3], ab + GS_AH + 656);
            }
#pragma unroll
            for (int nt = 0; nt < 8; nt++) {
                const uint32_t bb = sb + (bRow0 + nt * 8) * 80 + kof;
                LDS32(bhf[nt][0], bb + GS_BH);
                LDS32(bhf[nt][1], bb + GS_BH + 16);
            }
            // pass 1: Ah * Bh
#pragma unroll
            for (int mt = 0; mt < 2; mt++)
#pragma unroll
                for (int nt = 0; nt < 8; nt++)
                    mma_bf16(acc[mt][nt], ah[mt], bhf[nt]);

            // pass 2: Al * Bh
#pragma unroll
            for (int mt = 0; mt < 2; mt++) {
                const uint32_t ab = sb + (aRow0 + mt * 16) * 80 + kof;
                LDS32(al[mt][0], ab + GS_AL);
                LDS32(al[mt][1], ab + GS_AL + 640);
                LDS32(al[mt][2], ab + GS_AL + 16);
                LDS32(al[mt][3], ab + GS_AL + 656);
            }
#pragma unroll
            for (int mt = 0; mt < 2; mt++)
#pragma unroll
                for (int nt = 0; nt < 8; nt++)
                    mma_bf16(acc[mt][nt], al[mt], bhf[nt]);

            // pass 3: Ah * Bl
#pragma unroll
            for (int nt = 0; nt < 8; nt++) {
                const uint32_t bb = sb + (bRow0 + nt * 8) * 80 + kof;
                LDS32(blf[nt][0], bb + GS_BL);
                LDS32(blf[nt][1], bb + GS_BL + 16);
            }
#pragma unroll
            for (int mt = 0; mt < 2; mt++)
#pragma unroll
                for (int nt = 0; nt < 8; nt++)
                    mma_bf16(acc[mt][nt], ah[mt], blf[nt]);
        }
    }

    // ---- epilogue: direct stores (float2 per row-half) ----
    float* D0 = (mode == 0) ? g_xq : (mode == 1) ? g_xk : g_xv;
#pragma unroll
    for (int mt = 0; mt < 2; mt++) {
#pragma unroll
        for (int nt = 0; nt < 8; nt++) {
            const int row0 = m0 + wm * 32 + mt * 16 + g;
            const int col = n0 + wn * 64 + nt * 8 + t4 * 2;
            float2 v0 = make_float2(acc[mt][nt][0], acc[mt][nt][1]);
            float2 v1 = make_float2(acc[mt][nt][2], acc[mt][nt][3]);
            if (mode < 3) {
                const int h = col >> 6, dh = col & 63;
                {
                    const int bb = row0 >> 11, sq = row0 & 2047;
                    *(float2*)&D0[(((size_t)(bb * H_ + h) * S_) + sq) * HD_ + dh] = v0;
                }
                {
                    const int row1 = row0 + 8;
                    const int bb = row1 >> 11, sq = row1 & 2047;
                    *(float2*)&D0[(((size_t)(bb * H_ + h) * S_) + sq) * HD_ + dh] = v1;
                }
            } else {
                *(float2*)&Cout[(size_t)row0 * 1024 + col] = v0;
                *(float2*)&Cout[(size_t)(row0 + 8) * 1024 + col] = v1;
            }
        }
    }
}

// ---------------------------------------------------------------------------
// Flash attention, causal. Bq=128, Bk=64, 256 threads, fp32. (unchanged)
// ---------------------------------------------------------------------------
#define QSTRIDE 132
#define KVSTRIDE 68
#define SSTRIDE 68
#define OFF_Q  0
#define OFF_KV (64 * QSTRIDE)
#define OFF_S  (OFF_KV + 64 * KVSTRIDE)
#define OFF_M  (OFF_S + 128 * SSTRIDE)
#define OFF_L  (OFF_M + 128)
#define OFF_C  (OFF_L + 128)
#define SMEM_FLOATS (OFF_C + 128)

__global__ __launch_bounds__(256) void attn_k()
{
    const int tid = threadIdx.x;
    const int tx = tid & 15;
    const int ty = tid >> 4;
    const int qt = blockIdx.x;
    const int h  = blockIdx.y;
    const int b  = blockIdx.z;
    const int q0 = qt * 128;
    const long bh = (long)(b * H_ + h);

    const float* Qg = g_xq + bh * S_ * HD_;
    const float* Kg = g_xk + bh * S_ * HD_;
    const float* Vg = g_xv + bh * S_ * HD_;

    {
        int i = tid >> 1;
        int dg = (tid & 1) * 32;
        const float* src = Qg + (long)(q0 + i) * HD_ + dg;
#pragma unroll
        for (int q4 = 0; q4 < 8; q4++) {
            float4 v4 = *(const float4*)(src + q4 * 4);
            int d = dg + q4 * 4;
            sm[OFF_Q + (d + 0) * QSTRIDE + i] = v4.x;
            sm[OFF_Q + (d + 1) * QSTRIDE + i] = v4.y;
            sm[OFF_Q + (d + 2) * QSTRIDE + i] = v4.z;
            sm[OFF_Q + (d + 3) * QSTRIDE + i] = v4.w;
        }
    }
    if (tid < 128) {
        sm[OFF_M + tid] = -CUDART_INF_F;
        sm[OFF_L + tid] = 0.f;
    }

    float acc[8][4];
#pragma unroll
    for (int i = 0; i < 8; i++)
#pragma unroll
        for (int j = 0; j < 4; j++) acc[i][j] = 0.f;

    const int nkv = 2 * qt + 2;
    for (int kv = 0; kv < nkv; kv++) {
        const int k0 = kv * 64;
        __syncthreads();

        {
            int j = tid >> 2;
            int dg = (tid & 3) * 16;
            const float* src = Kg + (long)(k0 + j) * HD_ + dg;
#pragma unroll
            for (int q4 = 0; q4 < 4; q4++) {
                float4 v4 = *(const float4*)(src + q4 * 4);
                int d = dg + q4 * 4;
                sm[OFF_KV + (d + 0) * KVSTRIDE + j] = v4.x;
                sm[OFF_KV + (d + 1) * KVSTRIDE + j] = v4.y;
                sm[OFF_KV + (d + 2) * KVSTRIDE + j] = v4.z;
                sm[OFF_KV + (d + 3) * KVSTRIDE + j] = v4.w;
            }
        }
        __syncthreads();

        float s_acc[8][4];
#pragma unroll
        for (int i = 0; i < 8; i++)
#pragma unroll
            for (int j = 0; j < 4; j++) s_acc[i][j] = 0.f;

#pragma unroll 8
        for (int d = 0; d < 64; d++) {
            float a[8], bb[4];
#pragma unroll
            for (int i = 0; i < 8; i++) a[i] = sm[OFF_Q + d * QSTRIDE + ty + 16 * i];
#pragma unroll
            for (int j = 0; j < 4; j++) bb[j] = sm[OFF_KV + d * KVSTRIDE + tx + 16 * j];
#pragma unroll
            for (int i = 0; i < 8; i++)
#pragma unroll
                for (int j = 0; j < 4; j++) s_acc[i][j] = fmaf(a[i], bb[j], s_acc[i][j]);
        }
#pragma unroll
        for (int i = 0; i < 8; i++) {
            int rr = ty + 16 * i;
#pragma unroll
            for (int j = 0; j < 4; j++) {
                int col = tx + 16 * j;
                float v = s_acc[i][j] * 0.125f;
                if (k0 + col > q0 + rr) v = -CUDART_INF_F;
                sm[OFF_S + rr * SSTRIDE + col] = v;
            }
        }
        __syncthreads();

        if (tid < 128) {
            int rr = tid;
            float mold = sm[OFF_M + rr];
            float mx = mold;
#pragma unroll 8
            for (int j = 0; j < 64; j++) mx = fmaxf(mx, sm[OFF_S + rr * SSTRIDE + j]);
            float corr = __expf(mold - mx);
            float ssum = 0.f;
#pragma unroll 8
            for (int j = 0; j < 64; j++) {
                float p = __expf(sm[OFF_S + rr * SSTRIDE + j] - mx);
                sm[OFF_S + rr * SSTRIDE + j] = p;
                ssum += p;
            }
            sm[OFF_M + rr] = mx;
            sm[OFF_L + rr] = sm[OFF_L + rr] * corr + ssum;
            sm[OFF_C + rr] = corr;
        } else {
            int t2 = tid - 128;
            int d = t2 >> 1;
            int jg = (t2 & 1) * 32;
            const float* src = Vg + (long)(k0 + d) * HD_ + jg;
#pragma unroll
            for (int q4 = 0; q4 < 8; q4++) {
                float4 v4 = *(const float4*)(src + q4 * 4);
                *(float4*)&sm[OFF_KV + d * KVSTRIDE + jg + q4 * 4] = v4;
            }
        }
        __syncthreads();

        float cr[8];
#pragma unroll
        for (int i = 0; i < 8; i++) cr[i] = sm[OFF_C + ty + 16 * i];
#pragma unroll
        for (int i = 0; i < 8; i++)
#pragma unroll
            for (int j = 0; j < 4; j++) acc[i][j] *= cr[i];

#pragma unroll 8
        for (int d = 0; d < 64; d++) {
            float a[8], bb[4];
#pragma unroll
            for (int i = 0; i < 8; i++) a[i] = sm[OFF_S + (ty + 16 * i) * SSTRIDE + d];
#pragma unroll
            for (int j = 0; j < 4; j++) bb[j] = sm[OFF_KV + d * KVSTRIDE + tx + 16 * j];
#pragma unroll
            for (int i = 0; i < 8; i++)
#pragma unroll
                for (int j = 0; j < 4; j++) acc[i][j] = fmaf(a[i], bb[j], acc[i][j]);
        }
    }

    float invl[8];
#pragma unroll
    for (int i = 0; i < 8; i++) invl[i] = 1.f / sm[OFF_L + ty + 16 * i];
#pragma unroll
    for (int i = 0; i < 8; i++) {
        int s = q0 + ty + 16 * i;
#pragma unroll
        for (int j = 0; j < 4; j++) {
            int col = tx + 16 * j;
            g_ctx[((long)(b * S_ + s)) * D_ + h * HD_ + col] = acc[i][j] * invl[i];
        }
    }
}

// ---------------------------------------------------------------------------
extern "C" void kernel_launch(void* const* d_in, const int* in_sizes, int n_in,
                              void* d_out, int out_size)
{
    const float* q  = (const float*)d_in[0];
    const float* k  = (const float*)d_in[1];
    const float* v  = (const float*)d_in[2];
    const float* wq = (const float*)d_in[3];
    const float* wk = (const float*)d_in[4];
    const float* wv = (const float*)d_in[5];
    const float* wo = (const float*)d_in[6];
    float* out = (float*)d_out;

    dim3 wg(32, 32), wb(32, 8);
    wsplit_k<<<wg, wb>>>(wq, 0);
    wsplit_k<<<wg, wb>>>(wk, 1);
    wsplit_k<<<wg, wb>>>(wv, 2);
    wsplit_k<<<wg, wb>>>(wo, 3);

    cudaFuncSetAttribute(attn_k, cudaFuncAttributeMaxDynamicSharedMemorySize,
                         SMEM_FLOATS * (int)sizeof(float));

    dim3 gg(8, 64), gt(256);
    gemm_mma<<<gg, gt>>>(q, 0, nullptr, 0);
    gemm_mma<<<gg, gt>>>(k, 1, nullptr, 1);
    gemm_mma<<<gg, gt>>>(v, 2, nullptr, 2);

    attn_k<<<dim3(16, 16, 4), 256, SMEM_FLOATS * sizeof(float)>>>();

    gemm_mma<<<gg, gt>>>(nullptr, 3, out, 3);
}

// round 5
// speedup vs baseline: 2.3635x; 1.6161x over previous
#include <cuda_runtime.h>
#include <cuda_bf16.h>
#include <math_constants.h>
#include <cstdint>

#define B_  4
#define S_  2048
#define D_  1024
#define H_  16
#define HD_ 64

// Scratch (device globals: allocation-free rule)
__device__ float g_xq[B_ * S_ * D_];   // [b, h, s, dh]
__device__ float g_xk[B_ * S_ * D_];
__device__ float g_xv[B_ * S_ * D_];
__device__ float g_ctx[B_ * S_ * D_];  // [b, s, h*64+dh]
__device__ __nv_bfloat16 g_wth[4ull * 1024 * 1024];  // W^T hi  [n][k]
__device__ __nv_bfloat16 g_wtl[4ull * 1024 * 1024];  // W^T lo  [n][k]

__device__ __forceinline__ uint32_t smem_u32(const void* p) {
    uint32_t a;
    asm("{ .reg .u64 t; cvta.to.shared.u64 t, %1; cvt.u32.u64 %0, t; }" : "=r"(a) : "l"(p));
    return a;
}

#define STS128(addr, v) \
    asm volatile("st.shared.v4.b32 [%0], {%1,%2,%3,%4};" \
                 :: "r"(addr), "r"((v).x), "r"((v).y), "r"((v).z), "r"((v).w) : "memory")
#define STS32(addr, v) \
    asm volatile("st.shared.b32 [%0], %1;" :: "r"(addr), "r"(v) : "memory")
#define LDS32(r, addr) \
    asm volatile("ld.shared.b32 %0, [%1];" : "=r"(r) : "r"(addr))
#define CP_ASYNC16(dst, src) \
    asm volatile("cp.async.cg.shared.global [%0], [%1], 16;" :: "r"(dst), "l"(src) : "memory")
#define CP_COMMIT() asm volatile("cp.async.commit_group;" ::: "memory")
#define CP_WAIT(n)  asm volatile("cp.async.wait_group %0;" :: "n"(n) : "memory")

__device__ __forceinline__ void mma_bf16(float* d, const uint32_t* a, const uint32_t* b) {
    asm volatile(
        "mma.sync.aligned.m16n8k16.row.col.f32.bf16.bf16.f32 "
        "{%0,%1,%2,%3}, {%4,%5,%6,%7}, {%8,%9}, {%0,%1,%2,%3};"
        : "+f"(d[0]), "+f"(d[1]), "+f"(d[2]), "+f"(d[3])
        : "r"(a[0]), "r"(a[1]), "r"(a[2]), "r"(a[3]), "r"(b[0]), "r"(b[1]));
}

__device__ __forceinline__ void split2(float x, float y, uint32_t& hi, uint32_t& lo) {
    __nv_bfloat162 h = __floats2bfloat162_rn(x, y);
    float rx = x - __bfloat162float(h.x);
    float ry = y - __bfloat162float(h.y);
    __nv_bfloat162 l = __floats2bfloat162_rn(rx, ry);
    hi = reinterpret_cast<uint32_t&>(h);
    lo = reinterpret_cast<uint32_t&>(l);
}

// ---------------------------------------------------------------------------
// Weight transpose + bf16 hi/lo split: Wt[n][k] = W[k][n]  (4 weights, z-dim)
// ---------------------------------------------------------------------------
__global__ __launch_bounds__(256) void wsplit_k(const float* __restrict__ w0,
                                                const float* __restrict__ w1,
                                                const float* __restrict__ w2,
                                                const float* __restrict__ w3) {
    __shared__ float t[32][33];
    const int widx = blockIdx.z;
    const float* W = (widx == 0) ? w0 : (widx == 1) ? w1 : (widx == 2) ? w2 : w3;
    const int n0 = blockIdx.x * 32, k0 = blockIdx.y * 32;
    const int tx = threadIdx.x, ty = threadIdx.y;
#pragma unroll
    for (int i = 0; i < 32; i += 8)
        t[ty + i][tx] = W[(size_t)(k0 + ty + i) * 1024 + n0 + tx];
    __syncthreads();
    __nv_bfloat16* Th = g_wth + (size_t)widx * 1024 * 1024;
    __nv_bfloat16* Tl = g_wtl + (size_t)widx * 1024 * 1024;
#pragma unroll
    for (int i = 0; i < 32; i += 8) {
        const int n = n0 + ty + i, k = k0 + tx;
        float x = t[tx][ty + i];
        __nv_bfloat16 h = __float2bfloat16(x);
        float lo = x - __bfloat162float(h);
        Th[(size_t)n * 1024 + k] = h;
        Tl[(size_t)n * 1024 + k] = __float2bfloat16(lo);
    }
}

// ---------------------------------------------------------------------------
// Split-bf16 HMMA GEMM, cp.async double-buffered B, A register prefetch.
// BM=128, BN=128, BK=32, 256 threads, 8 warps each 32x64.
// smem: Ah/Al (80B rows) + 2-stage Bh/Bl.
// ---------------------------------------------------------------------------
#define GA_H 0
#define GA_L 10240
#define GB_ST(s) (20480 + (s) * 20480)   // Bh at +0, Bl at +10240
#define G_SMEM (20480 + 2 * 20480)       // 61440

extern __shared__ unsigned char g_dynsm[];

__global__ __launch_bounds__(256)
void gemm_mma(const float* __restrict__ aq, const float* __restrict__ ak,
              const float* __restrict__ av, float* __restrict__ Cout, int mode_base)
{
    const uint32_t sb = smem_u32(g_dynsm);

    const int tid = threadIdx.x;
    const int wid = tid >> 5;
    const int lid = tid & 31;
    const int g = lid >> 2;
    const int t4 = lid & 3;
    const int wm = wid & 3;
    const int wn = wid >> 2;

    const int mode = (mode_base == 3) ? 3 : (int)blockIdx.z;
    const int widx = mode;
    const float* Ap = (mode == 0) ? aq : (mode == 1) ? ak : (mode == 2) ? av : g_ctx;
    const __nv_bfloat16* Wth = g_wth + (size_t)widx * 1024 * 1024;
    const __nv_bfloat16* Wtl = g_wtl + (size_t)widx * 1024 * 1024;

    const int m0 = blockIdx.y * 128;
    const int n0 = blockIdx.x * 128;

    // loader mapping
    const int lr = tid >> 1;
    const int khalf = (tid & 1) * 16;
    const float* Asrc = Ap + (size_t)(m0 + lr) * 1024 + khalf;
    const __nv_bfloat16* BhSrc = Wth + (size_t)(n0 + lr) * 1024 + khalf;
    const __nv_bfloat16* BlSrc = Wtl + (size_t)(n0 + lr) * 1024 + khalf;
    const uint32_t sArow = sb + (uint32_t)lr * 80 + (uint32_t)khalf * 2;

    float acc[2][8][4];
#pragma unroll
    for (int mt = 0; mt < 2; mt++)
#pragma unroll
        for (int nt = 0; nt < 8; nt++)
#pragma unroll
            for (int q = 0; q < 4; q++) acc[mt][nt][q] = 0.f;

    const uint32_t aRow0 = (uint32_t)(wm * 32 + g);
    const uint32_t bRow0 = (uint32_t)(wn * 64 + g);

    // prologue: issue B chunk 0, prefetch A chunk 0
    {
        const uint32_t d = sArow + GB_ST(0);
        CP_ASYNC16(d, BhSrc);
        CP_ASYNC16(d + 16, BhSrc + 8);
        CP_ASYNC16(d + 10240, BlSrc);
        CP_ASYNC16(d + 10240 + 16, BlSrc + 8);
        CP_COMMIT();
    }
    float4 fA0 = *(const float4*)(Asrc);
    float4 fA1 = *(const float4*)(Asrc + 4);
    float4 fA2 = *(const float4*)(Asrc + 8);
    float4 fA3 = *(const float4*)(Asrc + 12);

    for (int c = 0; c < 32; c++) {
        const uint32_t sBst = sb + GB_ST(c & 1);
        __syncthreads();   // previous compute done everywhere

        // STS A(c) (split from prefetched regs)
        {
            uint4 h0, h1, l0, l1;
            split2(fA0.x, fA0.y, h0.x, l0.x);
            split2(fA0.z, fA0.w, h0.y, l0.y);
            split2(fA1.x, fA1.y, h0.z, l0.z);
            split2(fA1.z, fA1.w, h0.w, l0.w);
            split2(fA2.x, fA2.y, h1.x, l1.x);
            split2(fA2.z, fA2.w, h1.y, l1.y);
            split2(fA3.x, fA3.y, h1.z, l1.z);
            split2(fA3.z, fA3.w, h1.w, l1.w);
            STS128(sArow + GA_H, h0);
            STS128(sArow + GA_H + 16, h1);
            STS128(sArow + GA_L, l0);
            STS128(sArow + GA_L + 16, l1);
        }

        // issue B(c+1)
        if (c < 31) {
            const int kg = (c + 1) * 32;
            const uint32_t d = sArow + GB_ST((c + 1) & 1);
            CP_ASYNC16(d, BhSrc + kg);
            CP_ASYNC16(d + 16, BhSrc + kg + 8);
            CP_ASYNC16(d + 10240, BlSrc + kg);
            CP_ASYNC16(d + 10240 + 16, BlSrc + kg + 8);
            CP_COMMIT();
            CP_WAIT(1);            // B(c) landed
        } else {
            CP_WAIT(0);
        }
        __syncthreads();

        // prefetch A(c+1)
        if (c < 31) {
            const int kg = (c + 1) * 32;
            fA0 = *(const float4*)(Asrc + kg);
            fA1 = *(const float4*)(Asrc + kg + 4);
            fA2 = *(const float4*)(Asrc + kg + 8);
            fA3 = *(const float4*)(Asrc + kg + 12);
        }

        // compute chunk c
#pragma unroll
        for (int kk = 0; kk < 2; kk++) {
            const uint32_t kof = (uint32_t)kk * 32 + (uint32_t)t4 * 4;

            uint32_t ah[2][4], al[2][4], bhf[8][2], blf[8][2];
#pragma unroll
            for (int mt = 0; mt < 2; mt++) {
                const uint32_t ab = sb + (aRow0 + mt * 16) * 80 + kof;
                LDS32(ah[mt][0], ab + GA_H);
                LDS32(ah[mt][1], ab + GA_H + 640);
                LDS32(ah[mt][2], ab + GA_H + 16);
                LDS32(ah[mt][3], ab + GA_H + 656);
            }
#pragma unroll
            for (int nt = 0; nt < 8; nt++) {
                const uint32_t bb = sBst + (bRow0 + nt * 8) * 80 + kof;
                LDS32(bhf[nt][0], bb);
                LDS32(bhf[nt][1], bb + 16);
            }
#pragma unroll
            for (int mt = 0; mt < 2; mt++)
#pragma unroll
                for (int nt = 0; nt < 8; nt++)
                    mma_bf16(acc[mt][nt], ah[mt], bhf[nt]);

#pragma unroll
            for (int mt = 0; mt < 2; mt++) {
                const uint32_t ab = sb + (aRow0 + mt * 16) * 80 + kof;
                LDS32(al[mt][0], ab + GA_L);
                LDS32(al[mt][1], ab + GA_L + 640);
                LDS32(al[mt][2], ab + GA_L + 16);
                LDS32(al[mt][3], ab + GA_L + 656);
            }
#pragma unroll
            for (int mt = 0; mt < 2; mt++)
#pragma unroll
                for (int nt = 0; nt < 8; nt++)
                    mma_bf16(acc[mt][nt], al[mt], bhf[nt]);

#pragma unroll
            for (int nt = 0; nt < 8; nt++) {
                const uint32_t bb = sBst + 10240 + (bRow0 + nt * 8) * 80 + kof;
                LDS32(blf[nt][0], bb);
                LDS32(blf[nt][1], bb + 16);
            }
#pragma unroll
            for (int mt = 0; mt < 2; mt++)
#pragma unroll
                for (int nt = 0; nt < 8; nt++)
                    mma_bf16(acc[mt][nt], ah[mt], blf[nt]);
        }
    }

    // epilogue
    float* D0 = (mode == 0) ? g_xq : (mode == 1) ? g_xk : g_xv;
#pragma unroll
    for (int mt = 0; mt < 2; mt++) {
#pragma unroll
        for (int nt = 0; nt < 8; nt++) {
            const int row0 = m0 + wm * 32 + mt * 16 + g;
            const int col = n0 + wn * 64 + nt * 8 + t4 * 2;
            float2 v0 = make_float2(acc[mt][nt][0], acc[mt][nt][1]);
            float2 v1 = make_float2(acc[mt][nt][2], acc[mt][nt][3]);
            if (mode < 3) {
                const int h = col >> 6, dh = col & 63;
                {
                    const int bb = row0 >> 11, sq = row0 & 2047;
                    *(float2*)&D0[(((size_t)(bb * H_ + h) * S_) + sq) * HD_ + dh] = v0;
                }
                {
                    const int row1 = row0 + 8;
                    const int bb = row1 >> 11, sq = row1 & 2047;
                    *(float2*)&D0[(((size_t)(bb * H_ + h) * S_) + sq) * HD_ + dh] = v1;
                }
            } else {
                *(float2*)&Cout[(size_t)row0 * 1024 + col] = v0;
                *(float2*)&Cout[(size_t)(row0 + 8) * 1024 + col] = v1;
            }
        }
    }
}

// ---------------------------------------------------------------------------
// Flash attention on HMMA, split-bf16 (3 passes), causal.
// Bq=128, Bk=64, 8 warps (16 rows each), register softmax.
// smem: Kh/Kl [64][72bf16], Vth/Vtl (transposed) [64][72bf16]; 144B rows.
// ---------------------------------------------------------------------------
#define AT_KH 0
#define AT_KL 9216
#define AT_VH 18432
#define AT_VL 27648
#define AT_SMEM 36864

__global__ __launch_bounds__(256) void attn_k()
{
    __shared__ __align__(16) unsigned char smraw[AT_SMEM];
    const uint32_t sb = smem_u32(smraw);

    const int tid = threadIdx.x;
    const int wid = tid >> 5;
    const int lid = tid & 31;
    const int g = lid >> 2;
    const int t4 = lid & 3;
    const int qt = 15 - (int)blockIdx.x;   // big tiles first
    const int h = blockIdx.y;
    const int b = blockIdx.z;
    const int q0 = qt * 128;
    const long bh_ = (long)(b * H_ + h);

    const float* Qg = g_xq + bh_ * S_ * HD_;
    const float* Kg = g_xk + bh_ * S_ * HD_;
    const float* Vg = g_xv + bh_ * S_ * HD_;

    const int wrow = q0 + wid * 16;        // warp's first row
    const int row0 = wrow + g;             // rows row0 (d0,d1) and row0+8 (d2,d3)

    // Q fragments (scale 1/8 folded in), hi/lo split, kept in registers
    uint32_t qh[4][4], ql[4][4];
    {
        const float* qa = Qg + (size_t)row0 * 64;
        const float* qb = Qg + (size_t)(row0 + 8) * 64;
#pragma unroll
        for (int ks = 0; ks < 4; ks++) {
            const int k = ks * 16 + 2 * t4;
            float2 v;
            v = *(const float2*)(qa + k);
            split2(v.x * 0.125f, v.y * 0.125f, qh[ks][0], ql[ks][0]);
            v = *(const float2*)(qb + k);
            split2(v.x * 0.125f, v.y * 0.125f, qh[ks][1], ql[ks][1]);
            v = *(const float2*)(qa + k + 8);
            split2(v.x * 0.125f, v.y * 0.125f, qh[ks][2], ql[ks][2]);
            v = *(const float2*)(qb + k + 8);
            split2(v.x * 0.125f, v.y * 0.125f, qh[ks][3], ql[ks][3]);
        }
    }

    float o[8][4];
#pragma unroll
    for (int nt = 0; nt < 8; nt++)
#pragma unroll
        for (int q = 0; q < 4; q++) o[nt][q] = 0.f;
    float mrow0 = -CUDART_INF_F, mrow1 = -CUDART_INF_F;
    float lrow0 = 0.f, lrow1 = 0.f;

    const int nkv = 2 * qt + 2;
    for (int kv = 0; kv < nkv; kv++) {
        const int k0 = kv * 64;

        // ---- load K (split) ----
        {
            const int r = tid >> 2;
            const int kg2 = (tid & 3) * 16;
            const float* src = Kg + (size_t)(k0 + r) * 64 + kg2;
            const uint32_t base = sb + (uint32_t)r * 144 + (uint32_t)kg2 * 2;
#pragma unroll
            for (int i = 0; i < 4; i++) {
                float4 f = *(const float4*)(src + 4 * i);
                uint32_t h0, l0, h1, l1;
                split2(f.x, f.y, h0, l0);
                split2(f.z, f.w, h1, l1);
                const uint32_t ad = base + 8 * i;
                STS32(ad + AT_KH, h0);
                STS32(ad + AT_KH + 4, h1);
                STS32(ad + AT_KL, l0);
                STS32(ad + AT_KL + 4, l1);
            }
        }
        // ---- load V transposed (split) ----
        {
            const int r = tid >> 2;
            const int dg = (tid & 3) * 16;
            const float* src = Vg + (size_t)(k0 + r) * 64 + dg;
            __nv_bfloat16* vh = (__nv_bfloat16*)(smraw + AT_VH);
            __nv_bfloat16* vl = (__nv_bfloat16*)(smraw + AT_VL);
#pragma unroll
            for (int i = 0; i < 4; i++) {
                float4 f = *(const float4*)(src + 4 * i);
                float vals[4] = {f.x, f.y, f.z, f.w};
#pragma unroll
                for (int c2 = 0; c2 < 4; c2++) {
                    const int d = dg + 4 * i + c2;
                    __nv_bfloat16 hv = __float2bfloat16(vals[c2]);
                    float lo = vals[c2] - __bfloat162float(hv);
                    vh[(size_t)d * 72 + r] = hv;
                    vl[(size_t)d * 72 + r] = __float2bfloat16(lo);
                }
            }
        }
        __syncthreads();

        if (k0 <= wrow + 15) {   // warp has unmasked rows in this tile
            // ---- S = Q K^T (3 passes) ----
            float s[8][4];
#pragma unroll
            for (int nt = 0; nt < 8; nt++)
#pragma unroll
                for (int q = 0; q < 4; q++) s[nt][q] = 0.f;

#pragma unroll
            for (int ks = 0; ks < 4; ks++) {
                uint32_t kbh[8][2], kbl[8][2];
#pragma unroll
                for (int nt = 0; nt < 8; nt++) {
                    const uint32_t ad = sb + (uint32_t)(nt * 8 + g) * 144 +
                                        (uint32_t)(ks * 16 + 2 * t4) * 2;
                    LDS32(kbh[nt][0], ad + AT_KH);
                    LDS32(kbh[nt][1], ad + AT_KH + 16);
                }
#pragma unroll
                for (int nt = 0; nt < 8; nt++) mma_bf16(s[nt], qh[ks], kbh[nt]);
#pragma unroll
                for (int nt = 0; nt < 8; nt++) mma_bf16(s[nt], ql[ks], kbh[nt]);
#pragma unroll
                for (int nt = 0; nt < 8; nt++) {
                    const uint32_t ad = sb + (uint32_t)(nt * 8 + g) * 144 +
                                        (uint32_t)(ks * 16 + 2 * t4) * 2;
                    LDS32(kbl[nt][0], ad + AT_KL);
                    LDS32(kbl[nt][1], ad + AT_KL + 16);
                }
#pragma unroll
                for (int nt = 0; nt < 8; nt++) mma_bf16(s[nt], qh[ks], kbl[nt]);
            }

            // ---- causal mask (only on diagonal-straddling tiles) ----
            if (k0 + 63 > wrow) {
#pragma unroll
                for (int nt = 0; nt < 8; nt++) {
                    const int col0 = k0 + nt * 8 + 2 * t4;
                    if (col0 > row0)      s[nt][0] = -CUDART_INF_F;
                    if (col0 + 1 > row0)  s[nt][1] = -CUDART_INF_F;
                    if (col0 > row0 + 8)     s[nt][2] = -CUDART_INF_F;
                    if (col0 + 1 > row0 + 8) s[nt][3] = -CUDART_INF_F;
                }
            }

            // ---- online softmax ----
            float mx0 = -CUDART_INF_F, mx1 = -CUDART_INF_F;
#pragma unroll
            for (int nt = 0; nt < 8; nt++) {
                mx0 = fmaxf(mx0, fmaxf(s[nt][0], s[nt][1]));
                mx1 = fmaxf(mx1, fmaxf(s[nt][2], s[nt][3]));
            }
            mx0 = fmaxf(mx0, __shfl_xor_sync(0xffffffffu, mx0, 1));
            mx0 = fmaxf(mx0, __shfl_xor_sync(0xffffffffu, mx0, 2));
            mx1 = fmaxf(mx1, __shfl_xor_sync(0xffffffffu, mx1, 1));
            mx1 = fmaxf(mx1, __shfl_xor_sync(0xffffffffu, mx1, 2));

            const float nm0 = fmaxf(mrow0, mx0);
            const float nm1 = fmaxf(mrow1, mx1);
            const float c0 = __expf(mrow0 - nm0);
            const float c1 = __expf(mrow1 - nm1);
            float sum0 = 0.f, sum1 = 0.f;
#pragma unroll
            for (int nt = 0; nt < 8; nt++) {
                s[nt][0] = __expf(s[nt][0] - nm0);
                s[nt][1] = __expf(s[nt][1] - nm0);
                s[nt][2] = __expf(s[nt][2] - nm1);
                s[nt][3] = __expf(s[nt][3] - nm1);
                sum0 += s[nt][0] + s[nt][1];
                sum1 += s[nt][2] + s[nt][3];
            }
            sum0 += __shfl_xor_sync(0xffffffffu, sum0, 1);
            sum0 += __shfl_xor_sync(0xffffffffu, sum0, 2);
            sum1 += __shfl_xor_sync(0xffffffffu, sum1, 1);
            sum1 += __shfl_xor_sync(0xffffffffu, sum1, 2);
            lrow0 = lrow0 * c0 + sum0;
            lrow1 = lrow1 * c1 + sum1;
            mrow0 = nm0;
            mrow1 = nm1;
#pragma unroll
            for (int nt = 0; nt < 8; nt++) {
                o[nt][0] *= c0;
                o[nt][1] *= c0;
                o[nt][2] *= c1;
                o[nt][3] *= c1;
            }

            // ---- P -> bf16 split A-frags ----
            uint32_t pah[4][4], pal[4][4];
#pragma unroll
            for (int kk = 0; kk < 4; kk++) {
                split2(s[2 * kk][0], s[2 * kk][1], pah[kk][0], pal[kk][0]);
                split2(s[2 * kk][2], s[2 * kk][3], pah[kk][1], pal[kk][1]);
                split2(s[2 * kk + 1][0], s[2 * kk + 1][1], pah[kk][2], pal[kk][2]);
                split2(s[2 * kk + 1][2], s[2 * kk + 1][3], pah[kk][3], pal[kk][3]);
            }

            // ---- O += P V (3 passes) ----
#pragma unroll
            for (int kk = 0; kk < 4; kk++) {
                uint32_t vbh[8][2], vbl[8][2];
#pragma unroll
                for (int nt = 0; nt < 8; nt++) {
                    const uint32_t ad = sb + (uint32_t)(nt * 8 + g) * 144 +
                                        (uint32_t)(kk * 16 + 2 * t4) * 2;
                    LDS32(vbh[nt][0], ad + AT_VH);
                    LDS32(vbh[nt][1], ad + AT_VH + 16);
                }
#pragma unroll
                for (int nt = 0; nt < 8; nt++) mma_bf16(o[nt], pah[kk], vbh[nt]);
#pragma unroll
                for (int nt = 0; nt < 8; nt++) mma_bf16(o[nt], pal[kk], vbh[nt]);
#pragma unroll
                for (int nt = 0; nt < 8; nt++) {
                    const uint32_t ad = sb + (uint32_t)(nt * 8 + g) * 144 +
                                        (uint32_t)(kk * 16 + 2 * t4) * 2;
                    LDS32(vbl[nt][0], ad + AT_VL);
                    LDS32(vbl[nt][1], ad + AT_VL + 16);
                }
#pragma unroll
                for (int nt = 0; nt < 8; nt++) mma_bf16(o[nt], pah[kk], vbl[nt]);
            }
        }
        __syncthreads();
    }

    // ---- epilogue: divide by l, write ctx [b, s, h*64+d] ----
    const float inv0 = 1.f / lrow0;
    const float inv1 = 1.f / lrow1;
    float* dst0 = g_ctx + ((size_t)(b * S_ + row0)) * D_ + h * HD_;
    float* dst1 = g_ctx + ((size_t)(b * S_ + row0 + 8)) * D_ + h * HD_;
#pragma unroll
    for (int nt = 0; nt < 8; nt++) {
        const int d = nt * 8 + 2 * t4;
        *(float2*)(dst0 + d) = make_float2(o[nt][0] * inv0, o[nt][1] * inv0);
        *(float2*)(dst1 + d) = make_float2(o[nt][2] * inv1, o[nt][3] * inv1);
    }
}

// ---------------------------------------------------------------------------
extern "C" void kernel_launch(void* const* d_in, const int* in_sizes, int n_in,
                              void* d_out, int out_size)
{
    const float* q  = (const float*)d_in[0];
    const float* k  = (const float*)d_in[1];
    const float* v  = (const float*)d_in[2];
    const float* wq = (const float*)d_in[3];
    const float* wk = (const float*)d_in[4];
    const float* wv = (const float*)d_in[5];
    const float* wo = (const float*)d_in[6];
    float* out = (float*)d_out;

    wsplit_k<<<dim3(32, 32, 4), dim3(32, 8)>>>(wq, wk, wv, wo);

    cudaFuncSetAttribute(gemm_mma, cudaFuncAttributeMaxDynamicSharedMemorySize, G_SMEM);

    gemm_mma<<<dim3(8, 64, 3), 256, G_SMEM>>>(q, k, v, nullptr, 0);   // QKV fused

    attn_k<<<dim3(16, 16, 4), 256>>>();

    gemm_mma<<<dim3(8, 64, 1), 256, G_SMEM>>>(q, k, v, out, 3);       // O projection
}

// round 6
// speedup vs baseline: 2.6064x; 1.1028x over previous
#include <cuda_runtime.h>
#include <cuda_bf16.h>
#include <math_constants.h>
#include <cstdint>

#define B_  4
#define S_  2048
#define D_  1024
#define H_  16
#define HD_ 64
#define NEL (8ull * 1024 * 1024)   // 8192*1024 elements per matrix

// Scratch (device globals: allocation-free rule). All activations stored as
// bf16 hi/lo pairs (x ~= hi + lo, error ~2^-17 relative).
__device__ __nv_bfloat16 g_inh[3 * NEL], g_inl[3 * NEL];   // q,k,v inputs [m][k]
__device__ __nv_bfloat16 g_qh[NEL], g_ql[NEL];             // xq [b,h,s,dh]
__device__ __nv_bfloat16 g_kh[NEL], g_kl[NEL];             // xk
__device__ __nv_bfloat16 g_vh[NEL], g_vl[NEL];             // xv
__device__ __nv_bfloat16 g_cth[NEL], g_ctl[NEL];           // ctx [b,s,d]
__device__ __nv_bfloat16 g_wth[4 * NEL / 8], g_wtl[4 * NEL / 8];  // W^T [n][k] x4

__device__ __forceinline__ uint32_t smem_u32(const void* p) {
    uint32_t a;
    asm("{ .reg .u64 t; cvta.to.shared.u64 t, %1; cvt.u32.u64 %0, t; }" : "=r"(a) : "l"(p));
    return a;
}

#define STS16(addr, v) \
    asm volatile("st.shared.u16 [%0], %1;" :: "r"(addr), "h"((unsigned short)(v)) : "memory")
#define LDS32(r, addr) \
    asm volatile("ld.shared.b32 %0, [%1];" : "=r"(r) : "r"(addr))
#define CP_ASYNC16(dst, src) \
    asm volatile("cp.async.cg.shared.global [%0], [%1], 16;" :: "r"(dst), "l"(src) : "memory")
#define CP_COMMIT() asm volatile("cp.async.commit_group;" ::: "memory")
#define CP_WAIT(n)  asm volatile("cp.async.wait_group %0;" :: "n"(n) : "memory")

__device__ __forceinline__ void mma_bf16(float* d, const uint32_t* a, const uint32_t* b) {
    asm volatile(
        "mma.sync.aligned.m16n8k16.row.col.f32.bf16.bf16.f32 "
        "{%0,%1,%2,%3}, {%4,%5,%6,%7}, {%8,%9}, {%0,%1,%2,%3};"
        : "+f"(d[0]), "+f"(d[1]), "+f"(d[2]), "+f"(d[3])
        : "r"(a[0]), "r"(a[1]), "r"(a[2]), "r"(a[3]), "r"(b[0]), "r"(b[1]));
}

__device__ __forceinline__ void split2(float x, float y, uint32_t& hi, uint32_t& lo) {
    __nv_bfloat162 h = __floats2bfloat162_rn(x, y);
    float rx = x - __bfloat162float(h.x);
    float ry = y - __bfloat162float(h.y);
    __nv_bfloat162 l = __floats2bfloat162_rn(rx, ry);
    hi = reinterpret_cast<uint32_t&>(h);
    lo = reinterpret_cast<uint32_t&>(l);
}

// ---------------------------------------------------------------------------
// Activation split: q/k/v fp32 -> bf16 hi/lo (straight layout [m][k])
// ---------------------------------------------------------------------------
__global__ __launch_bounds__(256) void asplit_k(const float* __restrict__ q,
                                                const float* __restrict__ k,
                                                const float* __restrict__ v) {
    const int z = blockIdx.y;
    const float* src = (z == 0) ? q : (z == 1) ? k : v;
    const size_t i = ((size_t)blockIdx.x * 256 + threadIdx.x) * 4;
    float4 f = *(const float4*)(src + i);
    uint32_t h0, l0, h1, l1;
    split2(f.x, f.y, h0, l0);
    split2(f.z, f.w, h1, l1);
    *(uint2*)&g_inh[z * NEL + i] = make_uint2(h0, h1);
    *(uint2*)&g_inl[z * NEL + i] = make_uint2(l0, l1);
}

// ---------------------------------------------------------------------------
// Weight transpose + bf16 hi/lo split: Wt[n][k] = W[k][n]  (4 weights, z-dim)
// ---------------------------------------------------------------------------
__global__ __launch_bounds__(256) void wsplit_k(const float* __restrict__ w0,
                                                const float* __restrict__ w1,
                                                const float* __restrict__ w2,
                                                const float* __restrict__ w3) {
    __shared__ float t[32][33];
    const int widx = blockIdx.z;
    const float* W = (widx == 0) ? w0 : (widx == 1) ? w1 : (widx == 2) ? w2 : w3;
    const int n0 = blockIdx.x * 32, k0 = blockIdx.y * 32;
    const int tx = threadIdx.x, ty = threadIdx.y;
#pragma unroll
    for (int i = 0; i < 32; i += 8)
        t[ty + i][tx] = W[(size_t)(k0 + ty + i) * 1024 + n0 + tx];
    __syncthreads();
    __nv_bfloat16* Th = g_wth + (size_t)widx * 1024 * 1024;
    __nv_bfloat16* Tl = g_wtl + (size_t)widx * 1024 * 1024;
#pragma unroll
    for (int i = 0; i < 32; i += 8) {
        const int n = n0 + ty + i, k = k0 + tx;
        float x = t[tx][ty + i];
        __nv_bfloat16 h = __float2bfloat16(x);
        float lo = x - __bfloat162float(h);
        Th[(size_t)n * 1024 + k] = h;
        Tl[(size_t)n * 1024 + k] = __float2bfloat16(lo);
    }
}

// ---------------------------------------------------------------------------
// Split-bf16 HMMA GEMM, all-cp.async 2-stage pipeline, 1 sync per chunk.
// BM=128, BN=128, BK=32, 256 threads, 8 warps each 32x64, 2 CTAs/SM.
// ---------------------------------------------------------------------------
#define GA_H 0
#define GA_L 10240
#define GB_H 20480
#define GB_L 30720
#define GST  40960
#define G_SMEM (2 * GST)   // 81920

extern __shared__ unsigned char g_dynsm[];

__global__ __launch_bounds__(256, 2)
void gemm_mma(float* __restrict__ Cout, int mode_base)
{
    const uint32_t sb = smem_u32(g_dynsm);

    const int tid = threadIdx.x;
    const int wid = tid >> 5;
    const int lid = tid & 31;
    const int g = lid >> 2;
    const int t4 = lid & 3;
    const int wm = wid & 3;
    const int wn = wid >> 2;

    const int mode = (mode_base == 3) ? 3 : (int)blockIdx.z;
    const __nv_bfloat16* Ah = (mode == 3) ? g_cth : g_inh + (size_t)mode * NEL;
    const __nv_bfloat16* Al = (mode == 3) ? g_ctl : g_inl + (size_t)mode * NEL;
    const __nv_bfloat16* Bh = g_wth + (size_t)mode * 1024 * 1024;
    const __nv_bfloat16* Bl = g_wtl + (size_t)mode * 1024 * 1024;

    const int m0 = blockIdx.y * 128;
    const int n0 = blockIdx.x * 128;

    // loader mapping: row lr, 16-element half khalf
    const int lr = tid >> 1;
    const int khalf = (tid & 1) * 16;
    const __nv_bfloat16* sAh = Ah + (size_t)(m0 + lr) * 1024 + khalf;
    const __nv_bfloat16* sAl = Al + (size_t)(m0 + lr) * 1024 + khalf;
    const __nv_bfloat16* sBh = Bh + (size_t)(n0 + lr) * 1024 + khalf;
    const __nv_bfloat16* sBl = Bl + (size_t)(n0 + lr) * 1024 + khalf;
    const uint32_t drow = (uint32_t)lr * 80 + (uint32_t)khalf * 2;

    float acc[2][8][4];
#pragma unroll
    for (int mt = 0; mt < 2; mt++)
#pragma unroll
        for (int nt = 0; nt < 8; nt++)
#pragma unroll
            for (int q = 0; q < 4; q++) acc[mt][nt][q] = 0.f;

    const uint32_t aRow0 = (uint32_t)(wm * 32 + g);
    const uint32_t bRow0 = (uint32_t)(wn * 64 + g);

#define G_ISSUE(stg, c) do {                                     \
        const uint32_t d_ = sb + (uint32_t)(stg) * GST + drow;   \
        const int kg_ = (c) * 32;                                \
        CP_ASYNC16(d_ + GA_H,      sAh + kg_);                   \
        CP_ASYNC16(d_ + GA_H + 16, sAh + kg_ + 8);               \
        CP_ASYNC16(d_ + GA_L,      sAl + kg_);                   \
        CP_ASYNC16(d_ + GA_L + 16, sAl + kg_ + 8);               \
        CP_ASYNC16(d_ + GB_H,      sBh + kg_);                   \
        CP_ASYNC16(d_ + GB_H + 16, sBh + kg_ + 8);               \
        CP_ASYNC16(d_ + GB_L,      sBl + kg_);                   \
        CP_ASYNC16(d_ + GB_L + 16, sBl + kg_ + 8);               \
        CP_COMMIT();                                             \
    } while (0)

    G_ISSUE(0, 0);

    for (int c = 0; c < 32; c++) {
        CP_WAIT(0);            // chunk c landed
        __syncthreads();       // + all warps done with stage (c+1)&1's old data
        if (c < 31) G_ISSUE((c + 1) & 1, c + 1);

        const uint32_t sS = sb + (uint32_t)(c & 1) * GST;
#pragma unroll
        for (int kk = 0; kk < 2; kk++) {
            const uint32_t kof = (uint32_t)kk * 32 + (uint32_t)t4 * 4;

            uint32_t ah[2][4], al[2][4], bhf[8][2], blf[8][2];
#pragma unroll
            for (int mt = 0; mt < 2; mt++) {
                const uint32_t ab = sS + GA_H + (aRow0 + mt * 16) * 80 + kof;
                LDS32(ah[mt][0], ab);
                LDS32(ah[mt][1], ab + 640);
                LDS32(ah[mt][2], ab + 16);
                LDS32(ah[mt][3], ab + 656);
            }
#pragma unroll
            for (int nt = 0; nt < 8; nt++) {
                const uint32_t bb = sS + GB_H + (bRow0 + nt * 8) * 80 + kof;
                LDS32(bhf[nt][0], bb);
                LDS32(bhf[nt][1], bb + 16);
            }
#pragma unroll
            for (int mt = 0; mt < 2; mt++)
#pragma unroll
                for (int nt = 0; nt < 8; nt++)
                    mma_bf16(acc[mt][nt], ah[mt], bhf[nt]);

#pragma unroll
            for (int mt = 0; mt < 2; mt++) {
                const uint32_t ab = sS + GA_L + (aRow0 + mt * 16) * 80 + kof;
                LDS32(al[mt][0], ab);
                LDS32(al[mt][1], ab + 640);
                LDS32(al[mt][2], ab + 16);
                LDS32(al[mt][3], ab + 656);
            }
#pragma unroll
            for (int mt = 0; mt < 2; mt++)
#pragma unroll
                for (int nt = 0; nt < 8; nt++)
                    mma_bf16(acc[mt][nt], al[mt], bhf[nt]);

#pragma unroll
            for (int nt = 0; nt < 8; nt++) {
                const uint32_t bb = sS + GB_L + (bRow0 + nt * 8) * 80 + kof;
                LDS32(blf[nt][0], bb);
                LDS32(blf[nt][1], bb + 16);
            }
#pragma unroll
            for (int mt = 0; mt < 2; mt++)
#pragma unroll
                for (int nt = 0; nt < 8; nt++)
                    mma_bf16(acc[mt][nt], ah[mt], blf[nt]);
        }
    }

    // epilogue
    if (mode < 3) {
        __nv_bfloat16* OH = (mode == 0) ? g_qh : (mode == 1) ? g_kh : g_vh;
        __nv_bfloat16* OL = (mode == 0) ? g_ql : (mode == 1) ? g_kl : g_vl;
#pragma unroll
        for (int mt = 0; mt < 2; mt++) {
#pragma unroll
            for (int nt = 0; nt < 8; nt++) {
                const int row0 = m0 + wm * 32 + mt * 16 + g;
                const int col = n0 + wn * 64 + nt * 8 + t4 * 2;
                const int h = col >> 6, dh = col & 63;
                uint32_t hw, lw;
                {
                    const int bb = row0 >> 11, sq = row0 & 2047;
                    const size_t idx = (((size_t)(bb * H_ + h) * S_) + sq) * HD_ + dh;
                    split2(acc[mt][nt][0], acc[mt][nt][1], hw, lw);
                    *(uint32_t*)&OH[idx] = hw;
                    *(uint32_t*)&OL[idx] = lw;
                }
                {
                    const int row1 = row0 + 8;
                    const int bb = row1 >> 11, sq = row1 & 2047;
                    const size_t idx = (((size_t)(bb * H_ + h) * S_) + sq) * HD_ + dh;
                    split2(acc[mt][nt][2], acc[mt][nt][3], hw, lw);
                    *(uint32_t*)&OH[idx] = hw;
                    *(uint32_t*)&OL[idx] = lw;
                }
            }
        }
    } else {
#pragma unroll
        for (int mt = 0; mt < 2; mt++) {
#pragma unroll
            for (int nt = 0; nt < 8; nt++) {
                const int row0 = m0 + wm * 32 + mt * 16 + g;
                const int col = n0 + wn * 64 + nt * 8 + t4 * 2;
                *(float2*)&Cout[(size_t)row0 * 1024 + col] =
                    make_float2(acc[mt][nt][0], acc[mt][nt][1]);
                *(float2*)&Cout[(size_t)(row0 + 8) * 1024 + col] =
                    make_float2(acc[mt][nt][2], acc[mt][nt][3]);
            }
        }
    }
}

// ---------------------------------------------------------------------------
// Flash attention on HMMA, pre-split bf16 operands, causal.
// Bq=128, Bk=64, 8 warps (16 rows each), register softmax.
// smem: Kh/Kl [64 rows x 144B], Vth/Vtl (transposed) [64 x 144B].
// ---------------------------------------------------------------------------
#define AT_KH 0
#define AT_KL 9216
#define AT_VH 18432
#define AT_VL 27648
#define AT_SMEM 36864

__global__ __launch_bounds__(256) void attn_k()
{
    __shared__ __align__(16) unsigned char smraw[AT_SMEM];
    const uint32_t sb = smem_u32(smraw);

    const int tid = threadIdx.x;
    const int wid = tid >> 5;
    const int lid = tid & 31;
    const int g = lid >> 2;
    const int t4 = lid & 3;
    const int qt = 15 - (int)blockIdx.x;   // big tiles first
    const int h = blockIdx.y;
    const int b = blockIdx.z;
    const int q0 = qt * 128;
    const size_t bho = (size_t)(b * H_ + h) * S_ * HD_;

    const int wrow = q0 + wid * 16;
    const int row0 = wrow + g;

    // Q fragments directly from pre-split gmem
    uint32_t qh[4][4], ql[4][4];
    {
        const uint32_t* qhp = (const uint32_t*)(g_qh + bho);
        const uint32_t* qlp = (const uint32_t*)(g_ql + bho);
        const int ra = row0 * 32;          // uint32 index of row start (64 bf16 = 32 words)
        const int rb = (row0 + 8) * 32;
#pragma unroll
        for (int ks = 0; ks < 4; ks++) {
            const int kw = ks * 8 + t4;    // word index of element ks*16 + 2*t4
            qh[ks][0] = qhp[ra + kw];
            qh[ks][1] = qhp[rb + kw];
            qh[ks][2] = qhp[ra + kw + 4];
            qh[ks][3] = qhp[rb + kw + 4];
            ql[ks][0] = qlp[ra + kw];
            ql[ks][1] = qlp[rb + kw];
            ql[ks][2] = qlp[ra + kw + 4];
            ql[ks][3] = qlp[rb + kw + 4];
        }
    }

    float o[8][4];
#pragma unroll
    for (int nt = 0; nt < 8; nt++)
#pragma unroll
        for (int q = 0; q < 4; q++) o[nt][q] = 0.f;
    float mrow0 = -CUDART_INF_F, mrow1 = -CUDART_INF_F;
    float lrow0 = 0.f, lrow1 = 0.f;

    const int nkv = 2 * qt + 2;
    for (int kv = 0; kv < nkv; kv++) {
        const int k0 = kv * 64;

        // ---- K tiles via cp.async (row copy, 128B/row) ----
        {
            const int r = tid >> 2;
            const uint32_t part = (uint32_t)(tid & 3) * 32;
            const char* khp = (const char*)(g_kh + bho) + (size_t)(k0 + r) * 128 + part;
            const char* klp = (const char*)(g_kl + bho) + (size_t)(k0 + r) * 128 + part;
            const uint32_t dst = sb + (uint32_t)r * 144 + part;
            CP_ASYNC16(dst + AT_KH, khp);
            CP_ASYNC16(dst + AT_KH + 16, khp + 16);
            CP_ASYNC16(dst + AT_KL, klp);
            CP_ASYNC16(dst + AT_KL + 16, klp + 16);
            CP_COMMIT();
        }
        // ---- V transposed scatter (bf16, no conversion) ----
        {
            const int r = tid >> 2;
            const int dg = (tid & 3) * 16;
            const uint32_t* vhp = (const uint32_t*)(g_vh + bho + (size_t)(k0 + r) * 64 + dg);
            const uint32_t* vlp = (const uint32_t*)(g_vl + bho + (size_t)(k0 + r) * 64 + dg);
#pragma unroll
            for (int w = 0; w < 8; w++) {
                const uint32_t vh = vhp[w];
                const uint32_t vl = vlp[w];
                const int d = dg + 2 * w;
                const uint32_t a0 = sb + (uint32_t)(d * 72 + r) * 2;
                const uint32_t a1 = sb + (uint32_t)((d + 1) * 72 + r) * 2;
                STS16(a0 + AT_VH, vh);
                STS16(a1 + AT_VH, vh >> 16);
                STS16(a0 + AT_VL, vl);
                STS16(a1 + AT_VL, vl >> 16);
            }
        }
        CP_WAIT(0);
        __syncthreads();

        if (k0 <= wrow + 15) {   // warp has unmasked rows in this tile
            // ---- S = Q K^T (3 passes) ----
            float s[8][4];
#pragma unroll
            for (int nt = 0; nt < 8; nt++)
#pragma unroll
                for (int q = 0; q < 4; q++) s[nt][q] = 0.f;

#pragma unroll
            for (int ks = 0; ks < 4; ks++) {
                uint32_t kbh[8][2], kbl[8][2];
#pragma unroll
                for (int nt = 0; nt < 8; nt++) {
                    const uint32_t ad = sb + (uint32_t)(nt * 8 + g) * 144 +
                                        (uint32_t)(ks * 16 + 2 * t4) * 2;
                    LDS32(kbh[nt][0], ad + AT_KH);
                    LDS32(kbh[nt][1], ad + AT_KH + 16);
                }
#pragma unroll
                for (int nt = 0; nt < 8; nt++) mma_bf16(s[nt], qh[ks], kbh[nt]);
#pragma unroll
                for (int nt = 0; nt < 8; nt++) mma_bf16(s[nt], ql[ks], kbh[nt]);
#pragma unroll
                for (int nt = 0; nt < 8; nt++) {
                    const uint32_t ad = sb + (uint32_t)(nt * 8 + g) * 144 +
                                        (uint32_t)(ks * 16 + 2 * t4) * 2;
                    LDS32(kbl[nt][0], ad + AT_KL);
                    LDS32(kbl[nt][1], ad + AT_KL + 16);
                }
#pragma unroll
                for (int nt = 0; nt < 8; nt++) mma_bf16(s[nt], qh[ks], kbl[nt]);
            }

            // ---- scale (1/sqrt(64) = 1/8, exact) ----
#pragma unroll
            for (int nt = 0; nt < 8; nt++)
#pragma unroll
                for (int q = 0; q < 4; q++) s[nt][q] *= 0.125f;

            // ---- causal mask (only diagonal-straddling tiles) ----
            if (k0 + 63 > wrow) {
#pragma unroll
                for (int nt = 0; nt < 8; nt++) {
                    const int col0 = k0 + nt * 8 + 2 * t4;
                    if (col0 > row0)         s[nt][0] = -CUDART_INF_F;
                    if (col0 + 1 > row0)     s[nt][1] = -CUDART_INF_F;
                    if (col0 > row0 + 8)     s[nt][2] = -CUDART_INF_F;
                    if (col0 + 1 > row0 + 8) s[nt][3] = -CUDART_INF_F;
                }
            }

            // ---- online softmax ----
            float mx0 = -CUDART_INF_F, mx1 = -CUDART_INF_F;
#pragma unroll
            for (int nt = 0; nt < 8; nt++) {
                mx0 = fmaxf(mx0, fmaxf(s[nt][0], s[nt][1]));
                mx1 = fmaxf(mx1, fmaxf(s[nt][2], s[nt][3]));
            }
            mx0 = fmaxf(mx0, __shfl_xor_sync(0xffffffffu, mx0, 1));
            mx0 = fmaxf(mx0, __shfl_xor_sync(0xffffffffu, mx0, 2));
            mx1 = fmaxf(mx1, __shfl_xor_sync(0xffffffffu, mx1, 1));
            mx1 = fmaxf(mx1, __shfl_xor_sync(0xffffffffu, mx1, 2));

            const float nm0 = fmaxf(mrow0, mx0);
            const float nm1 = fmaxf(mrow1, mx1);
            const float c0 = __expf(mrow0 - nm0);
            const float c1 = __expf(mrow1 - nm1);
            float sum0 = 0.f, sum1 = 0.f;
#pragma unroll
            for (int nt = 0; nt < 8; nt++) {
                s[nt][0] = __expf(s[nt][0] - nm0);
                s[nt][1] = __expf(s[nt][1] - nm0);
                s[nt][2] = __expf(s[nt][2] - nm1);
                s[nt][3] = __expf(s[nt][3] - nm1);
                sum0 += s[nt][0] + s[nt][1];
                sum1 += s[nt][2] + s[nt][3];
            }
            sum0 += __shfl_xor_sync(0xffffffffu, sum0, 1);
            sum0 += __shfl_xor_sync(0xffffffffu, sum0, 2);
            sum1 += __shfl_xor_sync(0xffffffffu, sum1, 1);
            sum1 += __shfl_xor_sync(0xffffffffu, sum1, 2);
            lrow0 = lrow0 * c0 + sum0;
            lrow1 = lrow1 * c1 + sum1;
            mrow0 = nm0;
            mrow1 = nm1;
#pragma unroll
            for (int nt = 0; nt < 8; nt++) {
                o[nt][0] *= c0;
                o[nt][1] *= c0;
                o[nt][2] *= c1;
                o[nt][3] *= c1;
            }

            // ---- P -> bf16 split A-frags ----
            uint32_t pah[4][4], pal[4][4];
#pragma unroll
            for (int kk = 0; kk < 4; kk++) {
                split2(s[2 * kk][0], s[2 * kk][1], pah[kk][0], pal[kk][0]);
                split2(s[2 * kk][2], s[2 * kk][3], pah[kk][1], pal[kk][1]);
                split2(s[2 * kk + 1][0], s[2 * kk + 1][1], pah[kk][2], pal[kk][2]);
                split2(s[2 * kk + 1][2], s[2 * kk + 1][3], pah[kk][3], pal[kk][3]);
            }

            // ---- O += P V (3 passes) ----
#pragma unroll
            for (int kk = 0; kk < 4; kk++) {
                uint32_t vbh[8][2], vbl[8][2];
#pragma unroll
                for (int nt = 0; nt < 8; nt++) {
                    const uint32_t ad = sb + (uint32_t)(nt * 8 + g) * 144 +
                                        (uint32_t)(kk * 16 + 2 * t4) * 2;
                    LDS32(vbh[nt][0], ad + AT_VH);
                    LDS32(vbh[nt][1], ad + AT_VH + 16);
                }
#pragma unroll
                for (int nt = 0; nt < 8; nt++) mma_bf16(o[nt], pah[kk], vbh[nt]);
#pragma unroll
                for (int nt = 0; nt < 8; nt++) mma_bf16(o[nt], pal[kk], vbh[nt]);
#pragma unroll
                for (int nt = 0; nt < 8; nt++) {
                    const uint32_t ad = sb + (uint32_t)(nt * 8 + g) * 144 +
                                        (uint32_t)(kk * 16 + 2 * t4) * 2;
                    LDS32(vbl[nt][0], ad + AT_VL);
                    LDS32(vbl[nt][1], ad + AT_VL + 16);
                }
#pragma unroll
                for (int nt = 0; nt < 8; nt++) mma_bf16(o[nt], pah[kk], vbl[nt]);
            }
        }
        __syncthreads();
    }

    // ---- epilogue: divide by l, split, write ctx hi/lo [b, s, h*64+d] ----
    const float inv0 = 1.f / lrow0;
    const float inv1 = 1.f / lrow1;
    const size_t base0 = ((size_t)(b * S_ + row0)) * D_ + h * HD_;
    const size_t base1 = ((size_t)(b * S_ + row0 + 8)) * D_ + h * HD_;
#pragma unroll
    for (int nt = 0; nt < 8; nt++) {
        const int d = nt * 8 + 2 * t4;
        uint32_t hw, lw;
        split2(o[nt][0] * inv0, o[nt][1] * inv0, hw, lw);
        *(uint32_t*)&g_cth[base0 + d] = hw;
        *(uint32_t*)&g_ctl[base0 + d] = lw;
        split2(o[nt][2] * inv1, o[nt][3] * inv1, hw, lw);
        *(uint32_t*)&g_cth[base1 + d] = hw;
        *(uint32_t*)&g_ctl[base1 + d] = lw;
    }
}

// ---------------------------------------------------------------------------
extern "C" void kernel_launch(void* const* d_in, const int* in_sizes, int n_in,
                              void* d_out, int out_size)
{
    const float* q  = (const float*)d_in[0];
    const float* k  = (const float*)d_in[1];
    const float* v  = (const float*)d_in[2];
    const float* wq = (const float*)d_in[3];
    const float* wk = (const float*)d_in[4];
    const float* wv = (const float*)d_in[5];
    const float* wo = (const float*)d_in[6];
    float* out = (float*)d_out;

    asplit_k<<<dim3(8192, 3), 256>>>(q, k, v);
    wsplit_k<<<dim3(32, 32, 4), dim3(32, 8)>>>(wq, wk, wv, wo);

    cudaFuncSetAttribute(gemm_mma, cudaFuncAttributeMaxDynamicSharedMemorySize, G_SMEM);

    gemm_mma<<<dim3(8, 64, 3), 256, G_SMEM>>>(nullptr, 0);   // QKV fused

    attn_k<<<dim3(16, 16, 4), 256>>>();

    gemm_mma<<<dim3(8, 64, 1), 256, G_SMEM>>>(out, 3);       // O projection
}

// round 8
// speedup vs baseline: 3.1930x; 1.2251x over previous
#include <cuda_runtime.h>
#include <cuda_bf16.h>
#include <math_constants.h>
#include <cstdint>

#define B_  4
#define S_  2048
#define D_  1024
#define H_  16
#define HD_ 64
#define NEL (8ull * 1024 * 1024)   // 8192*1024 elements per matrix

// Scratch (device globals). All activations stored as bf16 hi/lo pairs.
__device__ __nv_bfloat16 g_inh[3 * NEL], g_inl[3 * NEL];   // q,k,v inputs [m][k]
__device__ __nv_bfloat16 g_qh[NEL], g_ql[NEL];             // xq [b,h,s,dh]
__device__ __nv_bfloat16 g_kh[NEL], g_kl[NEL];             // xk
__device__ __nv_bfloat16 g_vh[NEL], g_vl[NEL];             // xv
__device__ __nv_bfloat16 g_cth[NEL], g_ctl[NEL];           // ctx [b,s,d]
__device__ __nv_bfloat16 g_wth[4 * NEL / 8], g_wtl[4 * NEL / 8];  // W^T [n][k] x4

__device__ __forceinline__ uint32_t smem_u32(const void* p) {
    uint32_t a;
    asm("{ .reg .u64 t; cvta.to.shared.u64 t, %1; cvt.u32.u64 %0, t; }" : "=r"(a) : "l"(p));
    return a;
}

#define LDSM4(r0, r1, r2, r3, a) \
    asm volatile("ldmatrix.sync.aligned.m8n8.x4.shared.b16 {%0,%1,%2,%3}, [%4];" \
                 : "=r"(r0), "=r"(r1), "=r"(r2), "=r"(r3) : "r"(a))
#define LDSM4T(r0, r1, r2, r3, a) \
    asm volatile("ldmatrix.sync.aligned.m8n8.x4.trans.shared.b16 {%0,%1,%2,%3}, [%4];" \
                 : "=r"(r0), "=r"(r1), "=r"(r2), "=r"(r3) : "r"(a))
#define CP_ASYNC16(dst, src) \
    asm volatile("cp.async.cg.shared.global [%0], [%1], 16;" :: "r"(dst), "l"(src) : "memory")
#define CP_COMMIT() asm volatile("cp.async.commit_group;" ::: "memory")
#define CP_WAIT(n)  asm volatile("cp.async.wait_group %0;" :: "n"(n) : "memory")

__device__ __forceinline__ void mma_bf16(float* d, const uint32_t* a, const uint32_t* b) {
    asm volatile(
        "mma.sync.aligned.m16n8k16.row.col.f32.bf16.bf16.f32 "
        "{%0,%1,%2,%3}, {%4,%5,%6,%7}, {%8,%9}, {%0,%1,%2,%3};"
        : "+f"(d[0]), "+f"(d[1]), "+f"(d[2]), "+f"(d[3])
        : "r"(a[0]), "r"(a[1]), "r"(a[2]), "r"(a[3]), "r"(b[0]), "r"(b[1]));
}

__device__ __forceinline__ void split2(float x, float y, uint32_t& hi, uint32_t& lo) {
    __nv_bfloat162 h = __floats2bfloat162_rn(x, y);
    float rx = x - __bfloat162float(h.x);
    float ry = y - __bfloat162float(h.y);
    __nv_bfloat162 l = __floats2bfloat162_rn(rx, ry);
    hi = reinterpret_cast<uint32_t&>(h);
    lo = reinterpret_cast<uint32_t&>(l);
}

// ---------------------------------------------------------------------------
// Activation split: q/k/v fp32 -> bf16 hi/lo
// ---------------------------------------------------------------------------
__global__ __launch_bounds__(256) void asplit_k(const float* __restrict__ q,
                                                const float* __restrict__ k,
                                                const float* __restrict__ v) {
    const int z = blockIdx.y;
    const float* src = (z == 0) ? q : (z == 1) ? k : v;
    const size_t i = ((size_t)blockIdx.x * 256 + threadIdx.x) * 4;
    float4 f = *(const float4*)(src + i);
    uint32_t h0, l0, h1, l1;
    split2(f.x, f.y, h0, l0);
    split2(f.z, f.w, h1, l1);
    *(uint2*)&g_inh[z * NEL + i] = make_uint2(h0, h1);
    *(uint2*)&g_inl[z * NEL + i] = make_uint2(l0, l1);
}

// ---------------------------------------------------------------------------
// Weight transpose + bf16 hi/lo split: Wt[n][k] = W[k][n]
// ---------------------------------------------------------------------------
__global__ __launch_bounds__(256) void wsplit_k(const float* __restrict__ w0,
                                                const float* __restrict__ w1,
                                                const float* __restrict__ w2,
                                                const float* __restrict__ w3) {
    __shared__ float t[32][33];
    const int widx = blockIdx.z;
    const float* W = (widx == 0) ? w0 : (widx == 1) ? w1 : (widx == 2) ? w2 : w3;
    const int n0 = blockIdx.x * 32, k0 = blockIdx.y * 32;
    const int tx = threadIdx.x, ty = threadIdx.y;
#pragma unroll
    for (int i = 0; i < 32; i += 8)
        t[ty + i][tx] = W[(size_t)(k0 + ty + i) * 1024 + n0 + tx];
    __syncthreads();
    __nv_bfloat16* Th = g_wth + (size_t)widx * 1024 * 1024;
    __nv_bfloat16* Tl = g_wtl + (size_t)widx * 1024 * 1024;
#pragma unroll
    for (int i = 0; i < 32; i += 8) {
        const int n = n0 + ty + i, k = k0 + tx;
        float x = t[tx][ty + i];
        __nv_bfloat16 h = __float2bfloat16(x);
        float lo = x - __bfloat162float(h);
        Th[(size_t)n * 1024 + k] = h;
        Tl[(size_t)n * 1024 + k] = __float2bfloat16(lo);
    }
}

// ---------------------------------------------------------------------------
// Split-bf16 HMMA GEMM, cp.async 2-stage, ldmatrix fragment loads.
// BM=128, BN=128, BK=32, 256 threads, 8 warps each 32x64, 2 CTAs/SM.
// ---------------------------------------------------------------------------
#define GA_H 0
#define GA_L 10240
#define GB_H 20480
#define GB_L 30720
#define GST  40960
#define G_SMEM (2 * GST)   // 81920

extern __shared__ unsigned char g_dynsm[];

__global__ __launch_bounds__(256, 2)
void gemm_mma(float* __restrict__ Cout, int mode_base)
{
    const uint32_t sb = smem_u32(g_dynsm);

    const int tid = threadIdx.x;
    const int wid = tid >> 5;
    const int lid = tid & 31;
    const int g = lid >> 2;
    const int t4 = lid & 3;
    const int wm = wid & 3;
    const int wn = wid >> 2;
    const int lrow = lid & 7;
    const int mlo = (lid >> 3) & 1;
    const int mhi = (lid >> 4) & 1;

    const int mode = (mode_base == 3) ? 3 : (int)blockIdx.z;
    const __nv_bfloat16* Ah = (mode == 3) ? g_cth : g_inh + (size_t)mode * NEL;
    const __nv_bfloat16* Al = (mode == 3) ? g_ctl : g_inl + (size_t)mode * NEL;
    const __nv_bfloat16* Bh = g_wth + (size_t)mode * 1024 * 1024;
    const __nv_bfloat16* Bl = g_wtl + (size_t)mode * 1024 * 1024;

    const int m0 = blockIdx.y * 128;
    const int n0 = blockIdx.x * 128;

    // loader mapping
    const int lr = tid >> 1;
    const int khalf = (tid & 1) * 16;
    const __nv_bfloat16* sAh = Ah + (size_t)(m0 + lr) * 1024 + khalf;
    const __nv_bfloat16* sAl = Al + (size_t)(m0 + lr) * 1024 + khalf;
    const __nv_bfloat16* sBh = Bh + (size_t)(n0 + lr) * 1024 + khalf;
    const __nv_bfloat16* sBl = Bl + (size_t)(n0 + lr) * 1024 + khalf;
    const uint32_t drow = (uint32_t)lr * 80 + (uint32_t)khalf * 2;

    float acc[2][8][4];
#pragma unroll
    for (int mt = 0; mt < 2; mt++)
#pragma unroll
        for (int nt = 0; nt < 8; nt++)
#pragma unroll
            for (int q = 0; q < 4; q++) acc[mt][nt][q] = 0.f;

    // ldmatrix per-lane offsets (strides of 80B rows)
    const uint32_t aoff = (uint32_t)((wm * 32 + mlo * 8 + lrow) * 80 + mhi * 16);
    const uint32_t boff = (uint32_t)((wn * 64 + mhi * 8 + lrow) * 80 + mlo * 16);

#define G_ISSUE(stg, c) do {                                     \
        const uint32_t d_ = sb + (uint32_t)(stg) * GST + drow;   \
        const int kg_ = (c) * 32;                                \
        CP_ASYNC16(d_ + GA_H,      sAh + kg_);                   \
        CP_ASYNC16(d_ + GA_H + 16, sAh + kg_ + 8);               \
        CP_ASYNC16(d_ + GA_L,      sAl + kg_);                   \
        CP_ASYNC16(d_ + GA_L + 16, sAl + kg_ + 8);               \
        CP_ASYNC16(d_ + GB_H,      sBh + kg_);                   \
        CP_ASYNC16(d_ + GB_H + 16, sBh + kg_ + 8);               \
        CP_ASYNC16(d_ + GB_L,      sBl + kg_);                   \
        CP_ASYNC16(d_ + GB_L + 16, sBl + kg_ + 8);               \
        CP_COMMIT();                                             \
    } while (0)

    G_ISSUE(0, 0);

    for (int c = 0; c < 32; c++) {
        CP_WAIT(0);
        __syncthreads();
        if (c < 31) G_ISSUE((c + 1) & 1, c + 1);

        const uint32_t sS = sb + (uint32_t)(c & 1) * GST;
#pragma unroll
        for (int kk = 0; kk < 2; kk++) {
            const uint32_t kof = (uint32_t)kk * 32;

            uint32_t ah[2][4], al[2][4], bhf[8][2], blf[8][2];
            LDSM4(ah[0][0], ah[0][1], ah[0][2], ah[0][3], sS + GA_H + aoff + kof);
            LDSM4(ah[1][0], ah[1][1], ah[1][2], ah[1][3], sS + GA_H + aoff + 1280 + kof);
#pragma unroll
            for (int p = 0; p < 4; p++)
                LDSM4(bhf[2 * p][0], bhf[2 * p][1], bhf[2 * p + 1][0], bhf[2 * p + 1][1],
                      sS + GB_H + boff + (uint32_t)p * 1280 + kof);
#pragma unroll
            for (int mt = 0; mt < 2; mt++)
#pragma unroll
                for (int nt = 0; nt < 8; nt++)
                    mma_bf16(acc[mt][nt], ah[mt], bhf[nt]);

            LDSM4(al[0][0], al[0][1], al[0][2], al[0][3], sS + GA_L + aoff + kof);
            LDSM4(al[1][0], al[1][1], al[1][2], al[1][3], sS + GA_L + aoff + 1280 + kof);
#pragma unroll
            for (int mt = 0; mt < 2; mt++)
#pragma unroll
                for (int nt = 0; nt < 8; nt++)
                    mma_bf16(acc[mt][nt], al[mt], bhf[nt]);

#pragma unroll
            for (int p = 0; p < 4; p++)
                LDSM4(blf[2 * p][0], blf[2 * p][1], blf[2 * p + 1][0], blf[2 * p + 1][1],
                      sS + GB_L + boff + (uint32_t)p * 1280 + kof);
#pragma unroll
            for (int mt = 0; mt < 2; mt++)
#pragma unroll
                for (int nt = 0; nt < 8; nt++)
                    mma_bf16(acc[mt][nt], ah[mt], blf[nt]);
        }
    }

    // epilogue
    if (mode < 3) {
        __nv_bfloat16* OH = (mode == 0) ? g_qh : (mode == 1) ? g_kh : g_vh;
        __nv_bfloat16* OL = (mode == 0) ? g_ql : (mode == 1) ? g_kl : g_vl;
#pragma unroll
        for (int mt = 0; mt < 2; mt++) {
#pragma unroll
            for (int nt = 0; nt < 8; nt++) {
                const int row0 = m0 + wm * 32 + mt * 16 + g;
                const int col = n0 + wn * 64 + nt * 8 + t4 * 2;
                const int h = col >> 6, dh = col & 63;
                uint32_t hw, lw;
                {
                    const int bb = row0 >> 11, sq = row0 & 2047;
                    const size_t idx = (((size_t)(bb * H_ + h) * S_) + sq) * HD_ + dh;
                    split2(acc[mt][nt][0], acc[mt][nt][1], hw, lw);
                    *(uint32_t*)&OH[idx] = hw;
                    *(uint32_t*)&OL[idx] = lw;
                }
                {
                    const int row1 = row0 + 8;
                    const int bb = row1 >> 11, sq = row1 & 2047;
                    const size_t idx = (((size_t)(bb * H_ + h) * S_) + sq) * HD_ + dh;
                    split2(acc[mt][nt][2], acc[mt][nt][3], hw, lw);
                    *(uint32_t*)&OH[idx] = hw;
                    *(uint32_t*)&OL[idx] = lw;
                }
            }
        }
    } else {
#pragma unroll
        for (int mt = 0; mt < 2; mt++) {
#pragma unroll
            for (int nt = 0; nt < 8; nt++) {
                const int row0 = m0 + wm * 32 + mt * 16 + g;
                const int col = n0 + wn * 64 + nt * 8 + t4 * 2;
                *(float2*)&Cout[(size_t)row0 * 1024 + col] =
                    make_float2(acc[mt][nt][0], acc[mt][nt][1]);
                *(float2*)&Cout[(size_t)(row0 + 8) * 1024 + col] =
                    make_float2(acc[mt][nt][2], acc[mt][nt][3]);
            }
        }
    }
}

// ---------------------------------------------------------------------------
// Flash attention: HMMA, pre-split bf16, double-buffered cp.async K/V,
// ldmatrix(.trans) fragments. Bq=128, Bk=64, 8 warps, register softmax.
// Stage: Kh/Kl/Vh/Vl each [64 rows x 144B stride, 128B data] = 36864 B.
// ---------------------------------------------------------------------------
#define AT_KH 0
#define AT_KL 9216
#define AT_VH 18432
#define AT_VL 27648
#define AT_ST 36864
#define AT_SMEM (2 * AT_ST)   // 73728

__global__ __launch_bounds__(256, 2) void attn_k()
{
    const uint32_t sb = smem_u32(g_dynsm);

    const int tid = threadIdx.x;
    const int wid = tid >> 5;
    const int lid = tid & 31;
    const int g = lid >> 2;
    const int t4 = lid & 3;
    const int lrow = lid & 7;
    const int mlo = (lid >> 3) & 1;
    const int mhi = (lid >> 4) & 1;
    const int qt = 15 - (int)blockIdx.x;
    const int h = blockIdx.y;
    const int b = blockIdx.z;
    const int q0 = qt * 128;
    const size_t bho = (size_t)(b * H_ + h) * S_ * HD_;

    const int wrow = q0 + wid * 16;
    const int row0 = wrow + g;

    // ldmatrix per-lane offsets (144B stride)
    const uint32_t koff = (uint32_t)((mhi * 8 + lrow) * 144 + mlo * 16);
    const uint32_t voff = (uint32_t)((mlo * 8 + lrow) * 144 + mhi * 16);

    // loader mapping: row ldr (0..63), 16-elem column chunk
    const int ldr = tid >> 2;
    const int ldc = (tid & 3) * 16;
    const uint32_t ldst = (uint32_t)ldr * 144 + (uint32_t)ldc * 2;

#define ATT_ISSUE(stg, kvi) do {                                               \
        const size_t go_ = bho + (size_t)((kvi) * 64 + ldr) * 64 + ldc;        \
        const uint32_t d_ = sb + (uint32_t)(stg) * AT_ST + ldst;               \
        CP_ASYNC16(d_ + AT_KH,      g_kh + go_);                               \
        CP_ASYNC16(d_ + AT_KH + 16, g_kh + go_ + 8);                           \
        CP_ASYNC16(d_ + AT_KL,      g_kl + go_);                               \
        CP_ASYNC16(d_ + AT_KL + 16, g_kl + go_ + 8);                           \
        CP_ASYNC16(d_ + AT_VH,      g_vh + go_);                               \
        CP_ASYNC16(d_ + AT_VH + 16, g_vh + go_ + 8);                           \
        CP_ASYNC16(d_ + AT_VL,      g_vl + go_);                               \
        CP_ASYNC16(d_ + AT_VL + 16, g_vl + go_ + 8);                           \
        CP_COMMIT();                                                           \
    } while (0)

    // Q fragments from pre-split gmem
    uint32_t qh[4][4], ql[4][4];
    {
        const uint32_t* qhp = (const uint32_t*)(g_qh + bho);
        const uint32_t* qlp = (const uint32_t*)(g_ql + bho);
        const int ra = row0 * 32;
        const int rb = (row0 + 8) * 32;
#pragma unroll
        for (int ks = 0; ks < 4; ks++) {
            const int kw = ks * 8 + t4;
            qh[ks][0] = qhp[ra + kw];
            qh[ks][1] = qhp[rb + kw];
            qh[ks][2] = qhp[ra + kw + 4];
            qh[ks][3] = qhp[rb + kw + 4];
            ql[ks][0] = qlp[ra + kw];
            ql[ks][1] = qlp[rb + kw];
            ql[ks][2] = qlp[ra + kw + 4];
            ql[ks][3] = qlp[rb + kw + 4];
        }
    }

    float o[8][4];
#pragma unroll
    for (int nt = 0; nt < 8; nt++)
#pragma unroll
        for (int q = 0; q < 4; q++) o[nt][q] = 0.f;
    float mrow0 = -CUDART_INF_F, mrow1 = -CUDART_INF_F;
    float lrow0v = 0.f, lrow1v = 0.f;

    const int nkv = 2 * qt + 2;
    ATT_ISSUE(0, 0);

    for (int kv = 0; kv < nkv; kv++) {
        const int k0 = kv * 64;
        __syncthreads();                    // all warps done with other stage
        if (kv + 1 < nkv) {
            ATT_ISSUE((kv + 1) & 1, kv + 1);
            CP_WAIT(1);
        } else {
            CP_WAIT(0);
        }
        __syncthreads();                    // tile kv visible to all

        const uint32_t sbs = sb + (uint32_t)(kv & 1) * AT_ST;

        if (k0 <= wrow + 15) {
            // ---- S = Q K^T (3 passes) ----
            float s[8][4];
#pragma unroll
            for (int nt = 0; nt < 8; nt++)
#pragma unroll
                for (int q = 0; q < 4; q++) s[nt][q] = 0.f;

#pragma unroll
            for (int ks = 0; ks < 4; ks++) {
                uint32_t kbh[8][2], kbl[8][2];
#pragma unroll
                for (int p = 0; p < 4; p++)
                    LDSM4(kbh[2 * p][0], kbh[2 * p][1], kbh[2 * p + 1][0], kbh[2 * p + 1][1],
                          sbs + AT_KH + koff + (uint32_t)p * 2304 + (uint32_t)ks * 32);
#pragma unroll
                for (int nt = 0; nt < 8; nt++) mma_bf16(s[nt], qh[ks], kbh[nt]);
#pragma unroll
                for (int nt = 0; nt < 8; nt++) mma_bf16(s[nt], ql[ks], kbh[nt]);
#pragma unroll
                for (int p = 0; p < 4; p++)
                    LDSM4(kbl[2 * p][0], kbl[2 * p][1], kbl[2 * p + 1][0], kbl[2 * p + 1][1],
                          sbs + AT_KL + koff + (uint32_t)p * 2304 + (uint32_t)ks * 32);
#pragma unroll
                for (int nt = 0; nt < 8; nt++) mma_bf16(s[nt], qh[ks], kbl[nt]);
            }

            // ---- scale (1/8, exact) ----
#pragma unroll
            for (int nt = 0; nt < 8; nt++)
#pragma unroll
                for (int q = 0; q < 4; q++) s[nt][q] *= 0.125f;

            // ---- causal mask ----
            if (k0 + 63 > wrow) {
#pragma unroll
                for (int nt = 0; nt < 8; nt++) {
                    const int col0 = k0 + nt * 8 + 2 * t4;
                    if (col0 > row0)         s[nt][0] = -CUDART_INF_F;
                    if (col0 + 1 > row0)     s[nt][1] = -CUDART_INF_F;
                    if (col0 > row0 + 8)     s[nt][2] = -CUDART_INF_F;
                    if (col0 + 1 > row0 + 8) s[nt][3] = -CUDART_INF_F;
                }
            }

            // ---- online softmax ----
            float mx0 = -CUDART_INF_F, mx1 = -CUDART_INF_F;
#pragma unroll
            for (int nt = 0; nt < 8; nt++) {
                mx0 = fmaxf(mx0, fmaxf(s[nt][0], s[nt][1]));
                mx1 = fmaxf(mx1, fmaxf(s[nt][2], s[nt][3]));
            }
            mx0 = fmaxf(mx0, __shfl_xor_sync(0xffffffffu, mx0, 1));
            mx0 = fmaxf(mx0, __shfl_xor_sync(0xffffffffu, mx0, 2));
            mx1 = fmaxf(mx1, __shfl_xor_sync(0xffffffffu, mx1, 1));
            mx1 = fmaxf(mx1, __shfl_xor_sync(0xffffffffu, mx1, 2));

            const float nm0 = fmaxf(mrow0, mx0);
            const float nm1 = fmaxf(mrow1, mx1);
            const float c0 = __expf(mrow0 - nm0);
            const float c1 = __expf(mrow1 - nm1);
            float sum0 = 0.f, sum1 = 0.f;
#pragma unroll
            for (int nt = 0; nt < 8; nt++) {
                s[nt][0] = __expf(s[nt][0] - nm0);
                s[nt][1] = __expf(s[nt][1] - nm0);
                s[nt][2] = __expf(s[nt][2] - nm1);
                s[nt][3] = __expf(s[nt][3] - nm1);
                sum0 += s[nt][0] + s[nt][1];
                sum1 += s[nt][2] + s[nt][3];
            }
            sum0 += __shfl_xor_sync(0xffffffffu, sum0, 1);
            sum0 += __shfl_xor_sync(0xffffffffu, sum0, 2);
            sum1 += __shfl_xor_sync(0xffffffffu, sum1, 1);
            sum1 += __shfl_xor_sync(0xffffffffu, sum1, 2);
            lrow0v = lrow0v * c0 + sum0;
            lrow1v = lrow1v * c1 + sum1;
            mrow0 = nm0;
            mrow1 = nm1;
#pragma unroll
            for (int nt = 0; nt < 8; nt++) {
                o[nt][0] *= c0;
                o[nt][1] *= c0;
                o[nt][2] *= c1;
                o[nt][3] *= c1;
            }

            // ---- P -> bf16 split A-frags ----
            uint32_t pah[4][4], pal[4][4];
#pragma unroll
            for (int kk = 0; kk < 4; kk++) {
                split2(s[2 * kk][0], s[2 * kk][1], pah[kk][0], pal[kk][0]);
                split2(s[2 * kk][2], s[2 * kk][3], pah[kk][1], pal[kk][1]);
                split2(s[2 * kk + 1][0], s[2 * kk + 1][1], pah[kk][2], pal[kk][2]);
                split2(s[2 * kk + 1][2], s[2 * kk + 1][3], pah[kk][3], pal[kk][3]);
            }

            // ---- O += P V (3 passes), V^T frags via ldmatrix.trans ----
#pragma unroll
            for (int kk = 0; kk < 4; kk++) {
                uint32_t vbh[8][2], vbl[8][2];
#pragma unroll
                for (int p = 0; p < 4; p++)
                    LDSM4T(vbh[2 * p][0], vbh[2 * p][1], vbh[2 * p + 1][0], vbh[2 * p + 1][1],
                           sbs + AT_VH + voff + (uint32_t)kk * 2304 + (uint32_t)p * 32);
#pragma unroll
                for (int nt = 0; nt < 8; nt++) mma_bf16(o[nt], pah[kk], vbh[nt]);
#pragma unroll
                for (int nt = 0; nt < 8; nt++) mma_bf16(o[nt], pal[kk], vbh[nt]);
#pragma unroll
                for (int p = 0; p < 4; p++)
                    LDSM4T(vbl[2 * p][0], vbl[2 * p][1], vbl[2 * p + 1][0], vbl[2 * p + 1][1],
                           sbs + AT_VL + voff + (uint32_t)kk * 2304 + (uint32_t)p * 32);
#pragma unroll
                for (int nt = 0; nt < 8; nt++) mma_bf16(o[nt], pah[kk], vbl[nt]);
            }
        }
    }

    // ---- epilogue ----
    const float inv0 = 1.f / lrow0v;
    const float inv1 = 1.f / lrow1v;
    const size_t base0 = ((size_t)(b * S_ + row0)) * D_ + h * HD_;
    const size_t base1 = ((size_t)(b * S_ + row0 + 8)) * D_ + h * HD_;
#pragma unroll
    for (int nt = 0; nt < 8; nt++) {
        const int d = nt * 8 + 2 * t4;
        uint32_t hw, lw;
        split2(o[nt][0] * inv0, o[nt][1] * inv0, hw, lw);
        *(uint32_t*)&g_cth[base0 + d] = hw;
        *(uint32_t*)&g_ctl[base0 + d] = lw;
        split2(o[nt][2] * inv1, o[nt][3] * inv1, hw, lw);
        *(uint32_t*)&g_cth[base1 + d] = hw;
        *(uint32_t*)&g_ctl[base1 + d] = lw;
    }
}

// ---------------------------------------------------------------------------
extern "C" void kernel_launch(void* const* d_in, const int* in_sizes, int n_in,
                              void* d_out, int out_size)
{
    const float* q  = (const float*)d_in[0];
    const float* k  = (const float*)d_in[1];
    const float* v  = (const float*)d_in[2];
    const float* wq = (const float*)d_in[3];
    const float* wk = (const float*)d_in[4];
    const float* wv = (const float*)d_in[5];
    const float* wo = (const float*)d_in[6];
    float* out = (float*)d_out;

    asplit_k<<<dim3(8192, 3), 256>>>(q, k, v);
    wsplit_k<<<dim3(32, 32, 4), dim3(32, 8)>>>(wq, wk, wv, wo);

    cudaFuncSetAttribute(gemm_mma, cudaFuncAttributeMaxDynamicSharedMemorySize, G_SMEM);
    cudaFuncSetAttribute(attn_k, cudaFuncAttributeMaxDynamicSharedMemorySize, AT_SMEM);

    gemm_mma<<<dim3(8, 64, 3), 256, G_SMEM>>>(nullptr, 0);   // QKV fused

    attn_k<<<dim3(16, 16, 4), 256, AT_SMEM>>>();

    gemm_mma<<<dim3(8, 64, 1), 256, G_SMEM>>>(out, 3);       // O projection
}

// round 11
// speedup vs baseline: 4.4856x; 1.4048x over previous
#include <cuda_runtime.h>
#include <cuda_fp16.h>
#include <math_constants.h>
#include <cstdint>

#define B_  4
#define S_  2048
#define D_  1024
#define H_  16
#define HD_ 64
#define NEL (8ull * 1024 * 1024)   // 8192*1024 elements per matrix

// Scratch (device globals). fp16 2-pass split: A-side operands hi/lo, B-side hi only.
__device__ __half g_inh[3 * NEL], g_inl[3 * NEL];   // q,k,v inputs [m][k] (A of QKV gemms)
__device__ __half g_qh[NEL], g_ql[NEL];             // xq [b,h,s,dh] (A of S-gemm)
__device__ __half g_kh[NEL];                        // xk (B of S-gemm, hi only)
__device__ __half g_vh[NEL];                        // xv (B of PV-gemm, hi only)
__device__ __half g_cth[NEL], g_ctl[NEL];           // ctx [b,s,d] (A of O-gemm)
__device__ __half g_wth[4 * NEL / 8];               // W^T [n][k] x4 (B, hi only)

__device__ __forceinline__ uint32_t smem_u32(const void* p) {
    uint32_t a;
    asm("{ .reg .u64 t; cvta.to.shared.u64 t, %1; cvt.u32.u64 %0, t; }" : "=r"(a) : "l"(p));
    return a;
}

#define LDSM4(r0, r1, r2, r3, a) \
    asm volatile("ldmatrix.sync.aligned.m8n8.x4.shared.b16 {%0,%1,%2,%3}, [%4];" \
                 : "=r"(r0), "=r"(r1), "=r"(r2), "=r"(r3) : "r"(a))
#define LDSM4T(r0, r1, r2, r3, a) \
    asm volatile("ldmatrix.sync.aligned.m8n8.x4.trans.shared.b16 {%0,%1,%2,%3}, [%4];" \
                 : "=r"(r0), "=r"(r1), "=r"(r2), "=r"(r3) : "r"(a))
#define CP_ASYNC16(dst, src) \
    asm volatile("cp.async.cg.shared.global [%0], [%1], 16;" :: "r"(dst), "l"(src) : "memory")
#define CP_COMMIT() asm volatile("cp.async.commit_group;" ::: "memory")
#define CP_WAIT(n)  asm volatile("cp.async.wait_group %0;" :: "n"(n) : "memory")

__device__ __forceinline__ void mma_f16(float* d, const uint32_t* a, const uint32_t* b) {
    asm volatile(
        "mma.sync.aligned.m16n8k16.row.col.f32.f16.f16.f32 "
        "{%0,%1,%2,%3}, {%4,%5,%6,%7}, {%8,%9}, {%0,%1,%2,%3};"
        : "+f"(d[0]), "+f"(d[1]), "+f"(d[2]), "+f"(d[3])
        : "r"(a[0]), "r"(a[1]), "r"(a[2]), "r"(a[3]), "r"(b[0]), "r"(b[1]));
}

__device__ __forceinline__ void split2h(float x, float y, uint32_t& hi, uint32_t& lo) {
    __half2 h = __floats2half2_rn(x, y);
    float rx = x - __half2float(__low2half(h));
    float ry = y - __half2float(__high2half(h));
    __half2 l = __floats2half2_rn(rx, ry);
    hi = reinterpret_cast<uint32_t&>(h);
    lo = reinterpret_cast<uint32_t&>(l);
}

__device__ __forceinline__ uint32_t pack2h(float x, float y) {
    __half2 h = __floats2half2_rn(x, y);
    return reinterpret_cast<uint32_t&>(h);
}

// ---------------------------------------------------------------------------
// Activation split: q/k/v fp32 -> fp16 hi/lo
// ---------------------------------------------------------------------------
__global__ __launch_bounds__(256) void asplit_k(const float* __restrict__ q,
                                                const float* __restrict__ k,
                                                const float* __restrict__ v) {
    const int z = blockIdx.y;
    const float* src = (z == 0) ? q : (z == 1) ? k : v;
    const size_t i = ((size_t)blockIdx.x * 256 + threadIdx.x) * 4;
    float4 f = *(const float4*)(src + i);
    uint32_t h0, l0, h1, l1;
    split2h(f.x, f.y, h0, l0);
    split2h(f.z, f.w, h1, l1);
    *(uint2*)&g_inh[z * NEL + i] = make_uint2(h0, h1);
    *(uint2*)&g_inl[z * NEL + i] = make_uint2(l0, l1);
}

// ---------------------------------------------------------------------------
// Weight transpose + fp16 (hi only): Wt[n][k] = W[k][n]
// ---------------------------------------------------------------------------
__global__ __launch_bounds__(256) void wsplit_k(const float* __restrict__ w0,
                                                const float* __restrict__ w1,
                                                const float* __restrict__ w2,
                                                const float* __restrict__ w3) {
    __shared__ float t[32][33];
    const int widx = blockIdx.z;
    const float* W = (widx == 0) ? w0 : (widx == 1) ? w1 : (widx == 2) ? w2 : w3;
    const int n0 = blockIdx.x * 32, k0 = blockIdx.y * 32;
    const int tx = threadIdx.x, ty = threadIdx.y;
#pragma unroll
    for (int i = 0; i < 32; i += 8)
        t[ty + i][tx] = W[(size_t)(k0 + ty + i) * 1024 + n0 + tx];
    __syncthreads();
    __half* Th = g_wth + (size_t)widx * 1024 * 1024;
#pragma unroll
    for (int i = 0; i < 32; i += 8) {
        const int n = n0 + ty + i, k = k0 + tx;
        Th[(size_t)n * 1024 + k] = __float2half(t[tx][ty + i]);
    }
}

// ---------------------------------------------------------------------------
// fp16 2-pass HMMA GEMM: acc = Ah*Bh + Al*Bh. cp.async 3-stage, ldmatrix.
// BM=128, BN=128, BK=32, 256 threads, 8 warps each 32x64, 2 CTAs/SM.
// ---------------------------------------------------------------------------
#define GA_H 0
#define GA_L 10240
#define GB_H 20480
#define GST  30720
#define G_SMEM (3 * GST)   // 92160

extern __shared__ unsigned char g_dynsm[];

__global__ __launch_bounds__(256, 2)
void gemm_mma(float* __restrict__ Cout, int mode_base)
{
    const uint32_t sb = smem_u32(g_dynsm);

    const int tid = threadIdx.x;
    const int wid = tid >> 5;
    const int lid = tid & 31;
    const int g = lid >> 2;
    const int t4 = lid & 3;
    const int wm = wid & 3;
    const int wn = wid >> 2;
    const int lrow = lid & 7;
    const int mlo = (lid >> 3) & 1;
    const int mhi = (lid >> 4) & 1;

    const int mode = (mode_base == 3) ? 3 : (int)blockIdx.z;
    const __half* Ah = (mode == 3) ? g_cth : g_inh + (size_t)mode * NEL;
    const __half* Al = (mode == 3) ? g_ctl : g_inl + (size_t)mode * NEL;
    const __half* Bh = g_wth + (size_t)mode * 1024 * 1024;

    const int m0 = blockIdx.y * 128;
    const int n0 = blockIdx.x * 128;

    // loader mapping
    const int lr = tid >> 1;
    const int khalf = (tid & 1) * 16;
    const __half* sAh = Ah + (size_t)(m0 + lr) * 1024 + khalf;
    const __half* sAl = Al + (size_t)(m0 + lr) * 1024 + khalf;
    const __half* sBh = Bh + (size_t)(n0 + lr) * 1024 + khalf;
    const uint32_t drow = (uint32_t)lr * 80 + (uint32_t)khalf * 2;

    float acc[2][8][4];
#pragma unroll
    for (int mt = 0; mt < 2; mt++)
#pragma unroll
        for (int nt = 0; nt < 8; nt++)
#pragma unroll
            for (int q = 0; q < 4; q++) acc[mt][nt][q] = 0.f;

    // ldmatrix per-lane offsets (80B rows)
    const uint32_t aoff = (uint32_t)((wm * 32 + mlo * 8 + lrow) * 80 + mhi * 16);
    const uint32_t boff = (uint32_t)((wn * 64 + mhi * 8 + lrow) * 80 + mlo * 16);

#define G_ISSUE(stg, c) do {                                     \
        const uint32_t d_ = sb + (uint32_t)(stg) * GST + drow;   \
        const int kg_ = (c) * 32;                                \
        CP_ASYNC16(d_ + GA_H,      sAh + kg_);                   \
        CP_ASYNC16(d_ + GA_H + 16, sAh + kg_ + 8);               \
        CP_ASYNC16(d_ + GA_L,      sAl + kg_);                   \
        CP_ASYNC16(d_ + GA_L + 16, sAl + kg_ + 8);               \
        CP_ASYNC16(d_ + GB_H,      sBh + kg_);                   \
        CP_ASYNC16(d_ + GB_H + 16, sBh + kg_ + 8);               \
        CP_COMMIT();                                             \
    } while (0)

    G_ISSUE(0, 0);
    G_ISSUE(1, 1);

    for (int c = 0; c < 32; c++) {
        if (c < 31) { CP_WAIT(1); } else { CP_WAIT(0); }
        __syncthreads();                 // chunk c visible; stage (c+2)%3 free
        if (c < 30) G_ISSUE((c + 2) % 3, c + 2);

        const uint32_t sS = sb + (uint32_t)(c % 3) * GST;
#pragma unroll
        for (int kk = 0; kk < 2; kk++) {
            const uint32_t kof = (uint32_t)kk * 32;

            uint32_t ah[2][4], al[2][4], bhf[8][2];
            LDSM4(ah[0][0], ah[0][1], ah[0][2], ah[0][3], sS + GA_H + aoff + kof);
            LDSM4(ah[1][0], ah[1][1], ah[1][2], ah[1][3], sS + GA_H + aoff + 1280 + kof);
#pragma unroll
            for (int p = 0; p < 4; p++)
                LDSM4(bhf[2 * p][0], bhf[2 * p][1], bhf[2 * p + 1][0], bhf[2 * p + 1][1],
                      sS + GB_H + boff + (uint32_t)p * 1280 + kof);
#pragma unroll
            for (int mt = 0; mt < 2; mt++)
#pragma unroll
                for (int nt = 0; nt < 8; nt++)
                    mma_f16(acc[mt][nt], ah[mt], bhf[nt]);

            LDSM4(al[0][0], al[0][1], al[0][2], al[0][3], sS + GA_L + aoff + kof);
            LDSM4(al[1][0], al[1][1], al[1][2], al[1][3], sS + GA_L + aoff + 1280 + kof);
#pragma unroll
            for (int mt = 0; mt < 2; mt++)
#pragma unroll
                for (int nt = 0; nt < 8; nt++)
                    mma_f16(acc[mt][nt], al[mt], bhf[nt]);
        }
    }

    // epilogue
    if (mode < 3) {
#pragma unroll
        for (int mt = 0; mt < 2; mt++) {
#pragma unroll
            for (int nt = 0; nt < 8; nt++) {
                const int row0 = m0 + wm * 32 + mt * 16 + g;
                const int col = n0 + wn * 64 + nt * 8 + t4 * 2;
                const int h = col >> 6, dh = col & 63;
#pragma unroll
                for (int half = 0; half < 2; half++) {
                    const int row = row0 + half * 8;
                    const int bb = row >> 11, sq = row & 2047;
                    const size_t idx = (((size_t)(bb * H_ + h) * S_) + sq) * HD_ + dh;
                    const float v0 = acc[mt][nt][2 * half];
                    const float v1 = acc[mt][nt][2 * half + 1];
                    if (mode == 0) {
                        uint32_t hw, lw;
                        split2h(v0, v1, hw, lw);
                        *(uint32_t*)&g_qh[idx] = hw;
                        *(uint32_t*)&g_ql[idx] = lw;
                    } else if (mode == 1) {
                        *(uint32_t*)&g_kh[idx] = pack2h(v0, v1);
                    } else {
                        *(uint32_t*)&g_vh[idx] = pack2h(v0, v1);
                    }
                }
            }
        }
    } else {
#pragma unroll
        for (int mt = 0; mt < 2; mt++) {
#pragma unroll
            for (int nt = 0; nt < 8; nt++) {
                const int row0 = m0 + wm * 32 + mt * 16 + g;
                const int col = n0 + wn * 64 + nt * 8 + t4 * 2;
                *(float2*)&Cout[(size_t)row0 * 1024 + col] =
                    make_float2(acc[mt][nt][0], acc[mt][nt][1]);
                *(float2*)&Cout[(size_t)(row0 + 8) * 1024 + col] =
                    make_float2(acc[mt][nt][2], acc[mt][nt][3]);
            }
        }
    }
}

// ---------------------------------------------------------------------------
// Flash attention: fp16 2-pass HMMA, double-buffered cp.async K/V (hi only),
// ldmatrix(.trans). Bq=128, Bk=64, 8 warps, register softmax.
// Stage: Kh/Vh each [64 rows x 144B stride] = 18432 B; 2 stages.
// ---------------------------------------------------------------------------
#define AT_KH 0
#define AT_VH 9216
#define AT_ST 18432
#define AT_SMEM (2 * AT_ST)   // 36864

__global__ __launch_bounds__(256, 2) void attn_k()
{
    const uint32_t sb = smem_u32(g_dynsm);

    const int tid = threadIdx.x;
    const int wid = tid >> 5;
    const int lid = tid & 31;
    const int g = lid >> 2;
    const int t4 = lid & 3;
    const int lrow = lid & 7;
    const int mlo = (lid >> 3) & 1;
    const int mhi = (lid >> 4) & 1;
    const int qt = 15 - (int)blockIdx.x;
    const int h = blockIdx.y;
    const int b = blockIdx.z;
    const int q0 = qt * 128;
    const size_t bho = (size_t)(b * H_ + h) * S_ * HD_;

    const int wrow = q0 + wid * 16;
    const int row0 = wrow + g;

    // ldmatrix per-lane offsets (144B stride)
    const uint32_t koff = (uint32_t)((mhi * 8 + lrow) * 144 + mlo * 16);
    const uint32_t voff = (uint32_t)((mlo * 8 + lrow) * 144 + mhi * 16);

    // loader mapping
    const int ldr = tid >> 2;
    const int ldc = (tid & 3) * 16;
    const uint32_t ldst = (uint32_t)ldr * 144 + (uint32_t)ldc * 2;

#define ATT_ISSUE(stg, kvi) do {                                               \
        const size_t go_ = bho + (size_t)((kvi) * 64 + ldr) * 64 + ldc;        \
        const uint32_t d_ = sb + (uint32_t)(stg) * AT_ST + ldst;               \
        CP_ASYNC16(d_ + AT_KH,      g_kh + go_);                               \
        CP_ASYNC16(d_ + AT_KH + 16, g_kh + go_ + 8);                           \
        CP_ASYNC16(d_ + AT_VH,      g_vh + go_);                               \
        CP_ASYNC16(d_ + AT_VH + 16, g_vh + go_ + 8);                           \
        CP_COMMIT();                                                           \
    } while (0)

    // Q fragments from pre-split gmem
    uint32_t qh[4][4], ql[4][4];
    {
        const uint32_t* qhp = (const uint32_t*)(g_qh + bho);
        const uint32_t* qlp = (const uint32_t*)(g_ql + bho);
        const int ra = row0 * 32;
        const int rb = (row0 + 8) * 32;
#pragma unroll
        for (int ks = 0; ks < 4; ks++) {
            const int kw = ks * 8 + t4;
            qh[ks][0] = qhp[ra + kw];
            qh[ks][1] = qhp[rb + kw];
            qh[ks][2] = qhp[ra + kw + 4];
            qh[ks][3] = qhp[rb + kw + 4];
            ql[ks][0] = qlp[ra + kw];
            ql[ks][1] = qlp[rb + kw];
            ql[ks][2] = qlp[ra + kw + 4];
            ql[ks][3] = qlp[rb + kw + 4];
        }
    }

    float o[8][4];
#pragma unroll
    for (int nt = 0; nt < 8; nt++)
#pragma unroll
        for (int q = 0; q < 4; q++) o[nt][q] = 0.f;
    float mrow0 = -CUDART_INF_F, mrow1 = -CUDART_INF_F;
    float lrow0v = 0.f, lrow1v = 0.f;

    const int nkv = 2 * qt + 2;
    ATT_ISSUE(0, 0);

    for (int kv = 0; kv < nkv; kv++) {
        const int k0 = kv * 64;
        __syncthreads();                    // all warps done with other stage
        if (kv + 1 < nkv) {
            ATT_ISSUE((kv + 1) & 1, kv + 1);
            CP_WAIT(1);
        } else {
            CP_WAIT(0);
        }
        __syncthreads();                    // tile kv visible to all

        const uint32_t sbs = sb + (uint32_t)(kv & 1) * AT_ST;

        if (k0 <= wrow + 15) {
            // ---- S = Q K^T (2 passes: Qh*Kh + Ql*Kh) ----
            float s[8][4];
#pragma unroll
            for (int nt = 0; nt < 8; nt++)
#pragma unroll
                for (int q = 0; q < 4; q++) s[nt][q] = 0.f;

#pragma unroll
            for (int ks = 0; ks < 4; ks++) {
                uint32_t kbh[8][2];
#pragma unroll
                for (int p = 0; p < 4; p++)
                    LDSM4(kbh[2 * p][0], kbh[2 * p][1], kbh[2 * p + 1][0], kbh[2 * p + 1][1],
                          sbs + AT_KH + koff + (uint32_t)p * 2304 + (uint32_t)ks * 32);
#pragma unroll
                for (int nt = 0; nt < 8; nt++) mma_f16(s[nt], qh[ks], kbh[nt]);
#pragma unroll
                for (int nt = 0; nt < 8; nt++) mma_f16(s[nt], ql[ks], kbh[nt]);
            }

            // ---- scale (1/8, exact) ----
#pragma unroll
            for (int nt = 0; nt < 8; nt++)
#pragma unroll
                for (int q = 0; q < 4; q++) s[nt][q] *= 0.125f;

            // ---- causal mask ----
            if (k0 + 63 > wrow) {
#pragma unroll
                for (int nt = 0; nt < 8; nt++) {
                    const int col0 = k0 + nt * 8 + 2 * t4;
                    if (col0 > row0)         s[nt][0] = -CUDART_INF_F;
                    if (col0 + 1 > row0)     s[nt][1] = -CUDART_INF_F;
                    if (col0 > row0 + 8)     s[nt][2] = -CUDART_INF_F;
                    if (col0 + 1 > row0 + 8) s[nt][3] = -CUDART_INF_F;
                }
            }

            // ---- online softmax ----
            float mx0 = -CUDART_INF_F, mx1 = -CUDART_INF_F;
#pragma unroll
            for (int nt = 0; nt < 8; nt++) {
                mx0 = fmaxf(mx0, fmaxf(s[nt][0], s[nt][1]));
                mx1 = fmaxf(mx1, fmaxf(s[nt][2], s[nt][3]));
            }
            mx0 = fmaxf(mx0, __shfl_xor_sync(0xffffffffu, mx0, 1));
            mx0 = fmaxf(mx0, __shfl_xor_sync(0xffffffffu, mx0, 2));
            mx1 = fmaxf(mx1, __shfl_xor_sync(0xffffffffu, mx1, 1));
            mx1 = fmaxf(mx1, __shfl_xor_sync(0xffffffffu, mx1, 2));

            const float nm0 = fmaxf(mrow0, mx0);
            const float nm1 = fmaxf(mrow1, mx1);
            const float c0 = __expf(mrow0 - nm0);
            const float c1 = __expf(mrow1 - nm1);
            float sum0 = 0.f, sum1 = 0.f;
#pragma unroll
            for (int nt = 0; nt < 8; nt++) {
                s[nt][0] = __expf(s[nt][0] - nm0);
                s[nt][1] = __expf(s[nt][1] - nm0);
                s[nt][2] = __expf(s[nt][2] - nm1);
                s[nt][3] = __expf(s[nt][3] - nm1);
                sum0 += s[nt][0] + s[nt][1];
                sum1 += s[nt][2] + s[nt][3];
            }
            sum0 += __shfl_xor_sync(0xffffffffu, sum0, 1);
            sum0 += __shfl_xor_sync(0xffffffffu, sum0, 2);
            sum1 += __shfl_xor_sync(0xffffffffu, sum1, 1);
            sum1 += __shfl_xor_sync(0xffffffffu, sum1, 2);
            lrow0v = lrow0v * c0 + sum0;
            lrow1v = lrow1v * c1 + sum1;
            mrow0 = nm0;
            mrow1 = nm1;
#pragma unroll
            for (int nt = 0; nt < 8; nt++) {
                o[nt][0] *= c0;
                o[nt][1] *= c0;
                o[nt][2] *= c1;
                o[nt][3] *= c1;
            }

            // ---- P -> fp16 split A-frags ----
            uint32_t pah[4][4], pal[4][4];
#pragma unroll
            for (int kk = 0; kk < 4; kk++) {
                split2h(s[2 * kk][0], s[2 * kk][1], pah[kk][0], pal[kk][0]);
                split2h(s[2 * kk][2], s[2 * kk][3], pah[kk][1], pal[kk][1]);
                split2h(s[2 * kk + 1][0], s[2 * kk + 1][1], pah[kk][2], pal[kk][2]);
                split2h(s[2 * kk + 1][2], s[2 * kk + 1][3], pah[kk][3], pal[kk][3]);
            }

            // ---- O += P V (2 passes: Ph*Vh + Pl*Vh), V^T via ldmatrix.trans ----
#pragma unroll
            for (int kk = 0; kk < 4; kk++) {
                uint32_t vbh[8][2];
#pragma unroll
                for (int p = 0; p < 4; p++)
                    LDSM4T(vbh[2 * p][0], vbh[2 * p][1], vbh[2 * p + 1][0], vbh[2 * p + 1][1],
                           sbs + AT_VH + voff + (uint32_t)kk * 2304 + (uint32_t)p * 32);
#pragma unroll
                for (int nt = 0; nt < 8; nt++) mma_f16(o[nt], pah[kk], vbh[nt]);
#pragma unroll
                for (int nt = 0; nt < 8; nt++) mma_f16(o[nt], pal[kk], vbh[nt]);
            }
        }
    }

    // ---- epilogue: divide by l, split, write ctx hi/lo ----
    const float inv0 = 1.f / lrow0v;
    const float inv1 = 1.f / lrow1v;
    const size_t base0 = ((size_t)(b * S_ + row0)) * D_ + h * HD_;
    const size_t base1 = ((size_t)(b * S_ + row0 + 8)) * D_ + h * HD_;
#pragma unroll
    for (int nt = 0; nt < 8; nt++) {
        const int d = nt * 8 + 2 * t4;
        uint32_t hw, lw;
        split2h(o[nt][0] * inv0, o[nt][1] * inv0, hw, lw);
        *(uint32_t*)&g_cth[base0 + d] = hw;
        *(uint32_t*)&g_ctl[base0 + d] = lw;
        split2h(o[nt][2] * inv1, o[nt][3] * inv1, hw, lw);
        *(uint32_t*)&g_cth[base1 + d] = hw;
        *(uint32_t*)&g_ctl[base1 + d] = lw;
    }
}

// ---------------------------------------------------------------------------
extern "C" void kernel_launch(void* const* d_in, const int* in_sizes, int n_in,
                              void* d_out, int out_size)
{
    const float* q  = (const float*)d_in[0];
    const float* k  = (const float*)d_in[1];
    const float* v  = (const float*)d_in[2];
    const float* wq = (const float*)d_in[3];
    const float* wk = (const float*)d_in[4];
    const float* wv = (const float*)d_in[5];
    const float* wo = (const float*)d_in[6];
    float* out = (float*)d_out;

    asplit_k<<<dim3(8192, 3), 256>>>(q, k, v);
    wsplit_k<<<dim3(32, 32, 4), dim3(32, 8)>>>(wq, wk, wv, wo);

    cudaFuncSetAttribute(gemm_mma, cudaFuncAttributeMaxDynamicSharedMemorySize, G_SMEM);
    cudaFuncSetAttribute(attn_k, cudaFuncAttributeMaxDynamicSharedMemorySize, AT_SMEM);

    gemm_mma<<<dim3(8, 64, 3), 256, G_SMEM>>>(nullptr, 0);   // QKV fused

    attn_k<<<dim3(16, 16, 4), 256, AT_SMEM>>>();

    gemm_mma<<<dim3(8, 64, 1), 256, G_SMEM>>>(out, 3);       // O projection
}

// round 14
// speedup vs baseline: 5.1681x; 1.1522x over previous
#include <cuda_runtime.h>
#include <cuda_fp16.h>
#include <math_constants.h>
#include <cstdint>

#define B_  4
#define S_  2048
#define D_  1024
#define H_  16
#define HD_ 64
#define NEL (8ull * 1024 * 1024)   // 8192*1024 elements per matrix

// Scratch (device globals). fp16 split: A-side hi/lo where precision matters,
// B-side hi only. K/V projections are 1-pass (outputs stored hi-only anyway).
__device__ __half g_inh[3 * NEL], g_inl[3 * NEL];   // q,k,v inputs [m][k]
__device__ __half g_qh[NEL], g_ql[NEL];             // xq [b,h,s,dh]
__device__ __half g_kh[NEL];                        // xk (hi only)
__device__ __half g_vh[NEL];                        // xv (hi only)
__device__ __half g_cth[NEL], g_ctl[NEL];           // ctx [b,s,d]
__device__ __half g_wth[4 * NEL / 8];               // W^T [n][k] x4 (hi only)

__device__ __forceinline__ uint32_t smem_u32(const void* p) {
    uint32_t a;
    asm("{ .reg .u64 t; cvta.to.shared.u64 t, %1; cvt.u32.u64 %0, t; }" : "=r"(a) : "l"(p));
    return a;
}

#define LDSM4(r0, r1, r2, r3, a) \
    asm volatile("ldmatrix.sync.aligned.m8n8.x4.shared.b16 {%0,%1,%2,%3}, [%4];" \
                 : "=r"(r0), "=r"(r1), "=r"(r2), "=r"(r3) : "r"(a))
#define LDSM4T(r0, r1, r2, r3, a) \
    asm volatile("ldmatrix.sync.aligned.m8n8.x4.trans.shared.b16 {%0,%1,%2,%3}, [%4];" \
                 : "=r"(r0), "=r"(r1), "=r"(r2), "=r"(r3) : "r"(a))
#define CP_ASYNC16(dst, src) \
    asm volatile("cp.async.cg.shared.global [%0], [%1], 16;" :: "r"(dst), "l"(src) : "memory")
#define CP_COMMIT() asm volatile("cp.async.commit_group;" ::: "memory")
#define CP_WAIT(n)  asm volatile("cp.async.wait_group %0;" :: "n"(n) : "memory")

__device__ __forceinline__ void mma_f16(float* d, const uint32_t* a, const uint32_t* b) {
    asm volatile(
        "mma.sync.aligned.m16n8k16.row.col.f32.f16.f16.f32 "
        "{%0,%1,%2,%3}, {%4,%5,%6,%7}, {%8,%9}, {%0,%1,%2,%3};"
        : "+f"(d[0]), "+f"(d[1]), "+f"(d[2]), "+f"(d[3])
        : "r"(a[0]), "r"(a[1]), "r"(a[2]), "r"(a[3]), "r"(b[0]), "r"(b[1]));
}

__device__ __forceinline__ void split2h(float x, float y, uint32_t& hi, uint32_t& lo) {
    __half2 h = __floats2half2_rn(x, y);
    float rx = x - __half2float(__low2half(h));
    float ry = y - __half2float(__high2half(h));
    __half2 l = __floats2half2_rn(rx, ry);
    hi = reinterpret_cast<uint32_t&>(h);
    lo = reinterpret_cast<uint32_t&>(l);
}

__device__ __forceinline__ uint32_t pack2h(float x, float y) {
    __half2 h = __floats2half2_rn(x, y);
    return reinterpret_cast<uint32_t&>(h);
}

// ---------------------------------------------------------------------------
// Activation split: q/k/v fp32 -> fp16 hi (+lo for q only; k/v proj is 1-pass)
// ---------------------------------------------------------------------------
__global__ __launch_bounds__(256) void asplit_k(const float* __restrict__ q,
                                                const float* __restrict__ k,
                                                const float* __restrict__ v) {
    const int z = blockIdx.y;
    const float* src = (z == 0) ? q : (z == 1) ? k : v;
    const size_t i = ((size_t)blockIdx.x * 256 + threadIdx.x) * 4;
    float4 f = *(const float4*)(src + i);
    uint32_t h0, l0, h1, l1;
    split2h(f.x, f.y, h0, l0);
    split2h(f.z, f.w, h1, l1);
    *(uint2*)&g_inh[z * NEL + i] = make_uint2(h0, h1);
    if (z == 0)
        *(uint2*)&g_inl[z * NEL + i] = make_uint2(l0, l1);
}

// ---------------------------------------------------------------------------
// Weight transpose + fp16 (hi only): Wt[n][k] = W[k][n]
// ---------------------------------------------------------------------------
__global__ __launch_bounds__(256) void wsplit_k(const float* __restrict__ w0,
                                                const float* __restrict__ w1,
                                                const float* __restrict__ w2,
                                                const float* __restrict__ w3) {
    __shared__ float t[32][33];
    const int widx = blockIdx.z;
    const float* W = (widx == 0) ? w0 : (widx == 1) ? w1 : (widx == 2) ? w2 : w3;
    const int n0 = blockIdx.x * 32, k0 = blockIdx.y * 32;
    const int tx = threadIdx.x, ty = threadIdx.y;
#pragma unroll
    for (int i = 0; i < 32; i += 8)
        t[ty + i][tx] = W[(size_t)(k0 + ty + i) * 1024 + n0 + tx];
    __syncthreads();
    __half* Th = g_wth + (size_t)widx * 1024 * 1024;
#pragma unroll
    for (int i = 0; i < 32; i += 8) {
        const int n = n0 + ty + i, k = k0 + tx;
        Th[(size_t)n * 1024 + k] = __float2half(t[tx][ty + i]);
    }
}

// ---------------------------------------------------------------------------
// fp16 HMMA GEMM. Q/O projections: 2-pass (Ah*Bh + Al*Bh). K/V: 1-pass.
// cp.async 3-stage, ldmatrix. BM=128, BN=128, BK=32, 256 thr, 2 CTAs/SM.
// ---------------------------------------------------------------------------
#define GA_H 0
#define GA_L 10240
#define GB_H 20480
#define GST  30720
#define G_SMEM (3 * GST)   // 92160

extern __shared__ unsigned char g_dynsm[];

__global__ __launch_bounds__(256, 2)
void gemm_mma(float* __restrict__ Cout, int mode_base)
{
    const uint32_t sb = smem_u32(g_dynsm);

    const int tid = threadIdx.x;
    const int wid = tid >> 5;
    const int lid = tid & 31;
    const int g = lid >> 2;
    const int t4 = lid & 3;
    const int wm = wid & 3;
    const int wn = wid >> 2;
    const int lrow = lid & 7;
    const int mlo = (lid >> 3) & 1;
    const int mhi = (lid >> 4) & 1;

    const int mode = (mode_base == 3) ? 3 : (int)blockIdx.z;
    const bool two_pass = (mode == 0 || mode == 3);
    const __half* Ah = (mode == 3) ? g_cth : g_inh + (size_t)mode * NEL;
    const __half* Al = (mode == 3) ? g_ctl : g_inl + (size_t)mode * NEL;
    const __half* Bh = g_wth + (size_t)mode * 1024 * 1024;

    const int m0 = blockIdx.y * 128;
    const int n0 = blockIdx.x * 128;

    // loader mapping
    const int lr = tid >> 1;
    const int khalf = (tid & 1) * 16;
    const __half* sAh = Ah + (size_t)(m0 + lr) * 1024 + khalf;
    const __half* sAl = Al + (size_t)(m0 + lr) * 1024 + khalf;
    const __half* sBh = Bh + (size_t)(n0 + lr) * 1024 + khalf;
    const uint32_t drow = (uint32_t)lr * 80 + (uint32_t)khalf * 2;

    float acc[2][8][4];
#pragma unroll
    for (int mt = 0; mt < 2; mt++)
#pragma unroll
        for (int nt = 0; nt < 8; nt++)
#pragma unroll
            for (int q = 0; q < 4; q++) acc[mt][nt][q] = 0.f;

    // ldmatrix per-lane offsets (80B rows)
    const uint32_t aoff = (uint32_t)((wm * 32 + mlo * 8 + lrow) * 80 + mhi * 16);
    const uint32_t boff = (uint32_t)((wn * 64 + mhi * 8 + lrow) * 80 + mlo * 16);

#define G_ISSUE(stg, c) do {                                     \
        const uint32_t d_ = sb + (uint32_t)(stg) * GST + drow;   \
        const int kg_ = (c) * 32;                                \
        CP_ASYNC16(d_ + GA_H,      sAh + kg_);                   \
        CP_ASYNC16(d_ + GA_H + 16, sAh + kg_ + 8);               \
        if (two_pass) {                                          \
            CP_ASYNC16(d_ + GA_L,      sAl + kg_);               \
            CP_ASYNC16(d_ + GA_L + 16, sAl + kg_ + 8);           \
        }                                                        \
        CP_ASYNC16(d_ + GB_H,      sBh + kg_);                   \
        CP_ASYNC16(d_ + GB_H + 16, sBh + kg_ + 8);               \
        CP_COMMIT();                                             \
    } while (0)

    G_ISSUE(0, 0);
    G_ISSUE(1, 1);

    for (int c = 0; c < 32; c++) {
        if (c < 31) { CP_WAIT(1); } else { CP_WAIT(0); }
        __syncthreads();                 // chunk c visible; stage (c+2)%3 free
        if (c < 30) G_ISSUE((c + 2) % 3, c + 2);

        const uint32_t sS = sb + (uint32_t)(c % 3) * GST;
#pragma unroll
        for (int kk = 0; kk < 2; kk++) {
            const uint32_t kof = (uint32_t)kk * 32;

            uint32_t ah[2][4], al[2][4], bhf[8][2];
            LDSM4(ah[0][0], ah[0][1], ah[0][2], ah[0][3], sS + GA_H + aoff + kof);
            LDSM4(ah[1][0], ah[1][1], ah[1][2], ah[1][3], sS + GA_H + aoff + 1280 + kof);
#pragma unroll
            for (int p = 0; p < 4; p++)
                LDSM4(bhf[2 * p][0], bhf[2 * p][1], bhf[2 * p + 1][0], bhf[2 * p + 1][1],
                      sS + GB_H + boff + (uint32_t)p * 1280 + kof);
#pragma unroll
            for (int mt = 0; mt < 2; mt++)
#pragma unroll
                for (int nt = 0; nt < 8; nt++)
                    mma_f16(acc[mt][nt], ah[mt], bhf[nt]);

            if (two_pass) {
                LDSM4(al[0][0], al[0][1], al[0][2], al[0][3], sS + GA_L + aoff + kof);
                LDSM4(al[1][0], al[1][1], al[1][2], al[1][3], sS + GA_L + aoff + 1280 + kof);
#pragma unroll
                for (int mt = 0; mt < 2; mt++)
#pragma unroll
                    for (int nt = 0; nt < 8; nt++)
                        mma_f16(acc[mt][nt], al[mt], bhf[nt]);
            }
        }
    }

    // epilogue
    if (mode < 3) {
#pragma unroll
        for (int mt = 0; mt < 2; mt++) {
#pragma unroll
            for (int nt = 0; nt < 8; nt++) {
                const int row0 = m0 + wm * 32 + mt * 16 + g;
                const int col = n0 + wn * 64 + nt * 8 + t4 * 2;
                const int h = col >> 6, dh = col & 63;
#pragma unroll
                for (int half = 0; half < 2; half++) {
                    const int row = row0 + half * 8;
                    const int bb = row >> 11, sq = row & 2047;
                    const size_t idx = (((size_t)(bb * H_ + h) * S_) + sq) * HD_ + dh;
                    const float v0 = acc[mt][nt][2 * half];
                    const float v1 = acc[mt][nt][2 * half + 1];
                    if (mode == 0) {
                        uint32_t hw, lw;
                        split2h(v0, v1, hw, lw);
                        *(uint32_t*)&g_qh[idx] = hw;
                        *(uint32_t*)&g_ql[idx] = lw;
                    } else if (mode == 1) {
                        *(uint32_t*)&g_kh[idx] = pack2h(v0, v1);
                    } else {
                        *(uint32_t*)&g_vh[idx] = pack2h(v0, v1);
                    }
                }
            }
        }
    } else {
#pragma unroll
        for (int mt = 0; mt < 2; mt++) {
#pragma unroll
            for (int nt = 0; nt < 8; nt++) {
                const int row0 = m0 + wm * 32 + mt * 16 + g;
                const int col = n0 + wn * 64 + nt * 8 + t4 * 2;
                *(float2*)&Cout[(size_t)row0 * 1024 + col] =
                    make_float2(acc[mt][nt][0], acc[mt][nt][1]);
                *(float2*)&Cout[(size_t)(row0 + 8) * 1024 + col] =
                    make_float2(acc[mt][nt][2], acc[mt][nt][3]);
            }
        }
    }
}

// ---------------------------------------------------------------------------
// Flash attention: fp16 2-pass HMMA, double-buffered cp.async K/V (hi only),
// ldmatrix(.trans). Bq=128, Bk=64, 8 warps, register softmax.
// Stage: Kh/Vh each [64 rows x 144B stride] = 18432 B; 2 stages.
// ---------------------------------------------------------------------------
#define AT_KH 0
#define AT_VH 9216
#define AT_ST 18432
#define AT_SMEM (2 * AT_ST)   // 36864

__global__ __launch_bounds__(256, 2) void attn_k()
{
    const uint32_t sb = smem_u32(g_dynsm);

    const int tid = threadIdx.x;
    const int wid = tid >> 5;
    const int lid = tid & 31;
    const int g = lid >> 2;
    const int t4 = lid & 3;
    const int lrow = lid & 7;
    const int mlo = (lid >> 3) & 1;
    const int mhi = (lid >> 4) & 1;
    const int qt = 15 - (int)blockIdx.x;
    const int h = blockIdx.y;
    const int b = blockIdx.z;
    const int q0 = qt * 128;
    const size_t bho = (size_t)(b * H_ + h) * S_ * HD_;

    const int wrow = q0 + wid * 16;
    const int row0 = wrow + g;

    // ldmatrix per-lane offsets (144B stride)
    const uint32_t koff = (uint32_t)((mhi * 8 + lrow) * 144 + mlo * 16);
    const uint32_t voff = (uint32_t)((mlo * 8 + lrow) * 144 + mhi * 16);

    // loader mapping
    const int ldr = tid >> 2;
    const int ldc = (tid & 3) * 16;
    const uint32_t ldst = (uint32_t)ldr * 144 + (uint32_t)ldc * 2;

#define ATT_ISSUE(stg, kvi) do {                                               \
        const size_t go_ = bho + (size_t)((kvi) * 64 + ldr) * 64 + ldc;        \
        const uint32_t d_ = sb + (uint32_t)(stg) * AT_ST + ldst;               \
        CP_ASYNC16(d_ + AT_KH,      g_kh + go_);                               \
        CP_ASYNC16(d_ + AT_KH + 16, g_kh + go_ + 8);                           \
        CP_ASYNC16(d_ + AT_VH,      g_vh + go_);                               \
        CP_ASYNC16(d_ + AT_VH + 16, g_vh + go_ + 8);                           \
        CP_COMMIT();                                                           \
    } while (0)

    // Q fragments from pre-split gmem
    uint32_t qh[4][4], ql[4][4];
    {
        const uint32_t* qhp = (const uint32_t*)(g_qh + bho);
        const uint32_t* qlp = (const uint32_t*)(g_ql + bho);
        const int ra = row0 * 32;
        const int rb = (row0 + 8) * 32;
#pragma unroll
        for (int ks = 0; ks < 4; ks++) {
            const int kw = ks * 8 + t4;
            qh[ks][0] = qhp[ra + kw];
            qh[ks][1] = qhp[rb + kw];
            qh[ks][2] = qhp[ra + kw + 4];
            qh[ks][3] = qhp[rb + kw + 4];
            ql[ks][0] = qlp[ra + kw];
            ql[ks][1] = qlp[rb + kw];
            ql[ks][2] = qlp[ra + kw + 4];
            ql[ks][3] = qlp[rb + kw + 4];
        }
    }

    float o[8][4];
#pragma unroll
    for (int nt = 0; nt < 8; nt++)
#pragma unroll
        for (int q = 0; q < 4; q++) o[nt][q] = 0.f;
    float mrow0 = -CUDART_INF_F, mrow1 = -CUDART_INF_F;
    float lrow0v = 0.f, lrow1v = 0.f;

    const int nkv = 2 * qt + 2;
    ATT_ISSUE(0, 0);

    for (int kv = 0; kv < nkv; kv++) {
        const int k0 = kv * 64;
        __syncthreads();                    // all warps done with other stage
        if (kv + 1 < nkv) {
            ATT_ISSUE((kv + 1) & 1, kv + 1);
            CP_WAIT(1);
        } else {
            CP_WAIT(0);
        }
        __syncthreads();                    // tile kv visible to all

        const uint32_t sbs = sb + (uint32_t)(kv & 1) * AT_ST;

        if (k0 <= wrow + 15) {
            // ---- S = Q K^T (2 passes: Qh*Kh + Ql*Kh) ----
            float s[8][4];
#pragma unroll
            for (int nt = 0; nt < 8; nt++)
#pragma unroll
                for (int q = 0; q < 4; q++) s[nt][q] = 0.f;

#pragma unroll
            for (int ks = 0; ks < 4; ks++) {
                uint32_t kbh[8][2];
#pragma unroll
                for (int p = 0; p < 4; p++)
                    LDSM4(kbh[2 * p][0], kbh[2 * p][1], kbh[2 * p + 1][0], kbh[2 * p + 1][1],
                          sbs + AT_KH + koff + (uint32_t)p * 2304 + (uint32_t)ks * 32);
#pragma unroll
                for (int nt = 0; nt < 8; nt++) mma_f16(s[nt], qh[ks], kbh[nt]);
#pragma unroll
                for (int nt = 0; nt < 8; nt++) mma_f16(s[nt], ql[ks], kbh[nt]);
            }

            // ---- scale (1/8, exact) ----
#pragma unroll
            for (int nt = 0; nt < 8; nt++)
#pragma unroll
                for (int q = 0; q < 4; q++) s[nt][q] *= 0.125f;

            // ---- causal mask ----
            if (k0 + 63 > wrow) {
#pragma unroll
                for (int nt = 0; nt < 8; nt++) {
                    const int col0 = k0 + nt * 8 + 2 * t4;
                    if (col0 > row0)         s[nt][0] = -CUDART_INF_F;
                    if (col0 + 1 > row0)     s[nt][1] = -CUDART_INF_F;
                    if (col0 > row0 + 8)     s[nt][2] = -CUDART_INF_F;
                    if (col0 + 1 > row0 + 8) s[nt][3] = -CUDART_INF_F;
                }
            }

            // ---- online softmax ----
            float mx0 = -CUDART_INF_F, mx1 = -CUDART_INF_F;
#pragma unroll
            for (int nt = 0; nt < 8; nt++) {
                mx0 = fmaxf(mx0, fmaxf(s[nt][0], s[nt][1]));
                mx1 = fmaxf(mx1, fmaxf(s[nt][2], s[nt][3]));
            }
            mx0 = fmaxf(mx0, __shfl_xor_sync(0xffffffffu, mx0, 1));
            mx0 = fmaxf(mx0, __shfl_xor_sync(0xffffffffu, mx0, 2));
            mx1 = fmaxf(mx1, __shfl_xor_sync(0xffffffffu, mx1, 1));
            mx1 = fmaxf(mx1, __shfl_xor_sync(0xffffffffu, mx1, 2));

            const float nm0 = fmaxf(mrow0, mx0);
            const float nm1 = fmaxf(mrow1, mx1);
            const float c0 = __expf(mrow0 - nm0);
            const float c1 = __expf(mrow1 - nm1);
            float sum0 = 0.f, sum1 = 0.f;
#pragma unroll
            for (int nt = 0; nt < 8; nt++) {
                s[nt][0] = __expf(s[nt][0] - nm0);
                s[nt][1] = __expf(s[nt][1] - nm0);
                s[nt][2] = __expf(s[nt][2] - nm1);
                s[nt][3] = __expf(s[nt][3] - nm1);
                sum0 += s[nt][0] + s[nt][1];
                sum1 += s[nt][2] + s[nt][3];
            }
            sum0 += __shfl_xor_sync(0xffffffffu, sum0, 1);
            sum0 += __shfl_xor_sync(0xffffffffu, sum0, 2);
            sum1 += __shfl_xor_sync(0xffffffffu, sum1, 1);
            sum1 += __shfl_xor_sync(0xffffffffu, sum1, 2);
            lrow0v = lrow0v * c0 + sum0;
            lrow1v = lrow1v * c1 + sum1;
            mrow0 = nm0;
            mrow1 = nm1;
#pragma unroll
            for (int nt = 0; nt < 8; nt++) {
                o[nt][0] *= c0;
                o[nt][1] *= c0;
                o[nt][2] *= c1;
                o[nt][3] *= c1;
            }

            // ---- P -> fp16 split A-frags ----
            uint32_t pah[4][4], pal[4][4];
#pragma unroll
            for (int kk = 0; kk < 4; kk++) {
                split2h(s[2 * kk][0], s[2 * kk][1], pah[kk][0], pal[kk][0]);
                split2h(s[2 * kk][2], s[2 * kk][3], pah[kk][1], pal[kk][1]);
                split2h(s[2 * kk + 1][0], s[2 * kk + 1][1], pah[kk][2], pal[kk][2]);
                split2h(s[2 * kk + 1][2], s[2 * kk + 1][3], pah[kk][3], pal[kk][3]);
            }

            // ---- O += P V (2 passes: Ph*Vh + Pl*Vh), V^T via ldmatrix.trans ----
#pragma unroll
            for (int kk = 0; kk < 4; kk++) {
                uint32_t vbh[8][2];
#pragma unroll
                for (int p = 0; p < 4; p++)
                    LDSM4T(vbh[2 * p][0], vbh[2 * p][1], vbh[2 * p + 1][0], vbh[2 * p + 1][1],
                           sbs + AT_VH + voff + (uint32_t)kk * 2304 + (uint32_t)p * 32);
#pragma unroll
                for (int nt = 0; nt < 8; nt++) mma_f16(o[nt], pah[kk], vbh[nt]);
#pragma unroll
                for (int nt = 0; nt < 8; nt++) mma_f16(o[nt], pal[kk], vbh[nt]);
            }
        }
    }

    // ---- epilogue: divide by l, split, write ctx hi/lo ----
    const float inv0 = 1.f / lrow0v;
    const float inv1 = 1.f / lrow1v;
    const size_t base0 = ((size_t)(b * S_ + row0)) * D_ + h * HD_;
    const size_t base1 = ((size_t)(b * S_ + row0 + 8)) * D_ + h * HD_;
#pragma unroll
    for (int nt = 0; nt < 8; nt++) {
        const int d = nt * 8 + 2 * t4;
        uint32_t hw, lw;
        split2h(o[nt][0] * inv0, o[nt][1] * inv0, hw, lw);
        *(uint32_t*)&g_cth[base0 + d] = hw;
        *(uint32_t*)&g_ctl[base0 + d] = lw;
        split2h(o[nt][2] * inv1, o[nt][3] * inv1, hw, lw);
        *(uint32_t*)&g_cth[base1 + d] = hw;
        *(uint32_t*)&g_ctl[base1 + d] = lw;
    }
}

// ---------------------------------------------------------------------------
extern "C" void kernel_launch(void* const* d_in, const int* in_sizes, int n_in,
                              void* d_out, int out_size)
{
    const float* q  = (const float*)d_in[0];
    const float* k  = (const float*)d_in[1];
    const float* v  = (const float*)d_in[2];
    const float* wq = (const float*)d_in[3];
    const float* wk = (const float*)d_in[4];
    const float* wv = (const float*)d_in[5];
    const float* wo = (const float*)d_in[6];
    float* out = (float*)d_out;

    asplit_k<<<dim3(8192, 3), 256>>>(q, k, v);
    wsplit_k<<<dim3(32, 32, 4), dim3(32, 8)>>>(wq, wk, wv, wo);

    cudaFuncSetAttribute(gemm_mma, cudaFuncAttributeMaxDynamicSharedMemorySize, G_SMEM);
    cudaFuncSetAttribute(attn_k, cudaFuncAttributeMaxDynamicSharedMemorySize, AT_SMEM);

    gemm_mma<<<dim3(8, 64, 3), 256, G_SMEM>>>(nullptr, 0);   // QKV fused

    attn_k<<<dim3(16, 16, 4), 256, AT_SMEM>>>();

    gemm_mma<<<dim3(8, 64, 1), 256, G_SMEM>>>(out, 3);       // O projection
}

// round 15
// speedup vs baseline: 5.2117x; 1.0084x over previous
#include <cuda_runtime.h>
#include <cuda_fp16.h>
#include <math_constants.h>
#include <cstdint>

#define B_  4
#define S_  2048
#define D_  1024
#define H_  16
#define HD_ 64
#define NEL (8ull * 1024 * 1024)   // 8192*1024 elements per matrix

// Scratch (device globals). fp16 split: A-side hi/lo where precision matters,
// B-side hi only. K/V projections are 1-pass (outputs stored hi-only anyway).
__device__ __half g_inh[3 * NEL], g_inl[3 * NEL];   // q,k,v inputs [m][k]
__device__ __half g_qh[NEL], g_ql[NEL];             // xq [b,h,s,dh]
__device__ __half g_kh[NEL];                        // xk (hi only)
__device__ __half g_vh[NEL];                        // xv (hi only)
__device__ __half g_cth[NEL], g_ctl[NEL];           // ctx [b,s,d]
__device__ __half g_wth[4 * NEL / 8];               // W^T [n][k] x4 (hi only)

__device__ __forceinline__ uint32_t smem_u32(const void* p) {
    uint32_t a;
    asm("{ .reg .u64 t; cvta.to.shared.u64 t, %1; cvt.u32.u64 %0, t; }" : "=r"(a) : "l"(p));
    return a;
}

#define LDSM4(r0, r1, r2, r3, a) \
    asm volatile("ldmatrix.sync.aligned.m8n8.x4.shared.b16 {%0,%1,%2,%3}, [%4];" \
                 : "=r"(r0), "=r"(r1), "=r"(r2), "=r"(r3) : "r"(a))
#define LDSM4T(r0, r1, r2, r3, a) \
    asm volatile("ldmatrix.sync.aligned.m8n8.x4.trans.shared.b16 {%0,%1,%2,%3}, [%4];" \
                 : "=r"(r0), "=r"(r1), "=r"(r2), "=r"(r3) : "r"(a))
#define CP_ASYNC16(dst, src) \
    asm volatile("cp.async.cg.shared.global [%0], [%1], 16;" :: "r"(dst), "l"(src) : "memory")
#define CP_COMMIT() asm volatile("cp.async.commit_group;" ::: "memory")
#define CP_WAIT(n)  asm volatile("cp.async.wait_group %0;" :: "n"(n) : "memory")

__device__ __forceinline__ void mma_f16(float* d, const uint32_t* a, const uint32_t* b) {
    asm volatile(
        "mma.sync.aligned.m16n8k16.row.col.f32.f16.f16.f32 "
        "{%0,%1,%2,%3}, {%4,%5,%6,%7}, {%8,%9}, {%0,%1,%2,%3};"
        : "+f"(d[0]), "+f"(d[1]), "+f"(d[2]), "+f"(d[3])
        : "r"(a[0]), "r"(a[1]), "r"(a[2]), "r"(a[3]), "r"(b[0]), "r"(b[1]));
}

__device__ __forceinline__ void split2h(float x, float y, uint32_t& hi, uint32_t& lo) {
    __half2 h = __floats2half2_rn(x, y);
    float rx = x - __half2float(__low2half(h));
    float ry = y - __half2float(__high2half(h));
    __half2 l = __floats2half2_rn(rx, ry);
    hi = reinterpret_cast<uint32_t&>(h);
    lo = reinterpret_cast<uint32_t&>(l);
}

__device__ __forceinline__ uint32_t pack2h(float x, float y) {
    __half2 h = __floats2half2_rn(x, y);
    return reinterpret_cast<uint32_t&>(h);
}

// ---------------------------------------------------------------------------
// Activation split: q/k/v fp32 -> fp16 hi (+lo for q only; k/v proj is 1-pass)
// ---------------------------------------------------------------------------
__global__ __launch_bounds__(256) void asplit_k(const float* __restrict__ q,
                                                const float* __restrict__ k,
                                                const float* __restrict__ v) {
    const int z = blockIdx.y;
    const float* src = (z == 0) ? q : (z == 1) ? k : v;
    const size_t i = ((size_t)blockIdx.x * 256 + threadIdx.x) * 4;
    float4 f = *(const float4*)(src + i);
    uint32_t h0, l0, h1, l1;
    split2h(f.x, f.y, h0, l0);
    split2h(f.z, f.w, h1, l1);
    *(uint2*)&g_inh[z * NEL + i] = make_uint2(h0, h1);
    if (z == 0)
        *(uint2*)&g_inl[z * NEL + i] = make_uint2(l0, l1);
}

// ---------------------------------------------------------------------------
// Weight transpose + fp16 (hi only): Wt[n][k] = W[k][n]
// ---------------------------------------------------------------------------
__global__ __launch_bounds__(256) void wsplit_k(const float* __restrict__ w0,
                                                const float* __restrict__ w1,
                                                const float* __restrict__ w2,
                                                const float* __restrict__ w3) {
    __shared__ float t[32][33];
    const int widx = blockIdx.z;
    const float* W = (widx == 0) ? w0 : (widx == 1) ? w1 : (widx == 2) ? w2 : w3;
    const int n0 = blockIdx.x * 32, k0 = blockIdx.y * 32;
    const int tx = threadIdx.x, ty = threadIdx.y;
#pragma unroll
    for (int i = 0; i < 32; i += 8)
        t[ty + i][tx] = W[(size_t)(k0 + ty + i) * 1024 + n0 + tx];
    __syncthreads();
    __half* Th = g_wth + (size_t)widx * 1024 * 1024;
#pragma unroll
    for (int i = 0; i < 32; i += 8) {
        const int n = n0 + ty + i, k = k0 + tx;
        Th[(size_t)n * 1024 + k] = __float2half(t[tx][ty + i]);
    }
}

// ---------------------------------------------------------------------------
// fp16 HMMA GEMM. Q/O projections: 2-pass (Ah*Bh + Al*Bh). K/V: 1-pass.
// cp.async 3-stage, ldmatrix. BM=128, BN=128, BK=32, 256 thr, 2 CTAs/SM.
// ---------------------------------------------------------------------------
#define GA_H 0
#define GA_L 10240
#define GB_H 20480
#define GST  30720
#define G_SMEM (3 * GST)   // 92160

extern __shared__ unsigned char g_dynsm[];

__global__ __launch_bounds__(256, 2)
void gemm_mma(float* __restrict__ Cout, int mode_base)
{
    const uint32_t sb = smem_u32(g_dynsm);

    const int tid = threadIdx.x;
    const int wid = tid >> 5;
    const int lid = tid & 31;
    const int g = lid >> 2;
    const int t4 = lid & 3;
    const int wm = wid & 3;
    const int wn = wid >> 2;
    const int lrow = lid & 7;
    const int mlo = (lid >> 3) & 1;
    const int mhi = (lid >> 4) & 1;

    const int mode = (mode_base == 3) ? 3 : (int)blockIdx.z;
    const bool two_pass = (mode == 0 || mode == 3);
    const __half* Ah = (mode == 3) ? g_cth : g_inh + (size_t)mode * NEL;
    const __half* Al = (mode == 3) ? g_ctl : g_inl + (size_t)mode * NEL;
    const __half* Bh = g_wth + (size_t)mode * 1024 * 1024;

    const int m0 = blockIdx.y * 128;
    const int n0 = blockIdx.x * 128;

    // loader mapping
    const int lr = tid >> 1;
    const int khalf = (tid & 1) * 16;
    const __half* sAh = Ah + (size_t)(m0 + lr) * 1024 + khalf;
    const __half* sAl = Al + (size_t)(m0 + lr) * 1024 + khalf;
    const __half* sBh = Bh + (size_t)(n0 + lr) * 1024 + khalf;
    const uint32_t drow = (uint32_t)lr * 80 + (uint32_t)khalf * 2;

    float acc[2][8][4];
#pragma unroll
    for (int mt = 0; mt < 2; mt++)
#pragma unroll
        for (int nt = 0; nt < 8; nt++)
#pragma unroll
            for (int q = 0; q < 4; q++) acc[mt][nt][q] = 0.f;

    // ldmatrix per-lane offsets (80B rows)
    const uint32_t aoff = (uint32_t)((wm * 32 + mlo * 8 + lrow) * 80 + mhi * 16);
    const uint32_t boff = (uint32_t)((wn * 64 + mhi * 8 + lrow) * 80 + mlo * 16);

#define G_ISSUE(stg, c) do {                                     \
        const uint32_t d_ = sb + (uint32_t)(stg) * GST + drow;   \
        const int kg_ = (c) * 32;                                \
        CP_ASYNC16(d_ + GA_H,      sAh + kg_);                   \
        CP_ASYNC16(d_ + GA_H + 16, sAh + kg_ + 8);               \
        if (two_pass) {                                          \
            CP_ASYNC16(d_ + GA_L,      sAl + kg_);               \
            CP_ASYNC16(d_ + GA_L + 16, sAl + kg_ + 8);           \
        }                                                        \
        CP_ASYNC16(d_ + GB_H,      sBh + kg_);                   \
        CP_ASYNC16(d_ + GB_H + 16, sBh + kg_ + 8);               \
        CP_COMMIT();                                             \
    } while (0)

    G_ISSUE(0, 0);
    G_ISSUE(1, 1);

    for (int c = 0; c < 32; c++) {
        if (c < 31) { CP_WAIT(1); } else { CP_WAIT(0); }
        __syncthreads();                 // chunk c visible; stage (c+2)%3 free
        if (c < 30) G_ISSUE((c + 2) % 3, c + 2);

        const uint32_t sS = sb + (uint32_t)(c % 3) * GST;
#pragma unroll
        for (int kk = 0; kk < 2; kk++) {
            const uint32_t kof = (uint32_t)kk * 32;

            uint32_t ah[2][4], al[2][4], bhf[8][2];
            LDSM4(ah[0][0], ah[0][1], ah[0][2], ah[0][3], sS + GA_H + aoff + kof);
            LDSM4(ah[1][0], ah[1][1], ah[1][2], ah[1][3], sS + GA_H + aoff + 1280 + kof);
#pragma unroll
            for (int p = 0; p < 4; p++)
                LDSM4(bhf[2 * p][0], bhf[2 * p][1], bhf[2 * p + 1][0], bhf[2 * p + 1][1],
                      sS + GB_H + boff + (uint32_t)p * 1280 + kof);
#pragma unroll
            for (int mt = 0; mt < 2; mt++)
#pragma unroll
                for (int nt = 0; nt < 8; nt++)
                    mma_f16(acc[mt][nt], ah[mt], bhf[nt]);

            if (two_pass) {
                LDSM4(al[0][0], al[0][1], al[0][2], al[0][3], sS + GA_L + aoff + kof);
                LDSM4(al[1][0], al[1][1], al[1][2], al[1][3], sS + GA_L + aoff + 1280 + kof);
#pragma unroll
                for (int mt = 0; mt < 2; mt++)
#pragma unroll
                    for (int nt = 0; nt < 8; nt++)
                        mma_f16(acc[mt][nt], al[mt], bhf[nt]);
            }
        }
    }

    // epilogue
    if (mode < 3) {
#pragma unroll
        for (int mt = 0; mt < 2; mt++) {
#pragma unroll
            for (int nt = 0; nt < 8; nt++) {
                const int row0 = m0 + wm * 32 + mt * 16 + g;
                const int col = n0 + wn * 64 + nt * 8 + t4 * 2;
                const int h = col >> 6, dh = col & 63;
#pragma unroll
                for (int half = 0; half < 2; half++) {
                    const int row = row0 + half * 8;
                    const int bb = row >> 11, sq = row & 2047;
                    const size_t idx = (((size_t)(bb * H_ + h) * S_) + sq) * HD_ + dh;
                    const float v0 = acc[mt][nt][2 * half];
                    const float v1 = acc[mt][nt][2 * half + 1];
                    if (mode == 0) {
                        uint32_t hw, lw;
                        split2h(v0, v1, hw, lw);
                        *(uint32_t*)&g_qh[idx] = hw;
                        *(uint32_t*)&g_ql[idx] = lw;
                    } else if (mode == 1) {
                        *(uint32_t*)&g_kh[idx] = pack2h(v0, v1);
                    } else {
                        *(uint32_t*)&g_vh[idx] = pack2h(v0, v1);
                    }
                }
            }
        }
    } else {
#pragma unroll
        for (int mt = 0; mt < 2; mt++) {
#pragma unroll
            for (int nt = 0; nt < 8; nt++) {
                const int row0 = m0 + wm * 32 + mt * 16 + g;
                const int col = n0 + wn * 64 + nt * 8 + t4 * 2;
                *(float2*)&Cout[(size_t)row0 * 1024 + col] =
                    make_float2(acc[mt][nt][0], acc[mt][nt][1]);
                *(float2*)&Cout[(size_t)(row0 + 8) * 1024 + col] =
                    make_float2(acc[mt][nt][2], acc[mt][nt][3]);
            }
        }
    }
}

// ---------------------------------------------------------------------------
// Flash attention: fp16 2-pass HMMA, 3-stage cp.async K/V (hi only), one
// syncthreads per tile, exp2-domain softmax. Bq=128, Bk=64, 8 warps.
// Stage: Kh/Vh each [64 rows x 144B stride] = 18432 B; 3 stages.
// ---------------------------------------------------------------------------
#define AT_KH 0
#define AT_VH 9216
#define AT_ST 18432
#define AT_SMEM (3 * AT_ST)   // 55296

// softmax in exp2 domain: s_scaled = s_raw * (1/8) * log2(e)
#define ATT_SCL 0.18033688011112042f

__global__ __launch_bounds__(256, 2) void attn_k()
{
    const uint32_t sb = smem_u32(g_dynsm);

    const int tid = threadIdx.x;
    const int wid = tid >> 5;
    const int lid = tid & 31;
    const int g = lid >> 2;
    const int t4 = lid & 3;
    const int lrow = lid & 7;
    const int mlo = (lid >> 3) & 1;
    const int mhi = (lid >> 4) & 1;
    const int qt = 15 - (int)blockIdx.x;
    const int h = blockIdx.y;
    const int b = blockIdx.z;
    const int q0 = qt * 128;
    const size_t bho = (size_t)(b * H_ + h) * S_ * HD_;

    const int wrow = q0 + wid * 16;
    const int row0 = wrow + g;

    // ldmatrix per-lane offsets (144B stride)
    const uint32_t koff = (uint32_t)((mhi * 8 + lrow) * 144 + mlo * 16);
    const uint32_t voff = (uint32_t)((mlo * 8 + lrow) * 144 + mhi * 16);

    // loader mapping
    const int ldr = tid >> 2;
    const int ldc = (tid & 3) * 16;
    const uint32_t ldst = (uint32_t)ldr * 144 + (uint32_t)ldc * 2;

#define ATT_ISSUE(stg, kvi) do {                                               \
        const size_t go_ = bho + (size_t)((kvi) * 64 + ldr) * 64 + ldc;        \
        const uint32_t d_ = sb + (uint32_t)(stg) * AT_ST + ldst;               \
        CP_ASYNC16(d_ + AT_KH,      g_kh + go_);                               \
        CP_ASYNC16(d_ + AT_KH + 16, g_kh + go_ + 8);                           \
        CP_ASYNC16(d_ + AT_VH,      g_vh + go_);                               \
        CP_ASYNC16(d_ + AT_VH + 16, g_vh + go_ + 8);                           \
        CP_COMMIT();                                                           \
    } while (0)

    // Q fragments from pre-split gmem
    uint32_t qh[4][4], ql[4][4];
    {
        const uint32_t* qhp = (const uint32_t*)(g_qh + bho);
        const uint32_t* qlp = (const uint32_t*)(g_ql + bho);
        const int ra = row0 * 32;
        const int rb = (row0 + 8) * 32;
#pragma unroll
        for (int ks = 0; ks < 4; ks++) {
            const int kw = ks * 8 + t4;
            qh[ks][0] = qhp[ra + kw];
            qh[ks][1] = qhp[rb + kw];
            qh[ks][2] = qhp[ra + kw + 4];
            qh[ks][3] = qhp[rb + kw + 4];
            ql[ks][0] = qlp[ra + kw];
            ql[ks][1] = qlp[rb + kw];
            ql[ks][2] = qlp[ra + kw + 4];
            ql[ks][3] = qlp[rb + kw + 4];
        }
    }

    float o[8][4];
#pragma unroll
    for (int nt = 0; nt < 8; nt++)
#pragma unroll
        for (int q = 0; q < 4; q++) o[nt][q] = 0.f;
    float mrow0 = -CUDART_INF_F, mrow1 = -CUDART_INF_F;
    float lrow0v = 0.f, lrow1v = 0.f;

    const int nkv = 2 * qt + 2;
    ATT_ISSUE(0, 0);
    if (nkv > 1) ATT_ISSUE(1, 1);

    for (int kv = 0; kv < nkv; kv++) {
        const int k0 = kv * 64;
        if (kv + 1 < nkv) { CP_WAIT(1); } else { CP_WAIT(0); }
        __syncthreads();                    // tile kv visible; stage (kv+2)%3 free
        if (kv + 2 < nkv) ATT_ISSUE((kv + 2) % 3, kv + 2);

        const uint32_t sbs = sb + (uint32_t)(kv % 3) * AT_ST;

        if (k0 <= wrow + 15) {
            // ---- S = Q K^T (2 passes: Qh*Kh + Ql*Kh) ----
            float s[8][4];
#pragma unroll
            for (int nt = 0; nt < 8; nt++)
#pragma unroll
                for (int q = 0; q < 4; q++) s[nt][q] = 0.f;

#pragma unroll
            for (int ks = 0; ks < 4; ks++) {
                uint32_t kbh[8][2];
#pragma unroll
                for (int p = 0; p < 4; p++)
                    LDSM4(kbh[2 * p][0], kbh[2 * p][1], kbh[2 * p + 1][0], kbh[2 * p + 1][1],
                          sbs + AT_KH + koff + (uint32_t)p * 2304 + (uint32_t)ks * 32);
#pragma unroll
                for (int nt = 0; nt < 8; nt++) mma_f16(s[nt], qh[ks], kbh[nt]);
#pragma unroll
                for (int nt = 0; nt < 8; nt++) mma_f16(s[nt], ql[ks], kbh[nt]);
            }

            // ---- scale into exp2 domain ----
#pragma unroll
            for (int nt = 0; nt < 8; nt++)
#pragma unroll
                for (int q = 0; q < 4; q++) s[nt][q] *= ATT_SCL;

            // ---- causal mask ----
            if (k0 + 63 > wrow) {
#pragma unroll
                for (int nt = 0; nt < 8; nt++) {
                    const int col0 = k0 + nt * 8 + 2 * t4;
                    if (col0 > row0)         s[nt][0] = -CUDART_INF_F;
                    if (col0 + 1 > row0)     s[nt][1] = -CUDART_INF_F;
                    if (col0 > row0 + 8)     s[nt][2] = -CUDART_INF_F;
                    if (col0 + 1 > row0 + 8) s[nt][3] = -CUDART_INF_F;
                }
            }

            // ---- online softmax (exp2 domain) ----
            float mx0 = -CUDART_INF_F, mx1 = -CUDART_INF_F;
#pragma unroll
            for (int nt = 0; nt < 8; nt++) {
                mx0 = fmaxf(mx0, fmaxf(s[nt][0], s[nt][1]));
                mx1 = fmaxf(mx1, fmaxf(s[nt][2], s[nt][3]));
            }
            mx0 = fmaxf(mx0, __shfl_xor_sync(0xffffffffu, mx0, 1));
            mx0 = fmaxf(mx0, __shfl_xor_sync(0xffffffffu, mx0, 2));
            mx1 = fmaxf(mx1, __shfl_xor_sync(0xffffffffu, mx1, 1));
            mx1 = fmaxf(mx1, __shfl_xor_sync(0xffffffffu, mx1, 2));

            const float nm0 = fmaxf(mrow0, mx0);
            const float nm1 = fmaxf(mrow1, mx1);
            const float c0 = exp2f(mrow0 - nm0);
            const float c1 = exp2f(mrow1 - nm1);
            float sum0 = 0.f, sum1 = 0.f;
#pragma unroll
            for (int nt = 0; nt < 8; nt++) {
                s[nt][0] = exp2f(s[nt][0] - nm0);
                s[nt][1] = exp2f(s[nt][1] - nm0);
                s[nt][2] = exp2f(s[nt][2] - nm1);
                s[nt][3] = exp2f(s[nt][3] - nm1);
                sum0 += s[nt][0] + s[nt][1];
                sum1 += s[nt][2] + s[nt][3];
            }
            sum0 += __shfl_xor_sync(0xffffffffu, sum0, 1);
            sum0 += __shfl_xor_sync(0xffffffffu, sum0, 2);
            sum1 += __shfl_xor_sync(0xffffffffu, sum1, 1);
            sum1 += __shfl_xor_sync(0xffffffffu, sum1, 2);
            lrow0v = lrow0v * c0 + sum0;
            lrow1v = lrow1v * c1 + sum1;
            mrow0 = nm0;
            mrow1 = nm1;
#pragma unroll
            for (int nt = 0; nt < 8; nt++) {
                o[nt][0] *= c0;
                o[nt][1] *= c0;
                o[nt][2] *= c1;
                o[nt][3] *= c1;
            }

            // ---- P -> fp16 split A-frags ----
            uint32_t pah[4][4], pal[4][4];
#pragma unroll
            for (int kk = 0; kk < 4; kk++) {
                split2h(s[2 * kk][0], s[2 * kk][1], pah[kk][0], pal[kk][0]);
                split2h(s[2 * kk][2], s[2 * kk][3], pah[kk][1], pal[kk][1]);
                split2h(s[2 * kk + 1][0], s[2 * kk + 1][1], pah[kk][2], pal[kk][2]);
                split2h(s[2 * kk + 1][2], s[2 * kk + 1][3], pah[kk][3], pal[kk][3]);
            }

            // ---- O += P V (2 passes: Ph*Vh + Pl*Vh), V^T via ldmatrix.trans ----
#pragma unroll
            for (int kk = 0; kk < 4; kk++) {
                uint32_t vbh[8][2];
#pragma unroll
                for (int p = 0; p < 4; p++)
                    LDSM4T(vbh[2 * p][0], vbh[2 * p][1], vbh[2 * p + 1][0], vbh[2 * p + 1][1],
                           sbs + AT_VH + voff + (uint32_t)kk * 2304 + (uint32_t)p * 32);
#pragma unroll
                for (int nt = 0; nt < 8; nt++) mma_f16(o[nt], pah[kk], vbh[nt]);
#pragma unroll
                for (int nt = 0; nt < 8; nt++) mma_f16(o[nt], pal[kk], vbh[nt]);
            }
        }
    }

    // ---- epilogue: divide by l, split, write ctx hi/lo ----
    const float inv0 = 1.f / lrow0v;
    const float inv1 = 1.f / lrow1v;
    const size_t base0 = ((size_t)(b * S_ + row0)) * D_ + h * HD_;
    const size_t base1 = ((size_t)(b * S_ + row0 + 8)) * D_ + h * HD_;
#pragma unroll
    for (int nt = 0; nt < 8; nt++) {
        const int d = nt * 8 + 2 * t4;
        uint32_t hw, lw;
        split2h(o[nt][0] * inv0, o[nt][1] * inv0, hw, lw);
        *(uint32_t*)&g_cth[base0 + d] = hw;
        *(uint32_t*)&g_ctl[base0 + d] = lw;
        split2h(o[nt][2] * inv1, o[nt][3] * inv1, hw, lw);
        *(uint32_t*)&g_cth[base1 + d] = hw;
        *(uint32_t*)&g_ctl[base1 + d] = lw;
    }
}

// ---------------------------------------------------------------------------
extern "C" void kernel_launch(void* const* d_in, const int* in_sizes, int n_in,
                              void* d_out, int out_size)
{
    const float* q  = (const float*)d_in[0];
    const float* k  = (const float*)d_in[1];
    const float* v  = (const float*)d_in[2];
    const float* wq = (const float*)d_in[3];
    const float* wk = (const float*)d_in[4];
    const float* wv = (const float*)d_in[5];
    const float* wo = (const float*)d_in[6];
    float* out = (float*)d_out;

    asplit_k<<<dim3(8192, 3), 256>>>(q, k, v);
    wsplit_k<<<dim3(32, 32, 4), dim3(32, 8)>>>(wq, wk, wv, wo);

    cudaFuncSetAttribute(gemm_mma, cudaFuncAttributeMaxDynamicSharedMemorySize, G_SMEM);
    cudaFuncSetAttribute(attn_k, cudaFuncAttributeMaxDynamicSharedMemorySize, AT_SMEM);

    gemm_mma<<<dim3(8, 64, 3), 256, G_SMEM>>>(nullptr, 0);   // QKV fused

    attn_k<<<dim3(16, 16, 4), 256, AT_SMEM>>>();

    gemm_mma<<<dim3(8, 64, 1), 256, G_SMEM>>>(out, 3);       // O projection
}

// round 16
// speedup vs baseline: 5.7495x; 1.1032x over previous
#include <cuda_runtime.h>
#include <cuda_fp16.h>
#include <math_constants.h>
#include <cstdint>

#define B_  4
#define S_  2048
#define D_  1024
#define H_  16
#define HD_ 64
#define NEL (8ull * 1024 * 1024)   // 8192*1024 elements per matrix

// Scratch (device globals). fp16 split: hi/lo only where the extra pass pays.
// xq carries the softmax scale (0.125*log2e) folded in at projection time.
__device__ __half g_inh[3 * NEL], g_inl[NEL];       // q,k,v inputs [m][k]; lo for q only
__device__ __half g_qh[NEL], g_ql[NEL];             // xq*scl [b,h,s,dh]
__device__ __half g_kh[NEL];                        // xk (hi only)
__device__ __half g_vh[NEL];                        // xv (hi only)
__device__ __half g_cth[NEL];                       // ctx [b,s,d] (hi only)
__device__ __half g_wth[4 * NEL / 8];               // W^T [n][k] x4 (hi only)

// softmax scale folded into Q: s = (scl*q)k, softmax in exp2 domain
#define ATT_SCL 0.18033688011112042f

__device__ __forceinline__ uint32_t smem_u32(const void* p) {
    uint32_t a;
    asm("{ .reg .u64 t; cvta.to.shared.u64 t, %1; cvt.u32.u64 %0, t; }" : "=r"(a) : "l"(p));
    return a;
}

#define LDSM4(r0, r1, r2, r3, a) \
    asm volatile("ldmatrix.sync.aligned.m8n8.x4.shared.b16 {%0,%1,%2,%3}, [%4];" \
                 : "=r"(r0), "=r"(r1), "=r"(r2), "=r"(r3) : "r"(a))
#define LDSM4T(r0, r1, r2, r3, a) \
    asm volatile("ldmatrix.sync.aligned.m8n8.x4.trans.shared.b16 {%0,%1,%2,%3}, [%4];" \
                 : "=r"(r0), "=r"(r1), "=r"(r2), "=r"(r3) : "r"(a))
#define CP_ASYNC16(dst, src) \
    asm volatile("cp.async.cg.shared.global [%0], [%1], 16;" :: "r"(dst), "l"(src) : "memory")
#define CP_COMMIT() asm volatile("cp.async.commit_group;" ::: "memory")
#define CP_WAIT(n)  asm volatile("cp.async.wait_group %0;" :: "n"(n) : "memory")

__device__ __forceinline__ void mma_f16(float* d, const uint32_t* a, const uint32_t* b) {
    asm volatile(
        "mma.sync.aligned.m16n8k16.row.col.f32.f16.f16.f32 "
        "{%0,%1,%2,%3}, {%4,%5,%6,%7}, {%8,%9}, {%0,%1,%2,%3};"
        : "+f"(d[0]), "+f"(d[1]), "+f"(d[2]), "+f"(d[3])
        : "r"(a[0]), "r"(a[1]), "r"(a[2]), "r"(a[3]), "r"(b[0]), "r"(b[1]));
}

__device__ __forceinline__ void split2h(float x, float y, uint32_t& hi, uint32_t& lo) {
    __half2 h = __floats2half2_rn(x, y);
    float rx = x - __half2float(__low2half(h));
    float ry = y - __half2float(__high2half(h));
    __half2 l = __floats2half2_rn(rx, ry);
    hi = reinterpret_cast<uint32_t&>(h);
    lo = reinterpret_cast<uint32_t&>(l);
}

__device__ __forceinline__ uint32_t pack2h(float x, float y) {
    __half2 h = __floats2half2_rn(x, y);
    return reinterpret_cast<uint32_t&>(h);
}

// ---------------------------------------------------------------------------
// Activation split: q/k/v fp32 -> fp16 hi (+lo for q only; k/v proj is 1-pass)
// ---------------------------------------------------------------------------
__global__ __launch_bounds__(256) void asplit_k(const float* __restrict__ q,
                                                const float* __restrict__ k,
                                                const float* __restrict__ v) {
    const int z = blockIdx.y;
    const float* src = (z == 0) ? q : (z == 1) ? k : v;
    const size_t i = ((size_t)blockIdx.x * 256 + threadIdx.x) * 4;
    float4 f = *(const float4*)(src + i);
    uint32_t h0, l0, h1, l1;
    split2h(f.x, f.y, h0, l0);
    split2h(f.z, f.w, h1, l1);
    *(uint2*)&g_inh[z * NEL + i] = make_uint2(h0, h1);
    if (z == 0)
        *(uint2*)&g_inl[i] = make_uint2(l0, l1);
}

// ---------------------------------------------------------------------------
// Weight transpose + fp16 (hi only): Wt[n][k] = W[k][n]
// ---------------------------------------------------------------------------
__global__ __launch_bounds__(256) void wsplit_k(const float* __restrict__ w0,
                                                const float* __restrict__ w1,
                                                const float* __restrict__ w2,
                                                const float* __restrict__ w3) {
    __shared__ float t[32][33];
    const int widx = blockIdx.z;
    const float* W = (widx == 0) ? w0 : (widx == 1) ? w1 : (widx == 2) ? w2 : w3;
    const int n0 = blockIdx.x * 32, k0 = blockIdx.y * 32;
    const int tx = threadIdx.x, ty = threadIdx.y;
#pragma unroll
    for (int i = 0; i < 32; i += 8)
        t[ty + i][tx] = W[(size_t)(k0 + ty + i) * 1024 + n0 + tx];
    __syncthreads();
    __half* Th = g_wth + (size_t)widx * 1024 * 1024;
#pragma unroll
    for (int i = 0; i < 32; i += 8) {
        const int n = n0 + ty + i, k = k0 + tx;
        Th[(size_t)n * 1024 + k] = __float2half(t[tx][ty + i]);
    }
}

// ---------------------------------------------------------------------------
// fp16 HMMA GEMM. Q projection: 2-pass (Ah*Bh + Al*Bh). K/V/O: 1-pass.
// cp.async 3-stage, ldmatrix. BM=128, BN=128, BK=32, 256 thr, 2 CTAs/SM.
// ---------------------------------------------------------------------------
#define GA_H 0
#define GA_L 10240
#define GB_H 20480
#define GST  30720
#define G_SMEM (3 * GST)   // 92160

extern __shared__ unsigned char g_dynsm[];

__global__ __launch_bounds__(256, 2)
void gemm_mma(float* __restrict__ Cout, int mode_base)
{
    const uint32_t sb = smem_u32(g_dynsm);

    const int tid = threadIdx.x;
    const int wid = tid >> 5;
    const int lid = tid & 31;
    const int g = lid >> 2;
    const int t4 = lid & 3;
    const int wm = wid & 3;
    const int wn = wid >> 2;
    const int lrow = lid & 7;
    const int mlo = (lid >> 3) & 1;
    const int mhi = (lid >> 4) & 1;

    const int mode = (mode_base == 3) ? 3 : (int)blockIdx.z;
    const bool two_pass = (mode == 0);
    const __half* Ah = (mode == 3) ? g_cth : g_inh + (size_t)mode * NEL;
    const __half* Al = g_inl;   // only dereferenced when two_pass (mode 0)
    const __half* Bh = g_wth + (size_t)mode * 1024 * 1024;

    const int m0 = blockIdx.y * 128;
    const int n0 = blockIdx.x * 128;

    // loader mapping
    const int lr = tid >> 1;
    const int khalf = (tid & 1) * 16;
    const __half* sAh = Ah + (size_t)(m0 + lr) * 1024 + khalf;
    const __half* sAl = Al + (size_t)(m0 + lr) * 1024 + khalf;
    const __half* sBh = Bh + (size_t)(n0 + lr) * 1024 + khalf;
    const uint32_t drow = (uint32_t)lr * 80 + (uint32_t)khalf * 2;

    float acc[2][8][4];
#pragma unroll
    for (int mt = 0; mt < 2; mt++)
#pragma unroll
        for (int nt = 0; nt < 8; nt++)
#pragma unroll
            for (int q = 0; q < 4; q++) acc[mt][nt][q] = 0.f;

    // ldmatrix per-lane offsets (80B rows)
    const uint32_t aoff = (uint32_t)((wm * 32 + mlo * 8 + lrow) * 80 + mhi * 16);
    const uint32_t boff = (uint32_t)((wn * 64 + mhi * 8 + lrow) * 80 + mlo * 16);

#define G_ISSUE(stg, c) do {                                     \
        const uint32_t d_ = sb + (uint32_t)(stg) * GST + drow;   \
        const int kg_ = (c) * 32;                                \
        CP_ASYNC16(d_ + GA_H,      sAh + kg_);                   \
        CP_ASYNC16(d_ + GA_H + 16, sAh + kg_ + 8);               \
        if (two_pass) {                                          \
            CP_ASYNC16(d_ + GA_L,      sAl + kg_);               \
            CP_ASYNC16(d_ + GA_L + 16, sAl + kg_ + 8);           \
        }                                                        \
        CP_ASYNC16(d_ + GB_H,      sBh + kg_);                   \
        CP_ASYNC16(d_ + GB_H + 16, sBh + kg_ + 8);               \
        CP_COMMIT();                                             \
    } while (0)

    G_ISSUE(0, 0);
    G_ISSUE(1, 1);

    for (int c = 0; c < 32; c++) {
        if (c < 31) { CP_WAIT(1); } else { CP_WAIT(0); }
        __syncthreads();                 // chunk c visible; stage (c+2)%3 free
        if (c < 30) G_ISSUE((c + 2) % 3, c + 2);

        const uint32_t sS = sb + (uint32_t)(c % 3) * GST;
#pragma unroll
        for (int kk = 0; kk < 2; kk++) {
            const uint32_t kof = (uint32_t)kk * 32;

            uint32_t ah[2][4], al[2][4], bhf[8][2];
            LDSM4(ah[0][0], ah[0][1], ah[0][2], ah[0][3], sS + GA_H + aoff + kof);
            LDSM4(ah[1][0], ah[1][1], ah[1][2], ah[1][3], sS + GA_H + aoff + 1280 + kof);
#pragma unroll
            for (int p = 0; p < 4; p++)
                LDSM4(bhf[2 * p][0], bhf[2 * p][1], bhf[2 * p + 1][0], bhf[2 * p + 1][1],
                      sS + GB_H + boff + (uint32_t)p * 1280 + kof);
#pragma unroll
            for (int mt = 0; mt < 2; mt++)
#pragma unroll
                for (int nt = 0; nt < 8; nt++)
                    mma_f16(acc[mt][nt], ah[mt], bhf[nt]);

            if (two_pass) {
                LDSM4(al[0][0], al[0][1], al[0][2], al[0][3], sS + GA_L + aoff + kof);
                LDSM4(al[1][0], al[1][1], al[1][2], al[1][3], sS + GA_L + aoff + 1280 + kof);
#pragma unroll
                for (int mt = 0; mt < 2; mt++)
#pragma unroll
                    for (int nt = 0; nt < 8; nt++)
                        mma_f16(acc[mt][nt], al[mt], bhf[nt]);
            }
        }
    }

    // epilogue
    if (mode < 3) {
#pragma unroll
        for (int mt = 0; mt < 2; mt++) {
#pragma unroll
            for (int nt = 0; nt < 8; nt++) {
                const int row0 = m0 + wm * 32 + mt * 16 + g;
                const int col = n0 + wn * 64 + nt * 8 + t4 * 2;
                const int h = col >> 6, dh = col & 63;
#pragma unroll
                for (int half = 0; half < 2; half++) {
                    const int row = row0 + half * 8;
                    const int bb = row >> 11, sq = row & 2047;
                    const size_t idx = (((size_t)(bb * H_ + h) * S_) + sq) * HD_ + dh;
                    const float v0 = acc[mt][nt][2 * half];
                    const float v1 = acc[mt][nt][2 * half + 1];
                    if (mode == 0) {
                        // fold softmax scale into xq before hi/lo split
                        uint32_t hw, lw;
                        split2h(v0 * ATT_SCL, v1 * ATT_SCL, hw, lw);
                        *(uint32_t*)&g_qh[idx] = hw;
                        *(uint32_t*)&g_ql[idx] = lw;
                    } else if (mode == 1) {
                        *(uint32_t*)&g_kh[idx] = pack2h(v0, v1);
                    } else {
                        *(uint32_t*)&g_vh[idx] = pack2h(v0, v1);
                    }
                }
            }
        }
    } else {
#pragma unroll
        for (int mt = 0; mt < 2; mt++) {
#pragma unroll
            for (int nt = 0; nt < 8; nt++) {
                const int row0 = m0 + wm * 32 + mt * 16 + g;
                const int col = n0 + wn * 64 + nt * 8 + t4 * 2;
                *(float2*)&Cout[(size_t)row0 * 1024 + col] =
                    make_float2(acc[mt][nt][0], acc[mt][nt][1]);
                *(float2*)&Cout[(size_t)(row0 + 8) * 1024 + col] =
                    make_float2(acc[mt][nt][2], acc[mt][nt][3]);
            }
        }
    }
}

// ---------------------------------------------------------------------------
// Flash attention: fp16 2-pass HMMA, 3-stage cp.async K/V (hi only), one
// syncthreads per tile, exp2-domain softmax (scale pre-folded into Q).
// Bq=128, Bk=64, 8 warps. Stage: Kh/Vh each [64 x 144B] = 18432 B; 3 stages.
// ---------------------------------------------------------------------------
#define AT_KH 0
#define AT_VH 9216
#define AT_ST 18432
#define AT_SMEM (3 * AT_ST)   // 55296

__global__ __launch_bounds__(256, 2) void attn_k()
{
    const uint32_t sb = smem_u32(g_dynsm);

    const int tid = threadIdx.x;
    const int wid = tid >> 5;
    const int lid = tid & 31;
    const int g = lid >> 2;
    const int t4 = lid & 3;
    const int lrow = lid & 7;
    const int mlo = (lid >> 3) & 1;
    const int mhi = (lid >> 4) & 1;
    const int qt = 15 - (int)blockIdx.x;
    const int h = blockIdx.y;
    const int b = blockIdx.z;
    const int q0 = qt * 128;
    const size_t bho = (size_t)(b * H_ + h) * S_ * HD_;

    const int wrow = q0 + wid * 16;
    const int row0 = wrow + g;

    // ldmatrix per-lane offsets (144B stride)
    const uint32_t koff = (uint32_t)((mhi * 8 + lrow) * 144 + mlo * 16);
    const uint32_t voff = (uint32_t)((mlo * 8 + lrow) * 144 + mhi * 16);

    // loader mapping
    const int ldr = tid >> 2;
    const int ldc = (tid & 3) * 16;
    const uint32_t ldst = (uint32_t)ldr * 144 + (uint32_t)ldc * 2;

#define ATT_ISSUE(stg, kvi) do {                                               \
        const size_t go_ = bho + (size_t)((kvi) * 64 + ldr) * 64 + ldc;        \
        const uint32_t d_ = sb + (uint32_t)(stg) * AT_ST + ldst;               \
        CP_ASYNC16(d_ + AT_KH,      g_kh + go_);                               \
        CP_ASYNC16(d_ + AT_KH + 16, g_kh + go_ + 8);                           \
        CP_ASYNC16(d_ + AT_VH,      g_vh + go_);                               \
        CP_ASYNC16(d_ + AT_VH + 16, g_vh + go_ + 8);                           \
        CP_COMMIT();                                                           \
    } while (0)

    // Q fragments from pre-split gmem (scale already folded in)
    uint32_t qh[4][4], ql[4][4];
    {
        const uint32_t* qhp = (const uint32_t*)(g_qh + bho);
        const uint32_t* qlp = (const uint32_t*)(g_ql + bho);
        const int ra = row0 * 32;
        const int rb = (row0 + 8) * 32;
#pragma unroll
        for (int ks = 0; ks < 4; ks++) {
            const int kw = ks * 8 + t4;
            qh[ks][0] = qhp[ra + kw];
            qh[ks][1] = qhp[rb + kw];
            qh[ks][2] = qhp[ra + kw + 4];
            qh[ks][3] = qhp[rb + kw + 4];
            ql[ks][0] = qlp[ra + kw];
            ql[ks][1] = qlp[rb + kw];
            ql[ks][2] = qlp[ra + kw + 4];
            ql[ks][3] = qlp[rb + kw + 4];
        }
    }

    float o[8][4];
#pragma unroll
    for (int nt = 0; nt < 8; nt++)
#pragma unroll
        for (int q = 0; q < 4; q++) o[nt][q] = 0.f;
    float mrow0 = -CUDART_INF_F, mrow1 = -CUDART_INF_F;
    float lrow0v = 0.f, lrow1v = 0.f;

    const int nkv = 2 * qt + 2;
    ATT_ISSUE(0, 0);
    if (nkv > 1) ATT_ISSUE(1, 1);

    for (int kv = 0; kv < nkv; kv++) {
        const int k0 = kv * 64;
        if (kv + 1 < nkv) { CP_WAIT(1); } else { CP_WAIT(0); }
        __syncthreads();                    // tile kv visible; stage (kv+2)%3 free
        if (kv + 2 < nkv) ATT_ISSUE((kv + 2) % 3, kv + 2);

        const uint32_t sbs = sb + (uint32_t)(kv % 3) * AT_ST;

        if (k0 <= wrow + 15) {
            // ---- S = Q K^T (2 passes: Qh*Kh + Ql*Kh), already exp2-scaled ----
            float s[8][4];
#pragma unroll
            for (int nt = 0; nt < 8; nt++)
#pragma unroll
                for (int q = 0; q < 4; q++) s[nt][q] = 0.f;

#pragma unroll
            for (int ks = 0; ks < 4; ks++) {
                uint32_t kbh[8][2];
#pragma unroll
                for (int p = 0; p < 4; p++)
                    LDSM4(kbh[2 * p][0], kbh[2 * p][1], kbh[2 * p + 1][0], kbh[2 * p + 1][1],
                          sbs + AT_KH + koff + (uint32_t)p * 2304 + (uint32_t)ks * 32);
#pragma unroll
                for (int nt = 0; nt < 8; nt++) mma_f16(s[nt], qh[ks], kbh[nt]);
#pragma unroll
                for (int nt = 0; nt < 8; nt++) mma_f16(s[nt], ql[ks], kbh[nt]);
            }

            // ---- causal mask ----
            if (k0 + 63 > wrow) {
#pragma unroll
                for (int nt = 0; nt < 8; nt++) {
                    const int col0 = k0 + nt * 8 + 2 * t4;
                    if (col0 > row0)         s[nt][0] = -CUDART_INF_F;
                    if (col0 + 1 > row0)     s[nt][1] = -CUDART_INF_F;
                    if (col0 > row0 + 8)     s[nt][2] = -CUDART_INF_F;
                    if (col0 + 1 > row0 + 8) s[nt][3] = -CUDART_INF_F;
                }
            }

            // ---- online softmax (exp2 domain) ----
            float mx0 = -CUDART_INF_F, mx1 = -CUDART_INF_F;
#pragma unroll
            for (int nt = 0; nt < 8; nt++) {
                mx0 = fmaxf(mx0, fmaxf(s[nt][0], s[nt][1]));
                mx1 = fmaxf(mx1, fmaxf(s[nt][2], s[nt][3]));
            }
            mx0 = fmaxf(mx0, __shfl_xor_sync(0xffffffffu, mx0, 1));
            mx0 = fmaxf(mx0, __shfl_xor_sync(0xffffffffu, mx0, 2));
            mx1 = fmaxf(mx1, __shfl_xor_sync(0xffffffffu, mx1, 1));
            mx1 = fmaxf(mx1, __shfl_xor_sync(0xffffffffu, mx1, 2));

            const float nm0 = fmaxf(mrow0, mx0);
            const float nm1 = fmaxf(mrow1, mx1);
            const float c0 = exp2f(mrow0 - nm0);
            const float c1 = exp2f(mrow1 - nm1);
            float sum0 = 0.f, sum1 = 0.f;
#pragma unroll
            for (int nt = 0; nt < 8; nt++) {
                s[nt][0] = exp2f(s[nt][0] - nm0);
                s[nt][1] = exp2f(s[nt][1] - nm0);
                s[nt][2] = exp2f(s[nt][2] - nm1);
                s[nt][3] = exp2f(s[nt][3] - nm1);
                sum0 += s[nt][0] + s[nt][1];
                sum1 += s[nt][2] + s[nt][3];
            }
            sum0 += __shfl_xor_sync(0xffffffffu, sum0, 1);
            sum0 += __shfl_xor_sync(0xffffffffu, sum0, 2);
            sum1 += __shfl_xor_sync(0xffffffffu, sum1, 1);
            sum1 += __shfl_xor_sync(0xffffffffu, sum1, 2);
            lrow0v = lrow0v * c0 + sum0;
            lrow1v = lrow1v * c1 + sum1;
            mrow0 = nm0;
            mrow1 = nm1;
#pragma unroll
            for (int nt = 0; nt < 8; nt++) {
                o[nt][0] *= c0;
                o[nt][1] *= c0;
                o[nt][2] *= c1;
                o[nt][3] *= c1;
            }

            // ---- P -> fp16 split A-frags ----
            uint32_t pah[4][4], pal[4][4];
#pragma unroll
            for (int kk = 0; kk < 4; kk++) {
                split2h(s[2 * kk][0], s[2 * kk][1], pah[kk][0], pal[kk][0]);
                split2h(s[2 * kk][2], s[2 * kk][3], pah[kk][1], pal[kk][1]);
                split2h(s[2 * kk + 1][0], s[2 * kk + 1][1], pah[kk][2], pal[kk][2]);
                split2h(s[2 * kk + 1][2], s[2 * kk + 1][3], pah[kk][3], pal[kk][3]);
            }

            // ---- O += P V (2 passes: Ph*Vh + Pl*Vh), V^T via ldmatrix.trans ----
#pragma unroll
            for (int kk = 0; kk < 4; kk++) {
                uint32_t vbh[8][2];
#pragma unroll
                for (int p = 0; p < 4; p++)
                    LDSM4T(vbh[2 * p][0], vbh[2 * p][1], vbh[2 * p + 1][0], vbh[2 * p + 1][1],
                           sbs + AT_VH + voff + (uint32_t)kk * 2304 + (uint32_t)p * 32);
#pragma unroll
                for (int nt = 0; nt < 8; nt++) mma_f16(o[nt], pah[kk], vbh[nt]);
#pragma unroll
                for (int nt = 0; nt < 8; nt++) mma_f16(o[nt], pal[kk], vbh[nt]);
            }
        }
    }

    // ---- epilogue: divide by l, write ctx hi-only ----
    const float inv0 = 1.f / lrow0v;
    const float inv1 = 1.f / lrow1v;
    const size_t base0 = ((size_t)(b * S_ + row0)) * D_ + h * HD_;
    const size_t base1 = ((size_t)(b * S_ + row0 + 8)) * D_ + h * HD_;
#pragma unroll
    for (int nt = 0; nt < 8; nt++) {
        const int d = nt * 8 + 2 * t4;
        *(uint32_t*)&g_cth[base0 + d] = pack2h(o[nt][0] * inv0, o[nt][1] * inv0);
        *(uint32_t*)&g_cth[base1 + d] = pack2h(o[nt][2] * inv1, o[nt][3] * inv1);
    }
}

// ---------------------------------------------------------------------------
extern "C" void kernel_launch(void* const* d_in, const int* in_sizes, int n_in,
                              void* d_out, int out_size)
{
    const float* q  = (const float*)d_in[0];
    const float* k  = (const float*)d_in[1];
    const float* v  = (const float*)d_in[2];
    const float* wq = (const float*)d_in[3];
    const float* wk = (const float*)d_in[4];
    const float* wv = (const float*)d_in[5];
    const float* wo = (const float*)d_in[6];
    float* out = (float*)d_out;

    asplit_k<<<dim3(8192, 3), 256>>>(q, k, v);
    wsplit_k<<<dim3(32, 32, 4), dim3(32, 8)>>>(wq, wk, wv, wo);

    cudaFuncSetAttribute(gemm_mma, cudaFuncAttributeMaxDynamicSharedMemorySize, G_SMEM);
    cudaFuncSetAttribute(attn_k, cudaFuncAttributeMaxDynamicSharedMemorySize, AT_SMEM);

    gemm_mma<<<dim3(8, 64, 3), 256, G_SMEM>>>(nullptr, 0);   // QKV fused

    attn_k<<<dim3(16, 16, 4), 256, AT_SMEM>>>();

    gemm_mma<<<dim3(8, 64, 1), 256, G_SMEM>>>(out, 3);       // O projection
}